// round 12
// baseline (speedup 1.0000x reference)
#include <cuda_runtime.h>
#include <cuda_bf16.h>
#include <math.h>

#define D 512
#define NMAX 12288
#define HD 64
#define NHEAD 8
#define MASKMAX (32 * 512 * 512)
#define WELEMS 2883584   // 11 * 512 * 512 weight elements total
#define EMAX (16 * NMAX)
#define QT 64
#define ATTN_SMEM ((64 * 68 * 3 + 64 * 72) * 4)

// ---------------- scratch (static device globals; no allocation) ----------------
__device__ float  g_v  [NMAX * D];
__device__ float  g_h  [NMAX * D];
__device__ float  g_qk [NMAX * 2 * D];
__device__ double g_stats[2 * D];
__device__ unsigned char g_mask[MASKMAX];
__device__ __nv_bfloat16 g_whi[WELEMS];
__device__ __nv_bfloat16 g_wlo[WELEMS];
__device__ __nv_bfloat16 g_shi0[NMAX * D];
__device__ __nv_bfloat16 g_slo0[NMAX * D];
__device__ __nv_bfloat16 g_shi1[NMAX * D];
__device__ __nv_bfloat16 g_slo1[NMAX * D];
__device__ __nv_bfloat16 g_wfhi[1024 * 512];   // fused se@qk weight, [n][k] split
__device__ __nv_bfloat16 g_wflo[1024 * 512];
__device__ float  g_bf[1024];                   // fused bias
__device__ float  g_zero[1024];                 // zero bias (never written)
__device__ int    g_flags[4];
__device__ int    g_deg [NMAX];
__device__ int    g_bse [NMAX];
__device__ int    g_cur [NMAX];
__device__ int    g_eidx[EMAX];

__device__ __forceinline__ long long ldidx(const void* p, int is64, long long i) {
    if (is64) return ((const long long*)p)[i];
    return (long long)((const int*)p)[i];
}

__device__ __forceinline__ unsigned smem_u32(const void* p) {
    unsigned a;
    asm("{ .reg .u64 t; cvta.to.shared.u64 t, %1; cvt.u32.u64 %0, t; }" : "=r"(a) : "l"(p));
    return a;
}

__device__ __forceinline__ unsigned pack_bf2(float x, float y) {
    __nv_bfloat162 p(__float2bfloat16(x), __float2bfloat16(y));
    return *(unsigned*)&p;
}
__device__ __forceinline__ void split2(float x, float y, unsigned& hiw, unsigned& low) {
    __nv_bfloat16 hx = __float2bfloat16(x), hy = __float2bfloat16(y);
    __nv_bfloat162 hp(hx, hy);
    hiw = *(unsigned*)&hp;
    low = pack_bf2(x - __bfloat162float(hx), y - __bfloat162float(hy));
}

// ---------------- detection (parallel; see R1/R2 notes for the patterns) ----------------
__global__ void detect_kernel(const int* __restrict__ ew, const int* __restrict__ pw,
                              const unsigned int* __restrict__ mw) {
    __shared__ int bad;
    if (threadIdx.x == 0) bad = 0;
    __syncthreads();
    int ok = 1;
    for (int i = threadIdx.x; i < 4096; i += 256) {
        unsigned int w = mw[i];
        if (w != 0u && w != 1u && w != 0x3f800000u) { ok = 0; break; }
    }
    if (!ok) atomicExch(&bad, 1);
    __syncthreads();
    if (threadIdx.x == 0) {
        g_flags[0] = (ew[17] == 0) ? 1 : 0;
        g_flags[1] = (pw[1]  == 0) ? 1 : 0;
        g_flags[2] = bad ? 0 : 1;
    }
}

__global__ void mask_convert_kernel(const void* __restrict__ mask, long long total) {
    long long i = (long long)blockIdx.x * blockDim.x + threadIdx.x;
    if (i >= total) return;
    unsigned char m;
    if (g_flags[2]) m = (((const unsigned int*)mask)[i] != 0u) ? 1 : 0;
    else            m = (((const unsigned char*)mask)[i] != 0) ? 1 : 0;
    g_mask[i] = m;
}

// ---------------- fused weight split (fp32 -> bf16 hi/lo, transpose to [N][K]) ----------------
struct WJobs {
    const float* src[12];
    __nv_bfloat16* hi[12];
    __nv_bfloat16* lo[12];
    int N[12];
    int row0[12];
    int njobs;
};

__global__ void wsplit_all_kernel(WJobs J) {
    int row = blockIdx.x;
    int j = 0;
    while (j + 1 < J.njobs && row >= J.row0[j + 1]) j++;
    int n = row - J.row0[j];
    int Nc = J.N[j];
    const float* src = J.src[j];
    __nv_bfloat16* hi = J.hi[j];
    __nv_bfloat16* lo = J.lo[j];
    for (int k = threadIdx.x; k < 512; k += blockDim.x) {
        float v = src[(size_t)k * Nc + n];
        __nv_bfloat16 h = __float2bfloat16(v);
        hi[(size_t)n * 512 + k] = h;
        lo[(size_t)n * 512 + k] = __float2bfloat16(v - __bfloat162float(h));
    }
}

// ---------------- activation split (x -> bf16 hi/lo, row-major) ----------------
__global__ void __launch_bounds__(128)
asplit_kernel(const float* __restrict__ x, __nv_bfloat16* __restrict__ hi,
              __nv_bfloat16* __restrict__ lo) {
    int node = blockIdx.x, t = threadIdx.x;
    float4 v = *(const float4*)(x + (size_t)node * D + t * 4);
    unsigned h0, l0, h1, l1;
    split2(v.x, v.y, h0, l0);
    split2(v.z, v.w, h1, l1);
    *(uint2*)((char*)hi + ((size_t)node * D + t * 4) * 2) = make_uint2(h0, h1);
    *(uint2*)((char*)lo + ((size_t)node * D + t * 4) * 2) = make_uint2(l0, l1);
}

// ---------------- fused bias: b' = se_b @ qk_w + qk_b ----------------
__global__ void bfold_kernel(const float* __restrict__ seb, const float* __restrict__ qkw,
                             const float* __restrict__ qkb) {
    int j = blockIdx.x * blockDim.x + threadIdx.x;   // 1024 outputs
    float s = qkb[j];
    for (int k = 0; k < 512; k++) s = fmaf(seb[k], qkw[(size_t)k * 1024 + j], s);
    g_bf[j] = s;
}

// ---------------- in-edge CSR build (once per launch) ----------------
__global__ void csr_count_kernel(const void* __restrict__ edge, int E) {
    int e = blockIdx.x * blockDim.x + threadIdx.x;
    if (e >= E) return;
    int is64 = g_flags[0];
    long long t = ldidx(edge, is64, (long long)E + e);
    atomicAdd(&g_deg[t], 1);
}

__global__ void csr_scan_kernel(int N) {
    __shared__ int ss[1024];
    int t = threadIdx.x;
    int chunk = (N + 1023) >> 10;
    int s0 = t * chunk, s1 = min(s0 + chunk, N);
    int sum = 0;
    for (int i = s0; i < s1; i++) sum += g_deg[i];
    ss[t] = sum;
    __syncthreads();
    for (int off = 1; off < 1024; off <<= 1) {
        int v = (t >= off) ? ss[t - off] : 0;
        __syncthreads();
        ss[t] += v;
        __syncthreads();
    }
    int base = (t == 0) ? 0 : ss[t - 1];
    for (int i = s0; i < s1; i++) {
        g_bse[i] = base;
        g_cur[i] = base;
        base += g_deg[i];
    }
}

__global__ void csr_fill_kernel(const void* __restrict__ edge, int E) {
    int e = blockIdx.x * blockDim.x + threadIdx.x;
    if (e >= E) return;
    int is64 = g_flags[0];
    long long s = ldidx(edge, is64, e);
    long long t = ldidx(edge, is64, (long long)E + e);
    int pos = atomicAdd(&g_cur[t], 1);
    g_eidx[pos] = (int)s;
}

// ---------------- GIN aggregation: gather + self-add + split (no atomics) ----------------
__global__ void __launch_bounds__(128)
gather_kernel(const float* __restrict__ h, __nv_bfloat16* __restrict__ ohi,
              __nv_bfloat16* __restrict__ olo) {
    int node = blockIdx.x;
    int d4 = threadIdx.x;
    int base = g_bse[node], deg = g_deg[node];
    float4 acc = *(const float4*)(h + (size_t)node * D + d4 * 4);
    int j = 0;
    for (; j + 4 <= deg; j += 4) {
        int s0 = g_eidx[base + j];
        int s1 = g_eidx[base + j + 1];
        int s2 = g_eidx[base + j + 2];
        int s3 = g_eidx[base + j + 3];
        float4 v0 = *(const float4*)(h + (size_t)s0 * D + d4 * 4);
        float4 v1 = *(const float4*)(h + (size_t)s1 * D + d4 * 4);
        float4 v2 = *(const float4*)(h + (size_t)s2 * D + d4 * 4);
        float4 v3 = *(const float4*)(h + (size_t)s3 * D + d4 * 4);
        acc.x += v0.x + v1.x + v2.x + v3.x;
        acc.y += v0.y + v1.y + v2.y + v3.y;
        acc.z += v0.z + v1.z + v2.z + v3.z;
        acc.w += v0.w + v1.w + v2.w + v3.w;
    }
    for (; j < deg; j++) {
        int src = g_eidx[base + j];
        float4 v = *(const float4*)(h + (size_t)src * D + d4 * 4);
        acc.x += v.x; acc.y += v.y; acc.z += v.z; acc.w += v.w;
    }
    unsigned h0, l0, h1, l1;
    split2(acc.x, acc.y, h0, l0);
    split2(acc.z, acc.w, h1, l1);
    *(uint2*)((char*)ohi + ((size_t)node * D + d4 * 4) * 2) = make_uint2(h0, h1);
    *(uint2*)((char*)olo + ((size_t)node * D + d4 * 4) * 2) = make_uint2(l0, l1);
}

// ---------------- pipelined tensor-core GEMM (pre-split bf16 A and B, fp32 accum) ----------------
// 64x128 tile, 256 thr, 8 warps (2x4 of 32x32), BK=32, 3-stage cp.async pipeline,
// 64B rows with SW64 chunk swizzle, 3 CTAs/SM.
#define OFF_ALO 4096u
#define OFF_BHI 8192u
#define OFF_BLO 16384u
#define STAGEB  24576u
#define GEMM_SMEM (3 * 24576 + 128)

#define LDM4(r0, r1, r2, r3, addr) \
    asm volatile("ldmatrix.sync.aligned.m8n8.x4.shared.b16 {%0,%1,%2,%3}, [%4];" \
                 : "=r"(r0), "=r"(r1), "=r"(r2), "=r"(r3) : "r"(addr))
#define CP16(dst, src) \
    asm volatile("cp.async.cg.shared.global [%0], [%1], 16;" :: "r"(dst), "l"(src))
#define CPCOMMIT() asm volatile("cp.async.commit_group;" ::: "memory")
#define CPWAIT1()  asm volatile("cp.async.wait_group 1;" ::: "memory")

__device__ __forceinline__ void mma_bf16(float* c, unsigned a0, unsigned a1, unsigned a2,
                                         unsigned a3, unsigned b0, unsigned b1) {
    asm volatile(
        "mma.sync.aligned.m16n8k16.row.col.f32.bf16.bf16.f32 "
        "{%0,%1,%2,%3}, {%4,%5,%6,%7}, {%8,%9}, {%0,%1,%2,%3};"
        : "+f"(c[0]), "+f"(c[1]), "+f"(c[2]), "+f"(c[3])
        : "r"(a0), "r"(a1), "r"(a2), "r"(a3), "r"(b0), "r"(b1));
}

template <bool RELU, bool WSPLIT, bool WF32, bool WT>
__global__ void __launch_bounds__(256, 3)
pgemm_kernel(const __nv_bfloat16* __restrict__ Ahi, const __nv_bfloat16* __restrict__ Alo,
             const __nv_bfloat16* __restrict__ Bhi, const __nv_bfloat16* __restrict__ Blo,
             const float* __restrict__ bias, float* __restrict__ C,
             __nv_bfloat16* __restrict__ Ohi, __nv_bfloat16* __restrict__ Olo,
             int M, int Nc) {
    extern __shared__ char dynsmem[];
    unsigned sb = (smem_u32(dynsmem) + 127) & ~127u;

    int tid = threadIdx.x, wid = tid >> 5, lane = tid & 31;
    int m0 = blockIdx.y * 64, n0 = blockIdx.x * 128;
    int warp_m = (wid & 1) * 32, warp_n = (wid >> 1) * 32;
    int g = lane >> 2, kp = (lane & 3) * 2;

    // cp.async maps: A = 64 rows x 4 chunks (1 per thread); B = 128 rows x 4 chunks (2 per thread)
    int crow = tid >> 2, cch = tid & 3;
    unsigned dstA = (unsigned)(crow * 64 + ((cch ^ ((crow >> 1) & 3)) * 16));
    long long arow = m0 + crow; if (arow > M - 1) arow = M - 1;
    const __nv_bfloat16* pAhi = Ahi + arow * 512 + cch * 8;
    const __nv_bfloat16* pAlo = Alo + arow * 512 + cch * 8;
    int brow2 = crow + 64;
    unsigned dstB0 = dstA;
    unsigned dstB1 = (unsigned)(brow2 * 64 + ((cch ^ ((brow2 >> 1) & 3)) * 16));
    const __nv_bfloat16* pBhi0 = Bhi + (size_t)(n0 + crow) * 512 + cch * 8;
    const __nv_bfloat16* pBhi1 = Bhi + (size_t)(n0 + brow2) * 512 + cch * 8;
    const __nv_bfloat16* pBlo0 = Blo + (size_t)(n0 + crow) * 512 + cch * 8;
    const __nv_bfloat16* pBlo1 = Blo + (size_t)(n0 + brow2) * 512 + cch * 8;

    // ldmatrix per-lane offsets (swizzle term depends only on row mod 16)
    int rA = lane & 15, hA = lane >> 4;
    unsigned aoff = (unsigned)((warp_m + rA) * 64 + ((hA ^ ((rA >> 1) & 3)) * 16));
    int rB = (lane & 7) + ((lane >> 4) * 8);
    int cB = (lane >> 3) & 1;
    unsigned boff = (unsigned)((warp_n + rB) * 64 + ((cB ^ ((rB >> 1) & 3)) * 16));

    float acc[2][4][4];
#pragma unroll
    for (int i = 0; i < 2; i++)
#pragma unroll
        for (int j = 0; j < 4; j++)
#pragma unroll
            for (int r = 0; r < 4; r++) acc[i][j][r] = 0.f;

    // prologue: stages 0 and 1
#pragma unroll
    for (int s = 0; s < 2; s++) {
        unsigned bb = sb + (unsigned)s * STAGEB;
        int kg = s * 32;
        CP16(bb + dstA,            pAhi + kg);
        CP16(bb + OFF_ALO + dstA,  pAlo + kg);
        CP16(bb + OFF_BHI + dstB0, pBhi0 + kg);
        CP16(bb + OFF_BHI + dstB1, pBhi1 + kg);
        CP16(bb + OFF_BLO + dstB0, pBlo0 + kg);
        CP16(bb + OFF_BLO + dstB1, pBlo1 + kg);
        CPCOMMIT();
    }

    unsigned bufoff[3] = {0u, STAGEB, 2u * STAGEB};
#pragma unroll 1
    for (int s = 0; s < 16; s++) {
        CPWAIT1();
        __syncthreads();
        if (s + 2 < 16) {
            unsigned bb = sb + bufoff[(s + 2) % 3];
            int kg = (s + 2) * 32;
            CP16(bb + dstA,            pAhi + kg);
            CP16(bb + OFF_ALO + dstA,  pAlo + kg);
            CP16(bb + OFF_BHI + dstB0, pBhi0 + kg);
            CP16(bb + OFF_BHI + dstB1, pBhi1 + kg);
            CP16(bb + OFF_BLO + dstB0, pBlo0 + kg);
            CP16(bb + OFF_BLO + dstB1, pBlo1 + kg);
        }
        CPCOMMIT();

        unsigned bcur = sb + bufoff[s % 3];
#pragma unroll
        for (int kx = 0; kx < 2; kx++) {
            unsigned kxor = kx ? 32u : 0u;
            unsigned ah[2][4], al[2][4], bh[4][2], bl[4][2];
#pragma unroll
            for (int mi = 0; mi < 2; mi++)
                LDM4(ah[mi][0], ah[mi][1], ah[mi][2], ah[mi][3],
                     bcur + (unsigned)(mi * 1024) + (aoff ^ kxor));
            {
                unsigned r0, r1, r2, r3;
#pragma unroll
                for (int p = 0; p < 2; p++) {
                    LDM4(r0, r1, r2, r3, bcur + OFF_BHI + (unsigned)(p * 1024) + (boff ^ kxor));
                    bh[2 * p][0] = r0; bh[2 * p][1] = r1;
                    bh[2 * p + 1][0] = r2; bh[2 * p + 1][1] = r3;
                    LDM4(r0, r1, r2, r3, bcur + OFF_BLO + (unsigned)(p * 1024) + (boff ^ kxor));
                    bl[2 * p][0] = r0; bl[2 * p][1] = r1;
                    bl[2 * p + 1][0] = r2; bl[2 * p + 1][1] = r3;
                }
            }
#pragma unroll
            for (int mi = 0; mi < 2; mi++)
                LDM4(al[mi][0], al[mi][1], al[mi][2], al[mi][3],
                     bcur + OFF_ALO + (unsigned)(mi * 1024) + (aoff ^ kxor));
#pragma unroll
            for (int mi = 0; mi < 2; mi++)
#pragma unroll
                for (int ni = 0; ni < 4; ni++)
                    mma_bf16(acc[mi][ni], ah[mi][0], ah[mi][1], ah[mi][2], ah[mi][3],
                             bh[ni][0], bh[ni][1]);
#pragma unroll
            for (int mi = 0; mi < 2; mi++)
#pragma unroll
                for (int ni = 0; ni < 4; ni++)
                    mma_bf16(acc[mi][ni], ah[mi][0], ah[mi][1], ah[mi][2], ah[mi][3],
                             bl[ni][0], bl[ni][1]);
#pragma unroll
            for (int mi = 0; mi < 2; mi++)
#pragma unroll
                for (int ni = 0; ni < 4; ni++)
                    mma_bf16(acc[mi][ni], al[mi][0], al[mi][1], al[mi][2], al[mi][3],
                             bh[ni][0], bh[ni][1]);
        }
        __syncthreads();
    }

    // epilogue
#pragma unroll
    for (int mi = 0; mi < 2; mi++) {
        int row0 = m0 + warp_m + mi * 16 + g;
        int row1 = row0 + 8;
#pragma unroll
        for (int ni = 0; ni < 4; ni++) {
            int col = n0 + warp_n + ni * 8 + kp;
            float b0 = bias[col], b1 = bias[col + 1];
            float o0 = acc[mi][ni][0] + b0, o1 = acc[mi][ni][1] + b1;
            float o2 = acc[mi][ni][2] + b0, o3 = acc[mi][ni][3] + b1;
            if (RELU) {
                o0 = fmaxf(o0, 0.f); o1 = fmaxf(o1, 0.f);
                o2 = fmaxf(o2, 0.f); o3 = fmaxf(o3, 0.f);
            }
            if (row0 < M) {
                if (WF32)
                    *(float2*)(C + (size_t)row0 * Nc + col) = make_float2(o0, o1);
                if (WSPLIT && !WT) {
                    unsigned hw, lw;
                    split2(o0, o1, hw, lw);
                    *(unsigned*)((char*)Ohi + ((size_t)row0 * Nc + col) * 2) = hw;
                    *(unsigned*)((char*)Olo + ((size_t)row0 * Nc + col) * 2) = lw;
                }
                if (WT) {
                    __nv_bfloat16 h0 = __float2bfloat16(o0);
                    __nv_bfloat16 h1 = __float2bfloat16(o1);
                    Ohi[(size_t)col * 512 + row0] = h0;
                    Olo[(size_t)col * 512 + row0] = __float2bfloat16(o0 - __bfloat162float(h0));
                    Ohi[(size_t)(col + 1) * 512 + row0] = h1;
                    Olo[(size_t)(col + 1) * 512 + row0] = __float2bfloat16(o1 - __bfloat162float(h1));
                }
            }
            if (row1 < M) {
                if (WF32)
                    *(float2*)(C + (size_t)row1 * Nc + col) = make_float2(o2, o3);
                if (WSPLIT && !WT) {
                    unsigned hw, lw;
                    split2(o2, o3, hw, lw);
                    *(unsigned*)((char*)Ohi + ((size_t)row1 * Nc + col) * 2) = hw;
                    *(unsigned*)((char*)Olo + ((size_t)row1 * Nc + col) * 2) = lw;
                }
                if (WT) {
                    __nv_bfloat16 h2 = __float2bfloat16(o2);
                    __nv_bfloat16 h3 = __float2bfloat16(o3);
                    Ohi[(size_t)col * 512 + row1] = h2;
                    Olo[(size_t)col * 512 + row1] = __float2bfloat16(o2 - __bfloat162float(h2));
                    Ohi[(size_t)(col + 1) * 512 + row1] = h3;
                    Olo[(size_t)(col + 1) * 512 + row1] = __float2bfloat16(o3 - __bfloat162float(h3));
                }
            }
        }
    }
}

// ---------------- BatchNorm ----------------
__global__ void bn_stats_kernel(const float* __restrict__ h, int N) {
    int c = threadIdx.x;
    double s = 0.0, s2 = 0.0;
    for (int r = blockIdx.x; r < N; r += gridDim.x) {
        float v = h[(size_t)r * D + c];
        s += v;
        s2 += (double)v * v;
    }
    atomicAdd(&g_stats[c], s);
    atomicAdd(&g_stats[D + c], s2);
}

__global__ void bn_apply_kernel(const float* __restrict__ h, const float* __restrict__ gamma,
                                const float* __restrict__ beta,
                                __nv_bfloat16* __restrict__ ohi, __nv_bfloat16* __restrict__ olo,
                                int N) {
    long long i = (long long)blockIdx.x * blockDim.x + threadIdx.x;
    if (i >= (long long)N * (D / 2)) return;
    int p = (int)(i & (D / 2 - 1));
    long long row = i >> 8;
    int c0 = 2 * p, c1 = c0 + 1;
    double mean0 = g_stats[c0] / N, mean1 = g_stats[c1] / N;
    double var0  = g_stats[D + c0] / N - mean0 * mean0;
    double var1  = g_stats[D + c1] / N - mean1 * mean1;
    float is0 = rsqrtf((float)var0 + 1e-5f), is1 = rsqrtf((float)var1 + 1e-5f);
    float2 v = *(const float2*)(h + row * D + c0);
    float o0 = (v.x - (float)mean0) * is0 * gamma[c0] + beta[c0];
    float o1 = (v.y - (float)mean1) * is1 * gamma[c1] + beta[c1];
    unsigned hw, lw;
    split2(o0, o1, hw, lw);
    *(unsigned*)((char*)ohi + (row * D + c0) * 2) = hw;
    *(unsigned*)((char*)olo + (row * D + c0) * 2) = lw;
}

// ---------------- masked attention, 4-query register blocking, split output ----------------
__global__ void __launch_bounds__(128)
attn_kernel(const void* __restrict__ ptr, int L,
            __nv_bfloat16* __restrict__ ohi, __nv_bfloat16* __restrict__ olo) {
    extern __shared__ float asm_f[];
    float (*Qs)[68] = (float(*)[68])asm_f;
    float (*Ks)[68] = (float(*)[68])(asm_f + 64 * 68);
    float (*Vs)[68] = (float(*)[68])(asm_f + 2 * 64 * 68);
    float (*Ps)[72] = (float(*)[72])(asm_f + 3 * 64 * 68);

    int qt = blockIdx.x, hh = blockIdx.y, b = blockIdx.z;
    int is64 = g_flags[1];
    long long p0 = ldidx(ptr, is64, b);
    long long p1 = ldidx(ptr, is64, b + 1);
    int s = (int)(p1 - p0);
    int qbase = qt * QT;
    if (qbase >= s) return;

    int tid = threadIdx.x;
    int tq4 = tid >> 3, tg = tid & 7;
    int q[4];
    bool qok[4];
    const unsigned char* mrow[4];
#pragma unroll
    for (int qi = 0; qi < 4; qi++) {
        q[qi] = 4 * tq4 + qi;
        qok[qi] = (qbase + q[qi]) < s;
        mrow[qi] = g_mask + ((size_t)b * L + (qok[qi] ? qbase + q[qi] : 0)) * L;
    }

    for (int i = tid; i < QT * 16; i += 128) {
        int r = i >> 4, c4 = i & 15;
        float4 val = make_float4(0.f, 0.f, 0.f, 0.f);
        if (qbase + r < s)
            val = *(const float4*)(g_qk + (p0 + qbase + r) * (2 * D) + D + hh * HD + c4 * 4);
        *(float4*)&Qs[r][c4 * 4] = val;
    }

    float acc[4][8], mr[4], lr[4];
#pragma unroll
    for (int qi = 0; qi < 4; qi++) {
        mr[qi] = -1e30f; lr[qi] = 0.f;
#pragma unroll
        for (int dd = 0; dd < 8; dd++) acc[qi][dd] = 0.f;
    }

    for (int j0 = 0; j0 < s; j0 += 64) {
        __syncthreads();
        for (int i = tid; i < 64 * 16; i += 128) {
            int r = i >> 4, c4 = i & 15;
            float4 kv = make_float4(0.f, 0.f, 0.f, 0.f);
            float4 vv = kv;
            if (j0 + r < s) {
                long long node = p0 + j0 + r;
                kv = *(const float4*)(g_qk + node * (2 * D) + hh * HD + c4 * 4);
                vv = *(const float4*)(g_v + node * D + hh * HD + c4 * 4);
            }
            *(float4*)&Ks[r][c4 * 4] = kv;
            *(float4*)&Vs[r][c4 * 4] = vv;
        }
        __syncthreads();

        float sc[4][8];
#pragma unroll
        for (int qi = 0; qi < 4; qi++)
#pragma unroll
            for (int jj = 0; jj < 8; jj++) sc[qi][jj] = 0.f;
#pragma unroll
        for (int d4 = 0; d4 < 16; d4++) {
            float4 qv[4];
#pragma unroll
            for (int qi = 0; qi < 4; qi++) qv[qi] = *(float4*)&Qs[q[qi]][d4 * 4];
#pragma unroll
            for (int jj = 0; jj < 8; jj++) {
                float4 k4 = *(float4*)&Ks[jj * 8 + tg][d4 * 4];
#pragma unroll
                for (int qi = 0; qi < 4; qi++) {
                    sc[qi][jj] = fmaf(qv[qi].x, k4.x, sc[qi][jj]);
                    sc[qi][jj] = fmaf(qv[qi].y, k4.y, sc[qi][jj]);
                    sc[qi][jj] = fmaf(qv[qi].z, k4.z, sc[qi][jj]);
                    sc[qi][jj] = fmaf(qv[qi].w, k4.w, sc[qi][jj]);
                }
            }
        }
#pragma unroll
        for (int qi = 0; qi < 4; qi++)
#pragma unroll
            for (int jj = 0; jj < 8; jj++) {
                int j = jj * 8 + tg;
                bool valid = (j0 + j < s) && (mrow[qi][j0 + j] == 0);
                sc[qi][jj] = valid ? sc[qi][jj] * 0.125f : -1e30f;
            }
#pragma unroll
        for (int qi = 0; qi < 4; qi++) {
            float mt = sc[qi][0];
#pragma unroll
            for (int jj = 1; jj < 8; jj++) mt = fmaxf(mt, sc[qi][jj]);
#pragma unroll
            for (int off = 1; off < 8; off <<= 1)
                mt = fmaxf(mt, __shfl_xor_sync(0xffffffffu, mt, off));
            float mn = fmaxf(mr[qi], mt);
            float corr = __expf(mr[qi] - mn);
            float ps = 0.f;
#pragma unroll
            for (int jj = 0; jj < 8; jj++) {
                float pv = (sc[qi][jj] <= -1e29f) ? 0.f : __expf(sc[qi][jj] - mn);
                Ps[q[qi]][jj * 8 + tg] = pv;
                ps += pv;
            }
#pragma unroll
            for (int off = 1; off < 8; off <<= 1)
                ps += __shfl_xor_sync(0xffffffffu, ps, off);
            lr[qi] = lr[qi] * corr + ps;
            mr[qi] = mn;
#pragma unroll
            for (int dd = 0; dd < 8; dd++) acc[qi][dd] *= corr;
        }
        __syncwarp();

#pragma unroll 2
        for (int j = 0; j < 64; j += 4) {
            float4 pq[4];
#pragma unroll
            for (int qi = 0; qi < 4; qi++) pq[qi] = *(float4*)&Ps[q[qi]][j];
            float pv[4][4] = {{pq[0].x, pq[0].y, pq[0].z, pq[0].w},
                              {pq[1].x, pq[1].y, pq[1].z, pq[1].w},
                              {pq[2].x, pq[2].y, pq[2].z, pq[2].w},
                              {pq[3].x, pq[3].y, pq[3].z, pq[3].w}};
#pragma unroll
            for (int u = 0; u < 4; u++) {
                float4 va = *(float4*)&Vs[j + u][tg * 8];
                float4 vb = *(float4*)&Vs[j + u][tg * 8 + 4];
#pragma unroll
                for (int qi = 0; qi < 4; qi++) {
                    acc[qi][0] = fmaf(pv[qi][u], va.x, acc[qi][0]);
                    acc[qi][1] = fmaf(pv[qi][u], va.y, acc[qi][1]);
                    acc[qi][2] = fmaf(pv[qi][u], va.z, acc[qi][2]);
                    acc[qi][3] = fmaf(pv[qi][u], va.w, acc[qi][3]);
                    acc[qi][4] = fmaf(pv[qi][u], vb.x, acc[qi][4]);
                    acc[qi][5] = fmaf(pv[qi][u], vb.y, acc[qi][5]);
                    acc[qi][6] = fmaf(pv[qi][u], vb.z, acc[qi][6]);
                    acc[qi][7] = fmaf(pv[qi][u], vb.w, acc[qi][7]);
                }
            }
        }
    }

#pragma unroll
    for (int qi = 0; qi < 4; qi++) {
        if (qok[qi] && lr[qi] > 0.f) {
            float inv = 1.f / lr[qi];
            unsigned hw[4], lw[4];
#pragma unroll
            for (int k = 0; k < 4; k++)
                split2(acc[qi][2 * k] * inv, acc[qi][2 * k + 1] * inv, hw[k], lw[k]);
            size_t off = ((p0 + qbase + q[qi]) * D + hh * HD + tg * 8) * 2;
            *(uint4*)((char*)ohi + off) = make_uint4(hw[0], hw[1], hw[2], hw[3]);
            *(uint4*)((char*)olo + off) = make_uint4(lw[0], lw[1], lw[2], lw[3]);
        }
    }
}

// ---------------- host orchestration ----------------
extern "C" void kernel_launch(void* const* d_in, const int* in_sizes, int n_in,
                              void* d_out, int out_size) {
    const float* x   = (const float*)d_in[0];
    const void* edge = d_in[1];
    const void* mask = d_in[2];
    const void* ptr  = d_in[3];
    const float* gw1   = (const float*)d_in[4];
    const float* gb1   = (const float*)d_in[5];
    const float* gw2   = (const float*)d_in[6];
    const float* gb2   = (const float*)d_in[7];
    const float* gamma = (const float*)d_in[8];
    const float* beta  = (const float*)d_in[9];
    const float* sw    = (const float*)d_in[10];
    const float* sb    = (const float*)d_in[11];
    const float* qkw   = (const float*)d_in[12];
    const float* qkb   = (const float*)d_in[13];
    const float* vw    = (const float*)d_in[14];
    const float* vb    = (const float*)d_in[15];
    const float* ow    = (const float*)d_in[16];
    const float* ob    = (const float*)d_in[17];
    float* out = (float*)d_out;

    int N  = in_sizes[0] / D;
    int E  = in_sizes[1] / 2;
    int Bg = in_sizes[3] - 1;
    int ngin = in_sizes[4] / (D * D);
    int L;
    {
        long long ll = (long long)in_sizes[2] / Bg;
        int l = 1;
        while ((long long)l * l < ll) l++;
        L = l;
    }
    long long masktotal = (long long)Bg * L * L;
    if (N > NMAX || masktotal > MASKMAX || ngin > 3 || E > EMAX) return;

    float *pv, *ph, *pqk, *pbf, *pzero;
    double* pstats;
    __nv_bfloat16 *whi, *wlo, *shi0, *slo0, *shi1, *slo1, *wfhi, *wflo;
    int* pdeg;
    cudaGetSymbolAddress((void**)&pv,    g_v);
    cudaGetSymbolAddress((void**)&ph,    g_h);
    cudaGetSymbolAddress((void**)&pqk,   g_qk);
    cudaGetSymbolAddress((void**)&pstats, g_stats);
    cudaGetSymbolAddress((void**)&whi,   g_whi);
    cudaGetSymbolAddress((void**)&wlo,   g_wlo);
    cudaGetSymbolAddress((void**)&shi0,  g_shi0);
    cudaGetSymbolAddress((void**)&slo0,  g_slo0);
    cudaGetSymbolAddress((void**)&shi1,  g_shi1);
    cudaGetSymbolAddress((void**)&slo1,  g_slo1);
    cudaGetSymbolAddress((void**)&wfhi,  g_wfhi);
    cudaGetSymbolAddress((void**)&wflo,  g_wflo);
    cudaGetSymbolAddress((void**)&pbf,   g_bf);
    cudaGetSymbolAddress((void**)&pzero, g_zero);
    cudaGetSymbolAddress((void**)&pdeg,  g_deg);

    cudaFuncSetAttribute(pgemm_kernel<false, false, true, false>,
                         cudaFuncAttributeMaxDynamicSharedMemorySize, GEMM_SMEM);
    cudaFuncSetAttribute(pgemm_kernel<true, true, false, false>,
                         cudaFuncAttributeMaxDynamicSharedMemorySize, GEMM_SMEM);
    cudaFuncSetAttribute(pgemm_kernel<true, false, true, false>,
                         cudaFuncAttributeMaxDynamicSharedMemorySize, GEMM_SMEM);
    cudaFuncSetAttribute(pgemm_kernel<false, true, false, true>,
                         cudaFuncAttributeMaxDynamicSharedMemorySize, GEMM_SMEM);
    cudaFuncSetAttribute(attn_kernel,
                         cudaFuncAttributeMaxDynamicSharedMemorySize, ATTN_SMEM);

    const size_t SZ = (size_t)D * D;
    size_t off_v = 0, off_g1[3], off_g2[3];
    size_t cur = SZ;
    for (int i = 0; i < 3; i++) { off_g1[i] = cur; cur += SZ; off_g2[i] = cur; cur += SZ; }
    size_t off_se = cur; cur += SZ;
    size_t off_qk = cur; cur += 2 * SZ;
    size_t off_o  = cur;

    WJobs J;
    int jn = 0, rows = 0;
    auto addjob = [&](const float* src, size_t off, int Nc) {
        J.src[jn] = src; J.hi[jn] = whi + off; J.lo[jn] = wlo + off;
        J.N[jn] = Nc; J.row0[jn] = rows;
        rows += Nc; jn++;
    };
    addjob(vw, off_v, D);
    for (int i = 0; i < ngin; i++) {
        addjob(gw1 + SZ * i, off_g1[i], D);
        addjob(gw2 + SZ * i, off_g2[i], D);
    }
    addjob(qkw, off_qk, 2 * D);
    addjob(ow, off_o, D);
    J.njobs = jn;

    int mt = (N + 63) / 64;
    dim3 g512(D / 128, mt);          // 4 x 190
    dim3 g1024(2 * D / 128, mt);     // 8 x 190
    dim3 gprep(2 * D / 128, 512 / 64);  // 8 x 8 (W' = se_w @ qk_w)

    detect_kernel<<<1, 256>>>((const int*)edge, (const int*)ptr, (const unsigned int*)mask);
    asplit_kernel<<<N, 128>>>(x, shi0, slo0);
    wsplit_all_kernel<<<rows, 256>>>(J);
    pgemm_kernel<false, false, true, false><<<g512, 256, GEMM_SMEM>>>(      // v = x@vw
        shi0, slo0, whi + off_v, wlo + off_v, vb, pv, nullptr, nullptr, N, D);

    // fused se->qk weight prep: W' = se_w @ qk_w (transposed split out), b' = se_b@qk_w + qk_b
    asplit_kernel<<<512, 128>>>(sw, shi1, slo1);
    pgemm_kernel<false, true, false, true><<<gprep, 256, GEMM_SMEM>>>(
        shi1, slo1, whi + off_qk, wlo + off_qk, pzero, nullptr, wfhi, wflo, 512, 2 * D);
    bfold_kernel<<<4, 256>>>(sb, qkw, qkb);

    mask_convert_kernel<<<(unsigned)((masktotal + 511) / 512), 512>>>(mask, masktotal);
    cudaMemsetAsync(pdeg, 0, (size_t)N * sizeof(int));
    csr_count_kernel<<<(E + 255) / 256, 256>>>(edge, E);
    csr_scan_kernel<<<1, 1024>>>(N);
    csr_fill_kernel<<<(E + 255) / 256, 256>>>(edge, E);

    const float* hin = x;
    for (int i = 0; i < ngin; i++) {
        gather_kernel<<<N, 128>>>(hin, shi1, slo1);                          // split(h+agg) -> S1
        pgemm_kernel<true, true, false, false><<<g512, 256, GEMM_SMEM>>>(    // relu(z@w1+b1) -> S0
            shi1, slo1, whi + off_g1[i], wlo + off_g1[i], gb1 + (size_t)i * D,
            nullptr, shi0, slo0, N, D);
        pgemm_kernel<true, false, true, false><<<g512, 256, GEMM_SMEM>>>(    // relu(.@w2+b2) -> h f32
            shi0, slo0, whi + off_g2[i], wlo + off_g2[i], gb2 + (size_t)i * D,
            ph, nullptr, nullptr, N, D);
        hin = ph;
    }

    cudaMemsetAsync(pstats, 0, 2 * D * sizeof(double));
    bn_stats_kernel<<<256, D>>>(ph, N);
    bn_apply_kernel<<<(unsigned)(((long long)N * (D / 2) + 255) / 256), 256>>>(
        ph, gamma, beta, shi1, slo1, N);                                     // bn -> S1 split

    // qk = bn @ W' + b'   (se GEMM folded away)
    pgemm_kernel<false, false, true, false><<<g1024, 256, GEMM_SMEM>>>(
        shi1, slo1, wfhi, wflo, pbf, pqk, nullptr, nullptr, N, 2 * D);

    dim3 gattn((L + QT - 1) / QT, NHEAD, Bg);
    attn_kernel<<<gattn, 128, ATTN_SMEM>>>(ptr, L, shi1, slo1);              // attn -> S1 split

    pgemm_kernel<false, false, true, false><<<g512, 256, GEMM_SMEM>>>(       // out
        shi1, slo1, whi + off_o, wlo + off_o, ob, out, nullptr, nullptr, N, D);
}

// round 13
// speedup vs baseline: 1.0067x; 1.0067x over previous
#include <cuda_runtime.h>
#include <cuda_bf16.h>
#include <math.h>

#define D 512
#define NMAX 12288
#define HD 64
#define NHEAD 8
#define MASKMAX (32 * 512 * 512)
#define WELEMS 2883584   // 11 * 512 * 512 weight elements total
#define EMAX (16 * NMAX)
#define QT 64
#define ATTN_SMEM ((64 * 68 * 3 + 64 * 72) * 4)

// ---------------- scratch (static device globals; no allocation) ----------------
__device__ float  g_v  [NMAX * D];
__device__ float  g_h  [NMAX * D];
__device__ float  g_qk [NMAX * 2 * D];
__device__ double g_stats[2 * D];
__device__ unsigned char g_mask[MASKMAX];
__device__ __nv_bfloat16 g_whi[WELEMS];
__device__ __nv_bfloat16 g_wlo[WELEMS];
__device__ __nv_bfloat16 g_shi0[NMAX * D];
__device__ __nv_bfloat16 g_slo0[NMAX * D];
__device__ __nv_bfloat16 g_shi1[NMAX * D];
__device__ __nv_bfloat16 g_slo1[NMAX * D];
__device__ __nv_bfloat16 g_wfhi[1024 * 512];   // fused se@qk weight, [n][k] split
__device__ __nv_bfloat16 g_wflo[1024 * 512];
__device__ float  g_bf[1024];                   // fused bias
__device__ float  g_zero[1024];                 // zero bias (never written)
__device__ int    g_flags[4];
__device__ int    g_deg [NMAX];
__device__ int    g_bse [NMAX];
__device__ int    g_cur [NMAX];
__device__ int    g_eidx[EMAX];

__device__ __forceinline__ long long ldidx(const void* p, int is64, long long i) {
    if (is64) return ((const long long*)p)[i];
    return (long long)((const int*)p)[i];
}

__device__ __forceinline__ unsigned smem_u32(const void* p) {
    unsigned a;
    asm("{ .reg .u64 t; cvta.to.shared.u64 t, %1; cvt.u32.u64 %0, t; }" : "=r"(a) : "l"(p));
    return a;
}

__device__ __forceinline__ unsigned pack_bf2(float x, float y) {
    __nv_bfloat162 p(__float2bfloat16(x), __float2bfloat16(y));
    return *(unsigned*)&p;
}
__device__ __forceinline__ void split2(float x, float y, unsigned& hiw, unsigned& low) {
    __nv_bfloat16 hx = __float2bfloat16(x), hy = __float2bfloat16(y);
    __nv_bfloat162 hp(hx, hy);
    hiw = *(unsigned*)&hp;
    low = pack_bf2(x - __bfloat162float(hx), y - __bfloat162float(hy));
}

// ---------------- detection (parallel; see R1/R2 notes for the patterns) ----------------
__global__ void detect_kernel(const int* __restrict__ ew, const int* __restrict__ pw,
                              const unsigned int* __restrict__ mw) {
    __shared__ int bad;
    if (threadIdx.x == 0) bad = 0;
    __syncthreads();
    int ok = 1;
    for (int i = threadIdx.x; i < 4096; i += 256) {
        unsigned int w = mw[i];
        if (w != 0u && w != 1u && w != 0x3f800000u) { ok = 0; break; }
    }
    if (!ok) atomicExch(&bad, 1);
    __syncthreads();
    if (threadIdx.x == 0) {
        g_flags[0] = (ew[17] == 0) ? 1 : 0;
        g_flags[1] = (pw[1]  == 0) ? 1 : 0;
        g_flags[2] = bad ? 0 : 1;
    }
}

__global__ void mask_convert_kernel(const void* __restrict__ mask, long long total) {
    long long i = (long long)blockIdx.x * blockDim.x + threadIdx.x;
    if (i >= total) return;
    unsigned char m;
    if (g_flags[2]) m = (((const unsigned int*)mask)[i] != 0u) ? 1 : 0;
    else            m = (((const unsigned char*)mask)[i] != 0) ? 1 : 0;
    g_mask[i] = m;
}

// ---------------- fused weight split (fp32 -> bf16 hi/lo, transpose to [N][K]) ----------------
struct WJobs {
    const float* src[12];
    __nv_bfloat16* hi[12];
    __nv_bfloat16* lo[12];
    int N[12];
    int row0[12];
    int njobs;
};

__global__ void wsplit_all_kernel(WJobs J) {
    int row = blockIdx.x;
    int j = 0;
    while (j + 1 < J.njobs && row >= J.row0[j + 1]) j++;
    int n = row - J.row0[j];
    int Nc = J.N[j];
    const float* src = J.src[j];
    __nv_bfloat16* hi = J.hi[j];
    __nv_bfloat16* lo = J.lo[j];
    for (int k = threadIdx.x; k < 512; k += blockDim.x) {
        float v = src[(size_t)k * Nc + n];
        __nv_bfloat16 h = __float2bfloat16(v);
        hi[(size_t)n * 512 + k] = h;
        lo[(size_t)n * 512 + k] = __float2bfloat16(v - __bfloat162float(h));
    }
}

// ---------------- activation split (x -> bf16 hi/lo, row-major) ----------------
__global__ void __launch_bounds__(128)
asplit_kernel(const float* __restrict__ x, __nv_bfloat16* __restrict__ hi,
              __nv_bfloat16* __restrict__ lo) {
    int node = blockIdx.x, t = threadIdx.x;
    float4 v = *(const float4*)(x + (size_t)node * D + t * 4);
    unsigned h0, l0, h1, l1;
    split2(v.x, v.y, h0, l0);
    split2(v.z, v.w, h1, l1);
    *(uint2*)((char*)hi + ((size_t)node * D + t * 4) * 2) = make_uint2(h0, h1);
    *(uint2*)((char*)lo + ((size_t)node * D + t * 4) * 2) = make_uint2(l0, l1);
}

// ---------------- fused bias: b' = se_b @ qk_w + qk_b ----------------
__global__ void bfold_kernel(const float* __restrict__ seb, const float* __restrict__ qkw,
                             const float* __restrict__ qkb) {
    int j = blockIdx.x * blockDim.x + threadIdx.x;   // 1024 outputs
    float s = qkb[j];
    for (int k = 0; k < 512; k++) s = fmaf(seb[k], qkw[(size_t)k * 1024 + j], s);
    g_bf[j] = s;
}

// ---------------- in-edge CSR build (once per launch) ----------------
__global__ void csr_count_kernel(const void* __restrict__ edge, int E) {
    int e = blockIdx.x * blockDim.x + threadIdx.x;
    if (e >= E) return;
    int is64 = g_flags[0];
    long long t = ldidx(edge, is64, (long long)E + e);
    atomicAdd(&g_deg[t], 1);
}

__global__ void csr_scan_kernel(int N) {
    __shared__ int ss[1024];
    int t = threadIdx.x;
    int chunk = (N + 1023) >> 10;
    int s0 = t * chunk, s1 = min(s0 + chunk, N);
    int sum = 0;
    for (int i = s0; i < s1; i++) sum += g_deg[i];
    ss[t] = sum;
    __syncthreads();
    for (int off = 1; off < 1024; off <<= 1) {
        int v = (t >= off) ? ss[t - off] : 0;
        __syncthreads();
        ss[t] += v;
        __syncthreads();
    }
    int base = (t == 0) ? 0 : ss[t - 1];
    for (int i = s0; i < s1; i++) {
        g_bse[i] = base;
        g_cur[i] = base;
        base += g_deg[i];
    }
}

__global__ void csr_fill_kernel(const void* __restrict__ edge, int E) {
    int e = blockIdx.x * blockDim.x + threadIdx.x;
    if (e >= E) return;
    int is64 = g_flags[0];
    long long s = ldidx(edge, is64, e);
    long long t = ldidx(edge, is64, (long long)E + e);
    int pos = atomicAdd(&g_cur[t], 1);
    g_eidx[pos] = (int)s;
}

// ---------------- GIN aggregation: gather + self-add + split (no atomics) ----------------
__global__ void __launch_bounds__(128)
gather_kernel(const float* __restrict__ h, __nv_bfloat16* __restrict__ ohi,
              __nv_bfloat16* __restrict__ olo) {
    int node = blockIdx.x;
    int d4 = threadIdx.x;
    int base = g_bse[node], deg = g_deg[node];
    float4 acc = *(const float4*)(h + (size_t)node * D + d4 * 4);
    int j = 0;
    for (; j + 4 <= deg; j += 4) {
        int s0 = g_eidx[base + j];
        int s1 = g_eidx[base + j + 1];
        int s2 = g_eidx[base + j + 2];
        int s3 = g_eidx[base + j + 3];
        float4 v0 = *(const float4*)(h + (size_t)s0 * D + d4 * 4);
        float4 v1 = *(const float4*)(h + (size_t)s1 * D + d4 * 4);
        float4 v2 = *(const float4*)(h + (size_t)s2 * D + d4 * 4);
        float4 v3 = *(const float4*)(h + (size_t)s3 * D + d4 * 4);
        acc.x += v0.x + v1.x + v2.x + v3.x;
        acc.y += v0.y + v1.y + v2.y + v3.y;
        acc.z += v0.z + v1.z + v2.z + v3.z;
        acc.w += v0.w + v1.w + v2.w + v3.w;
    }
    for (; j < deg; j++) {
        int src = g_eidx[base + j];
        float4 v = *(const float4*)(h + (size_t)src * D + d4 * 4);
        acc.x += v.x; acc.y += v.y; acc.z += v.z; acc.w += v.w;
    }
    unsigned h0, l0, h1, l1;
    split2(acc.x, acc.y, h0, l0);
    split2(acc.z, acc.w, h1, l1);
    *(uint2*)((char*)ohi + ((size_t)node * D + d4 * 4) * 2) = make_uint2(h0, h1);
    *(uint2*)((char*)olo + ((size_t)node * D + d4 * 4) * 2) = make_uint2(l0, l1);
}

// ---------------- pipelined tensor-core GEMM (pre-split bf16 A and B, fp32 accum) ----------------
// 64x128 tile, 256 thr, 8 warps (2x4 of 32x32), BK=32, 3-stage cp.async pipeline,
// 64B rows with SW64 chunk swizzle, 3 CTAs/SM. ONE barrier per stage iteration.
#define OFF_ALO 4096u
#define OFF_BHI 8192u
#define OFF_BLO 16384u
#define STAGEB  24576u
#define GEMM_SMEM (3 * 24576 + 128)

#define LDM4(r0, r1, r2, r3, addr) \
    asm volatile("ldmatrix.sync.aligned.m8n8.x4.shared.b16 {%0,%1,%2,%3}, [%4];" \
                 : "=r"(r0), "=r"(r1), "=r"(r2), "=r"(r3) : "r"(addr))
#define CP16(dst, src) \
    asm volatile("cp.async.cg.shared.global [%0], [%1], 16;" :: "r"(dst), "l"(src))
#define CPCOMMIT() asm volatile("cp.async.commit_group;" ::: "memory")
#define CPWAIT1()  asm volatile("cp.async.wait_group 1;" ::: "memory")

__device__ __forceinline__ void mma_bf16(float* c, unsigned a0, unsigned a1, unsigned a2,
                                         unsigned a3, unsigned b0, unsigned b1) {
    asm volatile(
        "mma.sync.aligned.m16n8k16.row.col.f32.bf16.bf16.f32 "
        "{%0,%1,%2,%3}, {%4,%5,%6,%7}, {%8,%9}, {%0,%1,%2,%3};"
        : "+f"(c[0]), "+f"(c[1]), "+f"(c[2]), "+f"(c[3])
        : "r"(a0), "r"(a1), "r"(a2), "r"(a3), "r"(b0), "r"(b1));
}

template <bool RELU, bool WSPLIT, bool WF32, bool WT>
__global__ void __launch_bounds__(256, 3)
pgemm_kernel(const __nv_bfloat16* __restrict__ Ahi, const __nv_bfloat16* __restrict__ Alo,
             const __nv_bfloat16* __restrict__ Bhi, const __nv_bfloat16* __restrict__ Blo,
             const float* __restrict__ bias, float* __restrict__ C,
             __nv_bfloat16* __restrict__ Ohi, __nv_bfloat16* __restrict__ Olo,
             int M, int Nc) {
    extern __shared__ char dynsmem[];
    unsigned sb = (smem_u32(dynsmem) + 127) & ~127u;

    int tid = threadIdx.x, wid = tid >> 5, lane = tid & 31;
    int m0 = blockIdx.y * 64, n0 = blockIdx.x * 128;
    int warp_m = (wid & 1) * 32, warp_n = (wid >> 1) * 32;
    int g = lane >> 2, kp = (lane & 3) * 2;

    // cp.async maps: A = 64 rows x 4 chunks (1 per thread); B = 128 rows x 4 chunks (2 per thread)
    int crow = tid >> 2, cch = tid & 3;
    unsigned dstA = (unsigned)(crow * 64 + ((cch ^ ((crow >> 1) & 3)) * 16));
    long long arow = m0 + crow; if (arow > M - 1) arow = M - 1;
    const __nv_bfloat16* pAhi = Ahi + arow * 512 + cch * 8;
    const __nv_bfloat16* pAlo = Alo + arow * 512 + cch * 8;
    int brow2 = crow + 64;
    unsigned dstB0 = dstA;
    unsigned dstB1 = (unsigned)(brow2 * 64 + ((cch ^ ((brow2 >> 1) & 3)) * 16));
    const __nv_bfloat16* pBhi0 = Bhi + (size_t)(n0 + crow) * 512 + cch * 8;
    const __nv_bfloat16* pBhi1 = Bhi + (size_t)(n0 + brow2) * 512 + cch * 8;
    const __nv_bfloat16* pBlo0 = Blo + (size_t)(n0 + crow) * 512 + cch * 8;
    const __nv_bfloat16* pBlo1 = Blo + (size_t)(n0 + brow2) * 512 + cch * 8;

    // ldmatrix per-lane offsets (swizzle term depends only on row mod 16)
    int rA = lane & 15, hA = lane >> 4;
    unsigned aoff = (unsigned)((warp_m + rA) * 64 + ((hA ^ ((rA >> 1) & 3)) * 16));
    int rB = (lane & 7) + ((lane >> 4) * 8);
    int cB = (lane >> 3) & 1;
    unsigned boff = (unsigned)((warp_n + rB) * 64 + ((cB ^ ((rB >> 1) & 3)) * 16));

    float acc[2][4][4];
#pragma unroll
    for (int i = 0; i < 2; i++)
#pragma unroll
        for (int j = 0; j < 4; j++)
#pragma unroll
            for (int r = 0; r < 4; r++) acc[i][j][r] = 0.f;

    // prologue: stages 0 and 1
#pragma unroll
    for (int s = 0; s < 2; s++) {
        unsigned bb = sb + (unsigned)s * STAGEB;
        int kg = s * 32;
        CP16(bb + dstA,            pAhi + kg);
        CP16(bb + OFF_ALO + dstA,  pAlo + kg);
        CP16(bb + OFF_BHI + dstB0, pBhi0 + kg);
        CP16(bb + OFF_BHI + dstB1, pBhi1 + kg);
        CP16(bb + OFF_BLO + dstB0, pBlo0 + kg);
        CP16(bb + OFF_BLO + dstB1, pBlo1 + kg);
        CPCOMMIT();
    }

    unsigned bufoff[3] = {0u, STAGEB, 2u * STAGEB};
#pragma unroll 1
    for (int s = 0; s < 16; s++) {
        CPWAIT1();
        __syncthreads();   // all finished compute s-1; stage-s data visible to everyone
        if (s + 2 < 16) {
            unsigned bb = sb + bufoff[(s + 2) % 3];
            int kg = (s + 2) * 32;
            CP16(bb + dstA,            pAhi + kg);
            CP16(bb + OFF_ALO + dstA,  pAlo + kg);
            CP16(bb + OFF_BHI + dstB0, pBhi0 + kg);
            CP16(bb + OFF_BHI + dstB1, pBhi1 + kg);
            CP16(bb + OFF_BLO + dstB0, pBlo0 + kg);
            CP16(bb + OFF_BLO + dstB1, pBlo1 + kg);
        }
        CPCOMMIT();

        unsigned bcur = sb + bufoff[s % 3];
#pragma unroll
        for (int kx = 0; kx < 2; kx++) {
            unsigned kxor = kx ? 32u : 0u;
            unsigned ah[2][4], al[2][4], bh[4][2], bl[4][2];
#pragma unroll
            for (int mi = 0; mi < 2; mi++)
                LDM4(ah[mi][0], ah[mi][1], ah[mi][2], ah[mi][3],
                     bcur + (unsigned)(mi * 1024) + (aoff ^ kxor));
            {
                unsigned r0, r1, r2, r3;
#pragma unroll
                for (int p = 0; p < 2; p++) {
                    LDM4(r0, r1, r2, r3, bcur + OFF_BHI + (unsigned)(p * 1024) + (boff ^ kxor));
                    bh[2 * p][0] = r0; bh[2 * p][1] = r1;
                    bh[2 * p + 1][0] = r2; bh[2 * p + 1][1] = r3;
                    LDM4(r0, r1, r2, r3, bcur + OFF_BLO + (unsigned)(p * 1024) + (boff ^ kxor));
                    bl[2 * p][0] = r0; bl[2 * p][1] = r1;
                    bl[2 * p + 1][0] = r2; bl[2 * p + 1][1] = r3;
                }
            }
#pragma unroll
            for (int mi = 0; mi < 2; mi++)
                LDM4(al[mi][0], al[mi][1], al[mi][2], al[mi][3],
                     bcur + OFF_ALO + (unsigned)(mi * 1024) + (aoff ^ kxor));
#pragma unroll
            for (int mi = 0; mi < 2; mi++)
#pragma unroll
                for (int ni = 0; ni < 4; ni++)
                    mma_bf16(acc[mi][ni], ah[mi][0], ah[mi][1], ah[mi][2], ah[mi][3],
                             bh[ni][0], bh[ni][1]);
#pragma unroll
            for (int mi = 0; mi < 2; mi++)
#pragma unroll
                for (int ni = 0; ni < 4; ni++)
                    mma_bf16(acc[mi][ni], ah[mi][0], ah[mi][1], ah[mi][2], ah[mi][3],
                             bl[ni][0], bl[ni][1]);
#pragma unroll
            for (int mi = 0; mi < 2; mi++)
#pragma unroll
                for (int ni = 0; ni < 4; ni++)
                    mma_bf16(acc[mi][ni], al[mi][0], al[mi][1], al[mi][2], al[mi][3],
                             bh[ni][0], bh[ni][1]);
        }
        // trailing __syncthreads removed: next iteration's barrier (after its own
        // CPWAIT) provides the ordering before any thread writes buffer (s+3)%3.
    }

    // epilogue
#pragma unroll
    for (int mi = 0; mi < 2; mi++) {
        int row0 = m0 + warp_m + mi * 16 + g;
        int row1 = row0 + 8;
#pragma unroll
        for (int ni = 0; ni < 4; ni++) {
            int col = n0 + warp_n + ni * 8 + kp;
            float b0 = bias[col], b1 = bias[col + 1];
            float o0 = acc[mi][ni][0] + b0, o1 = acc[mi][ni][1] + b1;
            float o2 = acc[mi][ni][2] + b0, o3 = acc[mi][ni][3] + b1;
            if (RELU) {
                o0 = fmaxf(o0, 0.f); o1 = fmaxf(o1, 0.f);
                o2 = fmaxf(o2, 0.f); o3 = fmaxf(o3, 0.f);
            }
            if (row0 < M) {
                if (WF32)
                    *(float2*)(C + (size_t)row0 * Nc + col) = make_float2(o0, o1);
                if (WSPLIT && !WT) {
                    unsigned hw, lw;
                    split2(o0, o1, hw, lw);
                    *(unsigned*)((char*)Ohi + ((size_t)row0 * Nc + col) * 2) = hw;
                    *(unsigned*)((char*)Olo + ((size_t)row0 * Nc + col) * 2) = lw;
                }
                if (WT) {
                    __nv_bfloat16 h0 = __float2bfloat16(o0);
                    __nv_bfloat16 h1 = __float2bfloat16(o1);
                    Ohi[(size_t)col * 512 + row0] = h0;
                    Olo[(size_t)col * 512 + row0] = __float2bfloat16(o0 - __bfloat162float(h0));
                    Ohi[(size_t)(col + 1) * 512 + row0] = h1;
                    Olo[(size_t)(col + 1) * 512 + row0] = __float2bfloat16(o1 - __bfloat162float(h1));
                }
            }
            if (row1 < M) {
                if (WF32)
                    *(float2*)(C + (size_t)row1 * Nc + col) = make_float2(o2, o3);
                if (WSPLIT && !WT) {
                    unsigned hw, lw;
                    split2(o2, o3, hw, lw);
                    *(unsigned*)((char*)Ohi + ((size_t)row1 * Nc + col) * 2) = hw;
                    *(unsigned*)((char*)Olo + ((size_t)row1 * Nc + col) * 2) = lw;
                }
                if (WT) {
                    __nv_bfloat16 h2 = __float2bfloat16(o2);
                    __nv_bfloat16 h3 = __float2bfloat16(o3);
                    Ohi[(size_t)col * 512 + row1] = h2;
                    Olo[(size_t)col * 512 + row1] = __float2bfloat16(o2 - __bfloat162float(h2));
                    Ohi[(size_t)(col + 1) * 512 + row1] = h3;
                    Olo[(size_t)(col + 1) * 512 + row1] = __float2bfloat16(o3 - __bfloat162float(h3));
                }
            }
        }
    }
}

// ---------------- BatchNorm ----------------
__global__ void bn_stats_kernel(const float* __restrict__ h, int N) {
    int c = threadIdx.x;
    double s = 0.0, s2 = 0.0;
    for (int r = blockIdx.x; r < N; r += gridDim.x) {
        float v = h[(size_t)r * D + c];
        s += v;
        s2 += (double)v * v;
    }
    atomicAdd(&g_stats[c], s);
    atomicAdd(&g_stats[D + c], s2);
}

__global__ void bn_apply_kernel(const float* __restrict__ h, const float* __restrict__ gamma,
                                const float* __restrict__ beta,
                                __nv_bfloat16* __restrict__ ohi, __nv_bfloat16* __restrict__ olo,
                                int N) {
    long long i = (long long)blockIdx.x * blockDim.x + threadIdx.x;
    if (i >= (long long)N * (D / 2)) return;
    int p = (int)(i & (D / 2 - 1));
    long long row = i >> 8;
    int c0 = 2 * p, c1 = c0 + 1;
    double mean0 = g_stats[c0] / N, mean1 = g_stats[c1] / N;
    double var0  = g_stats[D + c0] / N - mean0 * mean0;
    double var1  = g_stats[D + c1] / N - mean1 * mean1;
    float is0 = rsqrtf((float)var0 + 1e-5f), is1 = rsqrtf((float)var1 + 1e-5f);
    float2 v = *(const float2*)(h + row * D + c0);
    float o0 = (v.x - (float)mean0) * is0 * gamma[c0] + beta[c0];
    float o1 = (v.y - (float)mean1) * is1 * gamma[c1] + beta[c1];
    unsigned hw, lw;
    split2(o0, o1, hw, lw);
    *(unsigned*)((char*)ohi + (row * D + c0) * 2) = hw;
    *(unsigned*)((char*)olo + (row * D + c0) * 2) = lw;
}

// ---------------- masked attention, 4-query register blocking, split output ----------------
// Scale 0.125 folded into the Q smem fill (exact: power-of-two multiply).
__global__ void __launch_bounds__(128)
attn_kernel(const void* __restrict__ ptr, int L,
            __nv_bfloat16* __restrict__ ohi, __nv_bfloat16* __restrict__ olo) {
    extern __shared__ float asm_f[];
    float (*Qs)[68] = (float(*)[68])asm_f;
    float (*Ks)[68] = (float(*)[68])(asm_f + 64 * 68);
    float (*Vs)[68] = (float(*)[68])(asm_f + 2 * 64 * 68);
    float (*Ps)[72] = (float(*)[72])(asm_f + 3 * 64 * 68);

    int qt = blockIdx.x, hh = blockIdx.y, b = blockIdx.z;
    int is64 = g_flags[1];
    long long p0 = ldidx(ptr, is64, b);
    long long p1 = ldidx(ptr, is64, b + 1);
    int s = (int)(p1 - p0);
    int qbase = qt * QT;
    if (qbase >= s) return;

    int tid = threadIdx.x;
    int tq4 = tid >> 3, tg = tid & 7;
    int q[4];
    bool qok[4];
    const unsigned char* mrow[4];
#pragma unroll
    for (int qi = 0; qi < 4; qi++) {
        q[qi] = 4 * tq4 + qi;
        qok[qi] = (qbase + q[qi]) < s;
        mrow[qi] = g_mask + ((size_t)b * L + (qok[qi] ? qbase + q[qi] : 0)) * L;
    }

    for (int i = tid; i < QT * 16; i += 128) {
        int r = i >> 4, c4 = i & 15;
        float4 val = make_float4(0.f, 0.f, 0.f, 0.f);
        if (qbase + r < s) {
            val = *(const float4*)(g_qk + (p0 + qbase + r) * (2 * D) + D + hh * HD + c4 * 4);
            val.x *= 0.125f; val.y *= 0.125f; val.z *= 0.125f; val.w *= 0.125f;
        }
        *(float4*)&Qs[r][c4 * 4] = val;
    }

    float acc[4][8], mr[4], lr[4];
#pragma unroll
    for (int qi = 0; qi < 4; qi++) {
        mr[qi] = -1e30f; lr[qi] = 0.f;
#pragma unroll
        for (int dd = 0; dd < 8; dd++) acc[qi][dd] = 0.f;
    }

    for (int j0 = 0; j0 < s; j0 += 64) {
        __syncthreads();
        for (int i = tid; i < 64 * 16; i += 128) {
            int r = i >> 4, c4 = i & 15;
            float4 kv = make_float4(0.f, 0.f, 0.f, 0.f);
            float4 vv = kv;
            if (j0 + r < s) {
                long long node = p0 + j0 + r;
                kv = *(const float4*)(g_qk + node * (2 * D) + hh * HD + c4 * 4);
                vv = *(const float4*)(g_v + node * D + hh * HD + c4 * 4);
            }
            *(float4*)&Ks[r][c4 * 4] = kv;
            *(float4*)&Vs[r][c4 * 4] = vv;
        }
        __syncthreads();

        float sc[4][8];
#pragma unroll
        for (int qi = 0; qi < 4; qi++)
#pragma unroll
            for (int jj = 0; jj < 8; jj++) sc[qi][jj] = 0.f;
#pragma unroll
        for (int d4 = 0; d4 < 16; d4++) {
            float4 qv[4];
#pragma unroll
            for (int qi = 0; qi < 4; qi++) qv[qi] = *(float4*)&Qs[q[qi]][d4 * 4];
#pragma unroll
            for (int jj = 0; jj < 8; jj++) {
                float4 k4 = *(float4*)&Ks[jj * 8 + tg][d4 * 4];
#pragma unroll
                for (int qi = 0; qi < 4; qi++) {
                    sc[qi][jj] = fmaf(qv[qi].x, k4.x, sc[qi][jj]);
                    sc[qi][jj] = fmaf(qv[qi].y, k4.y, sc[qi][jj]);
                    sc[qi][jj] = fmaf(qv[qi].z, k4.z, sc[qi][jj]);
                    sc[qi][jj] = fmaf(qv[qi].w, k4.w, sc[qi][jj]);
                }
            }
        }
#pragma unroll
        for (int qi = 0; qi < 4; qi++)
#pragma unroll
            for (int jj = 0; jj < 8; jj++) {
                int j = jj * 8 + tg;
                bool valid = (j0 + j < s) && (mrow[qi][j0 + j] == 0);
                sc[qi][jj] = valid ? sc[qi][jj] : -1e30f;
            }
#pragma unroll
        for (int qi = 0; qi < 4; qi++) {
            float mt = sc[qi][0];
#pragma unroll
            for (int jj = 1; jj < 8; jj++) mt = fmaxf(mt, sc[qi][jj]);
#pragma unroll
            for (int off = 1; off < 8; off <<= 1)
                mt = fmaxf(mt, __shfl_xor_sync(0xffffffffu, mt, off));
            float mn = fmaxf(mr[qi], mt);
            float corr = __expf(mr[qi] - mn);
            float ps = 0.f;
#pragma unroll
            for (int jj = 0; jj < 8; jj++) {
                float pv = (sc[qi][jj] <= -1e29f) ? 0.f : __expf(sc[qi][jj] - mn);
                Ps[q[qi]][jj * 8 + tg] = pv;
                ps += pv;
            }
#pragma unroll
            for (int off = 1; off < 8; off <<= 1)
                ps += __shfl_xor_sync(0xffffffffu, ps, off);
            lr[qi] = lr[qi] * corr + ps;
            mr[qi] = mn;
#pragma unroll
            for (int dd = 0; dd < 8; dd++) acc[qi][dd] *= corr;
        }
        __syncwarp();

#pragma unroll 2
        for (int j = 0; j < 64; j += 4) {
            float4 pq[4];
#pragma unroll
            for (int qi = 0; qi < 4; qi++) pq[qi] = *(float4*)&Ps[q[qi]][j];
            float pv[4][4] = {{pq[0].x, pq[0].y, pq[0].z, pq[0].w},
                              {pq[1].x, pq[1].y, pq[1].z, pq[1].w},
                              {pq[2].x, pq[2].y, pq[2].z, pq[2].w},
                              {pq[3].x, pq[3].y, pq[3].z, pq[3].w}};
#pragma unroll
            for (int u = 0; u < 4; u++) {
                float4 va = *(float4*)&Vs[j + u][tg * 8];
                float4 vb = *(float4*)&Vs[j + u][tg * 8 + 4];
#pragma unroll
                for (int qi = 0; qi < 4; qi++) {
                    acc[qi][0] = fmaf(pv[qi][u], va.x, acc[qi][0]);
                    acc[qi][1] = fmaf(pv[qi][u], va.y, acc[qi][1]);
                    acc[qi][2] = fmaf(pv[qi][u], va.z, acc[qi][2]);
                    acc[qi][3] = fmaf(pv[qi][u], va.w, acc[qi][3]);
                    acc[qi][4] = fmaf(pv[qi][u], vb.x, acc[qi][4]);
                    acc[qi][5] = fmaf(pv[qi][u], vb.y, acc[qi][5]);
                    acc[qi][6] = fmaf(pv[qi][u], vb.z, acc[qi][6]);
                    acc[qi][7] = fmaf(pv[qi][u], vb.w, acc[qi][7]);
                }
            }
        }
    }

#pragma unroll
    for (int qi = 0; qi < 4; qi++) {
        if (qok[qi] && lr[qi] > 0.f) {
            float inv = 1.f / lr[qi];
            unsigned hw[4], lw[4];
#pragma unroll
            for (int k = 0; k < 4; k++)
                split2(acc[qi][2 * k] * inv, acc[qi][2 * k + 1] * inv, hw[k], lw[k]);
            size_t off = ((p0 + qbase + q[qi]) * D + hh * HD + tg * 8) * 2;
            *(uint4*)((char*)ohi + off) = make_uint4(hw[0], hw[1], hw[2], hw[3]);
            *(uint4*)((char*)olo + off) = make_uint4(lw[0], lw[1], lw[2], lw[3]);
        }
    }
}

// ---------------- host orchestration ----------------
extern "C" void kernel_launch(void* const* d_in, const int* in_sizes, int n_in,
                              void* d_out, int out_size) {
    const float* x   = (const float*)d_in[0];
    const void* edge = d_in[1];
    const void* mask = d_in[2];
    const void* ptr  = d_in[3];
    const float* gw1   = (const float*)d_in[4];
    const float* gb1   = (const float*)d_in[5];
    const float* gw2   = (const float*)d_in[6];
    const float* gb2   = (const float*)d_in[7];
    const float* gamma = (const float*)d_in[8];
    const float* beta  = (const float*)d_in[9];
    const float* sw    = (const float*)d_in[10];
    const float* sb    = (const float*)d_in[11];
    const float* qkw   = (const float*)d_in[12];
    const float* qkb   = (const float*)d_in[13];
    const float* vw    = (const float*)d_in[14];
    const float* vb    = (const float*)d_in[15];
    const float* ow    = (const float*)d_in[16];
    const float* ob    = (const float*)d_in[17];
    float* out = (float*)d_out;

    int N  = in_sizes[0] / D;
    int E  = in_sizes[1] / 2;
    int Bg = in_sizes[3] - 1;
    int ngin = in_sizes[4] / (D * D);
    int L;
    {
        long long ll = (long long)in_sizes[2] / Bg;
        int l = 1;
        while ((long long)l * l < ll) l++;
        L = l;
    }
    long long masktotal = (long long)Bg * L * L;
    if (N > NMAX || masktotal > MASKMAX || ngin > 3 || E > EMAX) return;

    float *pv, *ph, *pqk, *pbf, *pzero;
    double* pstats;
    __nv_bfloat16 *whi, *wlo, *shi0, *slo0, *shi1, *slo1, *wfhi, *wflo;
    int* pdeg;
    cudaGetSymbolAddress((void**)&pv,    g_v);
    cudaGetSymbolAddress((void**)&ph,    g_h);
    cudaGetSymbolAddress((void**)&pqk,   g_qk);
    cudaGetSymbolAddress((void**)&pstats, g_stats);
    cudaGetSymbolAddress((void**)&whi,   g_whi);
    cudaGetSymbolAddress((void**)&wlo,   g_wlo);
    cudaGetSymbolAddress((void**)&shi0,  g_shi0);
    cudaGetSymbolAddress((void**)&slo0,  g_slo0);
    cudaGetSymbolAddress((void**)&shi1,  g_shi1);
    cudaGetSymbolAddress((void**)&slo1,  g_slo1);
    cudaGetSymbolAddress((void**)&wfhi,  g_wfhi);
    cudaGetSymbolAddress((void**)&wflo,  g_wflo);
    cudaGetSymbolAddress((void**)&pbf,   g_bf);
    cudaGetSymbolAddress((void**)&pzero, g_zero);
    cudaGetSymbolAddress((void**)&pdeg,  g_deg);

    cudaFuncSetAttribute(pgemm_kernel<false, false, true, false>,
                         cudaFuncAttributeMaxDynamicSharedMemorySize, GEMM_SMEM);
    cudaFuncSetAttribute(pgemm_kernel<true, true, false, false>,
                         cudaFuncAttributeMaxDynamicSharedMemorySize, GEMM_SMEM);
    cudaFuncSetAttribute(pgemm_kernel<true, false, true, false>,
                         cudaFuncAttributeMaxDynamicSharedMemorySize, GEMM_SMEM);
    cudaFuncSetAttribute(pgemm_kernel<false, true, false, true>,
                         cudaFuncAttributeMaxDynamicSharedMemorySize, GEMM_SMEM);
    cudaFuncSetAttribute(attn_kernel,
                         cudaFuncAttributeMaxDynamicSharedMemorySize, ATTN_SMEM);

    const size_t SZ = (size_t)D * D;
    size_t off_v = 0, off_g1[3], off_g2[3];
    size_t cur = SZ;
    for (int i = 0; i < 3; i++) { off_g1[i] = cur; cur += SZ; off_g2[i] = cur; cur += SZ; }
    size_t off_qk = cur; cur += 2 * SZ;
    size_t off_o  = cur;

    WJobs J;
    int jn = 0, rows = 0;
    auto addjob = [&](const float* src, size_t off, int Nc) {
        J.src[jn] = src; J.hi[jn] = whi + off; J.lo[jn] = wlo + off;
        J.N[jn] = Nc; J.row0[jn] = rows;
        rows += Nc; jn++;
    };
    addjob(vw, off_v, D);
    for (int i = 0; i < ngin; i++) {
        addjob(gw1 + SZ * i, off_g1[i], D);
        addjob(gw2 + SZ * i, off_g2[i], D);
    }
    addjob(qkw, off_qk, 2 * D);
    addjob(ow, off_o, D);
    J.njobs = jn;

    int mt = (N + 63) / 64;
    dim3 g512(D / 128, mt);          // 4 x 190
    dim3 g1024(2 * D / 128, mt);     // 8 x 190
    dim3 gprep(2 * D / 128, 512 / 64);  // 8 x 8 (W' = se_w @ qk_w)

    detect_kernel<<<1, 256>>>((const int*)edge, (const int*)ptr, (const unsigned int*)mask);
    asplit_kernel<<<N, 128>>>(x, shi0, slo0);
    wsplit_all_kernel<<<rows, 256>>>(J);
    pgemm_kernel<false, false, true, false><<<g512, 256, GEMM_SMEM>>>(      // v = x@vw
        shi0, slo0, whi + off_v, wlo + off_v, vb, pv, nullptr, nullptr, N, D);

    // fused se->qk weight prep: W' = se_w @ qk_w (transposed split out), b' = se_b@qk_w + qk_b
    asplit_kernel<<<512, 128>>>(sw, shi1, slo1);
    pgemm_kernel<false, true, false, true><<<gprep, 256, GEMM_SMEM>>>(
        shi1, slo1, whi + off_qk, wlo + off_qk, pzero, nullptr, wfhi, wflo, 512, 2 * D);
    bfold_kernel<<<4, 256>>>(sb, qkw, qkb);

    mask_convert_kernel<<<(unsigned)((masktotal + 511) / 512), 512>>>(mask, masktotal);
    cudaMemsetAsync(pdeg, 0, (size_t)N * sizeof(int));
    csr_count_kernel<<<(E + 255) / 256, 256>>>(edge, E);
    csr_scan_kernel<<<1, 1024>>>(N);
    csr_fill_kernel<<<(E + 255) / 256, 256>>>(edge, E);

    const float* hin = x;
    for (int i = 0; i < ngin; i++) {
        gather_kernel<<<N, 128>>>(hin, shi1, slo1);                          // split(h+agg) -> S1
        pgemm_kernel<true, true, false, false><<<g512, 256, GEMM_SMEM>>>(    // relu(z@w1+b1) -> S0
            shi1, slo1, whi + off_g1[i], wlo + off_g1[i], gb1 + (size_t)i * D,
            nullptr, shi0, slo0, N, D);
        pgemm_kernel<true, false, true, false><<<g512, 256, GEMM_SMEM>>>(    // relu(.@w2+b2) -> h f32
            shi0, slo0, whi + off_g2[i], wlo + off_g2[i], gb2 + (size_t)i * D,
            ph, nullptr, nullptr, N, D);
        hin = ph;
    }

    cudaMemsetAsync(pstats, 0, 2 * D * sizeof(double));
    bn_stats_kernel<<<256, D>>>(ph, N);
    bn_apply_kernel<<<(unsigned)(((long long)N * (D / 2) + 255) / 256), 256>>>(
        ph, gamma, beta, shi1, slo1, N);                                     // bn -> S1 split

    // qk = bn @ W' + b'   (se GEMM folded away)
    pgemm_kernel<false, false, true, false><<<g1024, 256, GEMM_SMEM>>>(
        shi1, slo1, wfhi, wflo, pbf, pqk, nullptr, nullptr, N, 2 * D);

    dim3 gattn((L + QT - 1) / QT, NHEAD, Bg);
    attn_kernel<<<gattn, 128, ATTN_SMEM>>>(ptr, L, shi1, slo1);              // attn -> S1 split

    pgemm_kernel<false, false, true, false><<<g512, 256, GEMM_SMEM>>>(       // out
        shi1, slo1, whi + off_o, wlo + off_o, ob, out, nullptr, nullptr, N, D);
}

// round 14
// speedup vs baseline: 1.0673x; 1.0602x over previous
#include <cuda_runtime.h>
#include <cuda_bf16.h>
#include <math.h>

#define D 512
#define NMAX 12288
#define HD 64
#define NHEAD 8
#define MASKMAX (32 * 512 * 512)
#define WELEMS 2883584
#define EMAX (16 * NMAX)
#define QT 64
#define ATTN_SMEM (68608 + 128)

// ---------------- scratch (static device globals; no allocation) ----------------
__device__ float  g_v  [NMAX * D];
__device__ float  g_h  [NMAX * D];
__device__ double g_stats[2 * D];
__device__ unsigned char g_mask[MASKMAX];
__device__ __nv_bfloat16 g_whi[WELEMS];
__device__ __nv_bfloat16 g_wlo[WELEMS];
__device__ __nv_bfloat16 g_shi0[NMAX * D];
__device__ __nv_bfloat16 g_slo0[NMAX * D];
__device__ __nv_bfloat16 g_shi1[NMAX * D];
__device__ __nv_bfloat16 g_slo1[NMAX * D];
__device__ __nv_bfloat16 g_qkhi[NMAX * 2 * D];
__device__ __nv_bfloat16 g_qklo[NMAX * 2 * D];
__device__ __nv_bfloat16 g_wfhi[1024 * 512];
__device__ __nv_bfloat16 g_wflo[1024 * 512];
__device__ float  g_bf[1024];
__device__ float  g_zero[1024];
__device__ int    g_flags[4];
__device__ int    g_deg [NMAX];
__device__ int    g_bse [NMAX];
__device__ int    g_cur [NMAX];
__device__ int    g_eidx[EMAX];

__device__ __forceinline__ long long ldidx(const void* p, int is64, long long i) {
    if (is64) return ((const long long*)p)[i];
    return (long long)((const int*)p)[i];
}

__device__ __forceinline__ unsigned smem_u32(const void* p) {
    unsigned a;
    asm("{ .reg .u64 t; cvta.to.shared.u64 t, %1; cvt.u32.u64 %0, t; }" : "=r"(a) : "l"(p));
    return a;
}

__device__ __forceinline__ unsigned pack_bf2(float x, float y) {
    __nv_bfloat162 p(__float2bfloat16(x), __float2bfloat16(y));
    return *(unsigned*)&p;
}
__device__ __forceinline__ void split2(float x, float y, unsigned& hiw, unsigned& low) {
    __nv_bfloat16 hx = __float2bfloat16(x), hy = __float2bfloat16(y);
    __nv_bfloat162 hp(hx, hy);
    hiw = *(unsigned*)&hp;
    low = pack_bf2(x - __bfloat162float(hx), y - __bfloat162float(hy));
}

// ---------------- detection ----------------
__global__ void detect_kernel(const int* __restrict__ ew, const int* __restrict__ pw,
                              const unsigned int* __restrict__ mw) {
    __shared__ int bad;
    if (threadIdx.x == 0) bad = 0;
    __syncthreads();
    int ok = 1;
    for (int i = threadIdx.x; i < 4096; i += 256) {
        unsigned int w = mw[i];
        if (w != 0u && w != 1u && w != 0x3f800000u) { ok = 0; break; }
    }
    if (!ok) atomicExch(&bad, 1);
    __syncthreads();
    if (threadIdx.x == 0) {
        g_flags[0] = (ew[17] == 0) ? 1 : 0;
        g_flags[1] = (pw[1]  == 0) ? 1 : 0;
        g_flags[2] = bad ? 0 : 1;
    }
}

__global__ void mask_convert_kernel(const void* __restrict__ mask, long long total) {
    long long i = (long long)blockIdx.x * blockDim.x + threadIdx.x;
    if (i >= total) return;
    unsigned char m;
    if (g_flags[2]) m = (((const unsigned int*)mask)[i] != 0u) ? 1 : 0;
    else            m = (((const unsigned char*)mask)[i] != 0) ? 1 : 0;
    g_mask[i] = m;
}

// ---------------- fused weight split ----------------
struct WJobs {
    const float* src[12];
    __nv_bfloat16* hi[12];
    __nv_bfloat16* lo[12];
    int N[12];
    int row0[12];
    int njobs;
};

__global__ void wsplit_all_kernel(WJobs J) {
    int row = blockIdx.x;
    int j = 0;
    while (j + 1 < J.njobs && row >= J.row0[j + 1]) j++;
    int n = row - J.row0[j];
    int Nc = J.N[j];
    const float* src = J.src[j];
    __nv_bfloat16* hi = J.hi[j];
    __nv_bfloat16* lo = J.lo[j];
    for (int k = threadIdx.x; k < 512; k += blockDim.x) {
        float v = src[(size_t)k * Nc + n];
        __nv_bfloat16 h = __float2bfloat16(v);
        hi[(size_t)n * 512 + k] = h;
        lo[(size_t)n * 512 + k] = __float2bfloat16(v - __bfloat162float(h));
    }
}

// ---------------- activation split ----------------
__global__ void __launch_bounds__(128)
asplit_kernel(const float* __restrict__ x, __nv_bfloat16* __restrict__ hi,
              __nv_bfloat16* __restrict__ lo) {
    int node = blockIdx.x, t = threadIdx.x;
    float4 v = *(const float4*)(x + (size_t)node * D + t * 4);
    unsigned h0, l0, h1, l1;
    split2(v.x, v.y, h0, l0);
    split2(v.z, v.w, h1, l1);
    *(uint2*)((char*)hi + ((size_t)node * D + t * 4) * 2) = make_uint2(h0, h1);
    *(uint2*)((char*)lo + ((size_t)node * D + t * 4) * 2) = make_uint2(l0, l1);
}

// ---------------- fused bias: b' = se_b @ qk_w + qk_b (q-half scaled by 0.125) ----------------
__global__ void bfold_kernel(const float* __restrict__ seb, const float* __restrict__ qkw,
                             const float* __restrict__ qkb) {
    int j = blockIdx.x * blockDim.x + threadIdx.x;
    float s = qkb[j];
    for (int k = 0; k < 512; k++) s = fmaf(seb[k], qkw[(size_t)k * 1024 + j], s);
    g_bf[j] = (j >= 512) ? s * 0.125f : s;
}

// ---------------- in-edge CSR build ----------------
__global__ void csr_count_kernel(const void* __restrict__ edge, int E) {
    int e = blockIdx.x * blockDim.x + threadIdx.x;
    if (e >= E) return;
    int is64 = g_flags[0];
    long long t = ldidx(edge, is64, (long long)E + e);
    atomicAdd(&g_deg[t], 1);
}

__global__ void csr_scan_kernel(int N) {
    __shared__ int ss[1024];
    int t = threadIdx.x;
    int chunk = (N + 1023) >> 10;
    int s0 = t * chunk, s1 = min(s0 + chunk, N);
    int sum = 0;
    for (int i = s0; i < s1; i++) sum += g_deg[i];
    ss[t] = sum;
    __syncthreads();
    for (int off = 1; off < 1024; off <<= 1) {
        int v = (t >= off) ? ss[t - off] : 0;
        __syncthreads();
        ss[t] += v;
        __syncthreads();
    }
    int base = (t == 0) ? 0 : ss[t - 1];
    for (int i = s0; i < s1; i++) {
        g_bse[i] = base;
        g_cur[i] = base;
        base += g_deg[i];
    }
}

__global__ void csr_fill_kernel(const void* __restrict__ edge, int E) {
    int e = blockIdx.x * blockDim.x + threadIdx.x;
    if (e >= E) return;
    int is64 = g_flags[0];
    long long s = ldidx(edge, is64, e);
    long long t = ldidx(edge, is64, (long long)E + e);
    int pos = atomicAdd(&g_cur[t], 1);
    g_eidx[pos] = (int)s;
}

// ---------------- GIN aggregation ----------------
__global__ void __launch_bounds__(128)
gather_kernel(const float* __restrict__ h, __nv_bfloat16* __restrict__ ohi,
              __nv_bfloat16* __restrict__ olo) {
    int node = blockIdx.x;
    int d4 = threadIdx.x;
    int base = g_bse[node], deg = g_deg[node];
    float4 acc = *(const float4*)(h + (size_t)node * D + d4 * 4);
    int j = 0;
    for (; j + 4 <= deg; j += 4) {
        int s0 = g_eidx[base + j];
        int s1 = g_eidx[base + j + 1];
        int s2 = g_eidx[base + j + 2];
        int s3 = g_eidx[base + j + 3];
        float4 v0 = *(const float4*)(h + (size_t)s0 * D + d4 * 4);
        float4 v1 = *(const float4*)(h + (size_t)s1 * D + d4 * 4);
        float4 v2 = *(const float4*)(h + (size_t)s2 * D + d4 * 4);
        float4 v3 = *(const float4*)(h + (size_t)s3 * D + d4 * 4);
        acc.x += v0.x + v1.x + v2.x + v3.x;
        acc.y += v0.y + v1.y + v2.y + v3.y;
        acc.z += v0.z + v1.z + v2.z + v3.z;
        acc.w += v0.w + v1.w + v2.w + v3.w;
    }
    for (; j < deg; j++) {
        int src = g_eidx[base + j];
        float4 v = *(const float4*)(h + (size_t)src * D + d4 * 4);
        acc.x += v.x; acc.y += v.y; acc.z += v.z; acc.w += v.w;
    }
    unsigned h0, l0, h1, l1;
    split2(acc.x, acc.y, h0, l0);
    split2(acc.z, acc.w, h1, l1);
    *(uint2*)((char*)ohi + ((size_t)node * D + d4 * 4) * 2) = make_uint2(h0, h1);
    *(uint2*)((char*)olo + ((size_t)node * D + d4 * 4) * 2) = make_uint2(l0, l1);
}

// ---------------- pipelined tensor-core GEMM ----------------
#define OFF_ALO 4096u
#define OFF_BHI 8192u
#define OFF_BLO 16384u
#define STAGEB  24576u
#define GEMM_SMEM (3 * 24576 + 128)

#define LDM4(r0, r1, r2, r3, addr) \
    asm volatile("ldmatrix.sync.aligned.m8n8.x4.shared.b16 {%0,%1,%2,%3}, [%4];" \
                 : "=r"(r0), "=r"(r1), "=r"(r2), "=r"(r3) : "r"(addr))
#define CP16(dst, src) \
    asm volatile("cp.async.cg.shared.global [%0], [%1], 16;" :: "r"(dst), "l"(src))
#define CPCOMMIT() asm volatile("cp.async.commit_group;" ::: "memory")
#define CPWAIT1()  asm volatile("cp.async.wait_group 1;" ::: "memory")
#define CPWAIT0()  asm volatile("cp.async.wait_group 0;" ::: "memory")

__device__ __forceinline__ void mma_bf16(float* c, unsigned a0, unsigned a1, unsigned a2,
                                         unsigned a3, unsigned b0, unsigned b1) {
    asm volatile(
        "mma.sync.aligned.m16n8k16.row.col.f32.bf16.bf16.f32 "
        "{%0,%1,%2,%3}, {%4,%5,%6,%7}, {%8,%9}, {%0,%1,%2,%3};"
        : "+f"(c[0]), "+f"(c[1]), "+f"(c[2]), "+f"(c[3])
        : "r"(a0), "r"(a1), "r"(a2), "r"(a3), "r"(b0), "r"(b1));
}

template <bool RELU, bool WSPLIT, bool WF32, bool WT>
__global__ void __launch_bounds__(256, 3)
pgemm_kernel(const __nv_bfloat16* __restrict__ Ahi, const __nv_bfloat16* __restrict__ Alo,
             const __nv_bfloat16* __restrict__ Bhi, const __nv_bfloat16* __restrict__ Blo,
             const float* __restrict__ bias, float* __restrict__ C,
             __nv_bfloat16* __restrict__ Ohi, __nv_bfloat16* __restrict__ Olo,
             int M, int Nc, int qscol) {
    extern __shared__ char dynsmem[];
    unsigned sb = (smem_u32(dynsmem) + 127) & ~127u;

    int tid = threadIdx.x, wid = tid >> 5, lane = tid & 31;
    int m0 = blockIdx.y * 64, n0 = blockIdx.x * 128;
    int warp_m = (wid & 1) * 32, warp_n = (wid >> 1) * 32;
    int g = lane >> 2, kp = (lane & 3) * 2;

    int crow = tid >> 2, cch = tid & 3;
    unsigned dstA = (unsigned)(crow * 64 + ((cch ^ ((crow >> 1) & 3)) * 16));
    long long arow = m0 + crow; if (arow > M - 1) arow = M - 1;
    const __nv_bfloat16* pAhi = Ahi + arow * 512 + cch * 8;
    const __nv_bfloat16* pAlo = Alo + arow * 512 + cch * 8;
    int brow2 = crow + 64;
    unsigned dstB0 = dstA;
    unsigned dstB1 = (unsigned)(brow2 * 64 + ((cch ^ ((brow2 >> 1) & 3)) * 16));
    const __nv_bfloat16* pBhi0 = Bhi + (size_t)(n0 + crow) * 512 + cch * 8;
    const __nv_bfloat16* pBhi1 = Bhi + (size_t)(n0 + brow2) * 512 + cch * 8;
    const __nv_bfloat16* pBlo0 = Blo + (size_t)(n0 + crow) * 512 + cch * 8;
    const __nv_bfloat16* pBlo1 = Blo + (size_t)(n0 + brow2) * 512 + cch * 8;

    int rA = lane & 15, hA = lane >> 4;
    unsigned aoff = (unsigned)((warp_m + rA) * 64 + ((hA ^ ((rA >> 1) & 3)) * 16));
    int rB = (lane & 7) + ((lane >> 4) * 8);
    int cB = (lane >> 3) & 1;
    unsigned boff = (unsigned)((warp_n + rB) * 64 + ((cB ^ ((rB >> 1) & 3)) * 16));

    float acc[2][4][4];
#pragma unroll
    for (int i = 0; i < 2; i++)
#pragma unroll
        for (int j = 0; j < 4; j++)
#pragma unroll
            for (int r = 0; r < 4; r++) acc[i][j][r] = 0.f;

#pragma unroll
    for (int s = 0; s < 2; s++) {
        unsigned bb = sb + (unsigned)s * STAGEB;
        int kg = s * 32;
        CP16(bb + dstA,            pAhi + kg);
        CP16(bb + OFF_ALO + dstA,  pAlo + kg);
        CP16(bb + OFF_BHI + dstB0, pBhi0 + kg);
        CP16(bb + OFF_BHI + dstB1, pBhi1 + kg);
        CP16(bb + OFF_BLO + dstB0, pBlo0 + kg);
        CP16(bb + OFF_BLO + dstB1, pBlo1 + kg);
        CPCOMMIT();
    }

    unsigned bufoff[3] = {0u, STAGEB, 2u * STAGEB};
#pragma unroll 1
    for (int s = 0; s < 16; s++) {
        CPWAIT1();
        __syncthreads();
        if (s + 2 < 16) {
            unsigned bb = sb + bufoff[(s + 2) % 3];
            int kg = (s + 2) * 32;
            CP16(bb + dstA,            pAhi + kg);
            CP16(bb + OFF_ALO + dstA,  pAlo + kg);
            CP16(bb + OFF_BHI + dstB0, pBhi0 + kg);
            CP16(bb + OFF_BHI + dstB1, pBhi1 + kg);
            CP16(bb + OFF_BLO + dstB0, pBlo0 + kg);
            CP16(bb + OFF_BLO + dstB1, pBlo1 + kg);
        }
        CPCOMMIT();

        unsigned bcur = sb + bufoff[s % 3];
#pragma unroll
        for (int kx = 0; kx < 2; kx++) {
            unsigned kxor = kx ? 32u : 0u;
            unsigned ah[2][4], al[2][4], bh[4][2], bl[4][2];
#pragma unroll
            for (int mi = 0; mi < 2; mi++)
                LDM4(ah[mi][0], ah[mi][1], ah[mi][2], ah[mi][3],
                     bcur + (unsigned)(mi * 1024) + (aoff ^ kxor));
            {
                unsigned r0, r1, r2, r3;
#pragma unroll
                for (int p = 0; p < 2; p++) {
                    LDM4(r0, r1, r2, r3, bcur + OFF_BHI + (unsigned)(p * 1024) + (boff ^ kxor));
                    bh[2 * p][0] = r0; bh[2 * p][1] = r1;
                    bh[2 * p + 1][0] = r2; bh[2 * p + 1][1] = r3;
                    LDM4(r0, r1, r2, r3, bcur + OFF_BLO + (unsigned)(p * 1024) + (boff ^ kxor));
                    bl[2 * p][0] = r0; bl[2 * p][1] = r1;
                    bl[2 * p + 1][0] = r2; bl[2 * p + 1][1] = r3;
                }
            }
#pragma unroll
            for (int mi = 0; mi < 2; mi++)
                LDM4(al[mi][0], al[mi][1], al[mi][2], al[mi][3],
                     bcur + OFF_ALO + (unsigned)(mi * 1024) + (aoff ^ kxor));
#pragma unroll
            for (int mi = 0; mi < 2; mi++)
#pragma unroll
                for (int ni = 0; ni < 4; ni++)
                    mma_bf16(acc[mi][ni], ah[mi][0], ah[mi][1], ah[mi][2], ah[mi][3],
                             bh[ni][0], bh[ni][1]);
#pragma unroll
            for (int mi = 0; mi < 2; mi++)
#pragma unroll
                for (int ni = 0; ni < 4; ni++)
                    mma_bf16(acc[mi][ni], ah[mi][0], ah[mi][1], ah[mi][2], ah[mi][3],
                             bl[ni][0], bl[ni][1]);
#pragma unroll
            for (int mi = 0; mi < 2; mi++)
#pragma unroll
                for (int ni = 0; ni < 4; ni++)
                    mma_bf16(acc[mi][ni], al[mi][0], al[mi][1], al[mi][2], al[mi][3],
                             bh[ni][0], bh[ni][1]);
        }
    }

#pragma unroll
    for (int mi = 0; mi < 2; mi++) {
        int row0 = m0 + warp_m + mi * 16 + g;
        int row1 = row0 + 8;
#pragma unroll
        for (int ni = 0; ni < 4; ni++) {
            int col = n0 + warp_n + ni * 8 + kp;
            float b0 = bias[col], b1 = bias[col + 1];
            float o0 = acc[mi][ni][0] + b0, o1 = acc[mi][ni][1] + b1;
            float o2 = acc[mi][ni][2] + b0, o3 = acc[mi][ni][3] + b1;
            if (RELU) {
                o0 = fmaxf(o0, 0.f); o1 = fmaxf(o1, 0.f);
                o2 = fmaxf(o2, 0.f); o3 = fmaxf(o3, 0.f);
            }
            if (WT) {
                float f0 = (col >= qscol) ? 0.125f : 1.f;
                float f1 = (col + 1 >= qscol) ? 0.125f : 1.f;
                o0 *= f0; o1 *= f1; o2 *= f0; o3 *= f1;
            }
            if (row0 < M) {
                if (WF32)
                    *(float2*)(C + (size_t)row0 * Nc + col) = make_float2(o0, o1);
                if (WSPLIT && !WT) {
                    unsigned hw, lw;
                    split2(o0, o1, hw, lw);
                    *(unsigned*)((char*)Ohi + ((size_t)row0 * Nc + col) * 2) = hw;
                    *(unsigned*)((char*)Olo + ((size_t)row0 * Nc + col) * 2) = lw;
                }
                if (WT) {
                    __nv_bfloat16 h0 = __float2bfloat16(o0);
                    __nv_bfloat16 h1 = __float2bfloat16(o1);
                    Ohi[(size_t)col * 512 + row0] = h0;
                    Olo[(size_t)col * 512 + row0] = __float2bfloat16(o0 - __bfloat162float(h0));
                    Ohi[(size_t)(col + 1) * 512 + row0] = h1;
                    Olo[(size_t)(col + 1) * 512 + row0] = __float2bfloat16(o1 - __bfloat162float(h1));
                }
            }
            if (row1 < M) {
                if (WF32)
                    *(float2*)(C + (size_t)row1 * Nc + col) = make_float2(o2, o3);
                if (WSPLIT && !WT) {
                    unsigned hw, lw;
                    split2(o2, o3, hw, lw);
                    *(unsigned*)((char*)Ohi + ((size_t)row1 * Nc + col) * 2) = hw;
                    *(unsigned*)((char*)Olo + ((size_t)row1 * Nc + col) * 2) = lw;
                }
                if (WT) {
                    __nv_bfloat16 h2 = __float2bfloat16(o2);
                    __nv_bfloat16 h3 = __float2bfloat16(o3);
                    Ohi[(size_t)col * 512 + row1] = h2;
                    Olo[(size_t)col * 512 + row1] = __float2bfloat16(o2 - __bfloat162float(h2));
                    Ohi[(size_t)(col + 1) * 512 + row1] = h3;
                    Olo[(size_t)(col + 1) * 512 + row1] = __float2bfloat16(o3 - __bfloat162float(h3));
                }
            }
        }
    }
}

// ---------------- BatchNorm ----------------
__global__ void bn_stats_kernel(const float* __restrict__ h, int N) {
    int c = threadIdx.x;
    double s = 0.0, s2 = 0.0;
    for (int r = blockIdx.x; r < N; r += gridDim.x) {
        float v = h[(size_t)r * D + c];
        s += v;
        s2 += (double)v * v;
    }
    atomicAdd(&g_stats[c], s);
    atomicAdd(&g_stats[D + c], s2);
}

__global__ void bn_apply_kernel(const float* __restrict__ h, const float* __restrict__ gamma,
                                const float* __restrict__ beta,
                                __nv_bfloat16* __restrict__ ohi, __nv_bfloat16* __restrict__ olo,
                                int N) {
    long long i = (long long)blockIdx.x * blockDim.x + threadIdx.x;
    if (i >= (long long)N * (D / 2)) return;
    int p = (int)(i & (D / 2 - 1));
    long long row = i >> 8;
    int c0 = 2 * p, c1 = c0 + 1;
    double mean0 = g_stats[c0] / N, mean1 = g_stats[c1] / N;
    double var0  = g_stats[D + c0] / N - mean0 * mean0;
    double var1  = g_stats[D + c1] / N - mean1 * mean1;
    float is0 = rsqrtf((float)var0 + 1e-5f), is1 = rsqrtf((float)var1 + 1e-5f);
    float2 v = *(const float2*)(h + row * D + c0);
    float o0 = (v.x - (float)mean0) * is0 * gamma[c0] + beta[c0];
    float o1 = (v.y - (float)mean1) * is1 * gamma[c1] + beta[c1];
    unsigned hw, lw;
    split2(o0, o1, hw, lw);
    *(unsigned*)((char*)ohi + (row * D + c0) * 2) = hw;
    *(unsigned*)((char*)olo + (row * D + c0) * 2) = lw;
}

// ---------------- attention: tensor-core scores + fp32 softmax/AV ----------------
// Block = (64-query tile, head, graph). 128 threads = 4 warps; warp w owns q-rows
// [16w,16w+16) for mma scores, softmax, and AV — Ps traffic is warp-local.
// Q/K tiles: split bf16 in 64B subrows (subrow = 2*row+kb), chunk swizzle c^(row&3).
__global__ void __launch_bounds__(128)
attn_kernel(const void* __restrict__ ptr, int L,
            const __nv_bfloat16* __restrict__ qkhi, const __nv_bfloat16* __restrict__ qklo,
            __nv_bfloat16* __restrict__ ohi, __nv_bfloat16* __restrict__ olo) {
    extern __shared__ char smraw[];
    unsigned sb0 = smem_u32(smraw);
    unsigned sb = (sb0 + 127) & ~127u;
    char* smem = smraw + (sb - sb0);
    const unsigned QHI = 0, QLO = 8192, KHI = 16384, KLO = 24576;
    float (*Vs)[68] = (float(*)[68])(smem + 32768);
    float (*Ps)[72] = (float(*)[72])(smem + 50176);

    int qt = blockIdx.x, hh = blockIdx.y, b = blockIdx.z;
    int is64 = g_flags[1];
    long long p0 = ldidx(ptr, is64, b);
    long long p1 = ldidx(ptr, is64, b + 1);
    int s = (int)(p1 - p0);
    int qbase = qt * QT;
    if (qbase >= s) return;

    int tid = threadIdx.x, wid = tid >> 5, lane = tid & 31;
    int tq4 = tid >> 3, tg = tid & 7;
    int w16 = wid * 16;
    int rA = lane & 15, hA = lane >> 4;
    int rB = (lane & 7) + ((lane >> 4) * 8);
    int cB = (lane >> 3) & 1;
    int fg = lane >> 2, fc = (lane & 3) * 2;
    unsigned aswz = (unsigned)((hA ^ (rA & 3)) * 16);
    unsigned bswz = (unsigned)((cB ^ (rB & 3)) * 16);

    // load Q tile once (q half = cols 512.., pre-scaled by 0.125 in W'/b')
    {
        int row = tid >> 1, kb = tid & 1;
        long long node = p0 + min(qbase + row, s - 1);
        const __nv_bfloat16* qh = qkhi + node * 1024 + 512 + hh * 64 + kb * 32;
        const __nv_bfloat16* ql = qklo + node * 1024 + 512 + hh * 64 + kb * 32;
        unsigned dst = (unsigned)((row * 2 + kb) * 64);
        unsigned sw = (unsigned)(row & 3);
#pragma unroll
        for (int c = 0; c < 4; c++) {
            CP16(sb + QHI + dst + ((c ^ sw) * 16), qh + c * 8);
            CP16(sb + QLO + dst + ((c ^ sw) * 16), ql + c * 8);
        }
        CPCOMMIT();
    }

    int q[4];
    bool qok[4];
    const unsigned char* mrow[4];
#pragma unroll
    for (int qi = 0; qi < 4; qi++) {
        q[qi] = 4 * tq4 + qi;
        qok[qi] = (qbase + q[qi]) < s;
        mrow[qi] = g_mask + ((size_t)b * L + (qok[qi] ? qbase + q[qi] : 0)) * L;
    }

    float acc[4][8], mr[4], lr[4];
#pragma unroll
    for (int qi = 0; qi < 4; qi++) {
        mr[qi] = -1e30f; lr[qi] = 0.f;
#pragma unroll
        for (int dd = 0; dd < 8; dd++) acc[qi][dd] = 0.f;
    }

    for (int j0 = 0; j0 < s; j0 += 64) {
        __syncthreads();
        // K tile (split bf16 via cp.async)
        {
            int row = tid >> 1, kb = tid & 1;
            long long node = p0 + min(j0 + row, s - 1);
            const __nv_bfloat16* kh = qkhi + node * 1024 + hh * 64 + kb * 32;
            const __nv_bfloat16* kl = qklo + node * 1024 + hh * 64 + kb * 32;
            unsigned dst = (unsigned)((row * 2 + kb) * 64);
            unsigned sw = (unsigned)(row & 3);
#pragma unroll
            for (int c = 0; c < 4; c++) {
                CP16(sb + KHI + dst + ((c ^ sw) * 16), kh + c * 8);
                CP16(sb + KLO + dst + ((c ^ sw) * 16), kl + c * 8);
            }
        }
        // V tile (fp32)
        for (int i = tid; i < 64 * 16; i += 128) {
            int r = i >> 4, c4 = i & 15;
            float4 vv = make_float4(0.f, 0.f, 0.f, 0.f);
            if (j0 + r < s)
                vv = *(const float4*)(g_v + (p0 + j0 + r) * D + hh * HD + c4 * 4);
            *(float4*)&Vs[r][c4 * 4] = vv;
        }
        CPCOMMIT();
        CPWAIT0();
        __syncthreads();

        // ---- scores via mma: warp w computes rows [16w,16w+16) x 64 keys ----
        float sacc[8][4];
#pragma unroll
        for (int nt = 0; nt < 8; nt++)
#pragma unroll
            for (int r = 0; r < 4; r++) sacc[nt][r] = 0.f;
#pragma unroll
        for (int ks = 0; ks < 4; ks++) {
            int kb = ks >> 1;
            unsigned kxor = (unsigned)((ks & 1) * 32);
            unsigned asub = (unsigned)((2 * (w16 + rA) + kb) * 64) + (aswz ^ kxor);
            unsigned ah[4], al[4], bh[8][2], bl[8][2];
            LDM4(ah[0], ah[1], ah[2], ah[3], sb + QHI + asub);
            LDM4(al[0], al[1], al[2], al[3], sb + QLO + asub);
#pragma unroll
            for (int p = 0; p < 4; p++) {
                unsigned bsub = (unsigned)((2 * (p * 16 + rB) + kb) * 64) + (bswz ^ kxor);
                unsigned r0, r1, r2, r3;
                LDM4(r0, r1, r2, r3, sb + KHI + bsub);
                bh[2 * p][0] = r0; bh[2 * p][1] = r1;
                bh[2 * p + 1][0] = r2; bh[2 * p + 1][1] = r3;
                LDM4(r0, r1, r2, r3, sb + KLO + bsub);
                bl[2 * p][0] = r0; bl[2 * p][1] = r1;
                bl[2 * p + 1][0] = r2; bl[2 * p + 1][1] = r3;
            }
#pragma unroll
            for (int nt = 0; nt < 8; nt++)
                mma_bf16(sacc[nt], ah[0], ah[1], ah[2], ah[3], bh[nt][0], bh[nt][1]);
#pragma unroll
            for (int nt = 0; nt < 8; nt++)
                mma_bf16(sacc[nt], al[0], al[1], al[2], al[3], bh[nt][0], bh[nt][1]);
#pragma unroll
            for (int nt = 0; nt < 8; nt++)
                mma_bf16(sacc[nt], ah[0], ah[1], ah[2], ah[3], bl[nt][0], bl[nt][1]);
        }
        // frag -> Ps (warp-local rows)
#pragma unroll
        for (int nt = 0; nt < 8; nt++) {
            *(float2*)&Ps[w16 + fg][nt * 8 + fc]     = make_float2(sacc[nt][0], sacc[nt][1]);
            *(float2*)&Ps[w16 + fg + 8][nt * 8 + fc] = make_float2(sacc[nt][2], sacc[nt][3]);
        }
        __syncwarp();

        // ---- softmax (per-thread: 4 q-rows x 8 keys, warp-local Ps) ----
        float sc[4][8];
#pragma unroll
        for (int qi = 0; qi < 4; qi++)
#pragma unroll
            for (int jj = 0; jj < 8; jj++) {
                int j = jj * 8 + tg;
                float v = Ps[q[qi]][j];
                bool valid = (j0 + j < s) && (mrow[qi][j0 + j] == 0);
                sc[qi][jj] = valid ? v : -1e30f;
            }
#pragma unroll
        for (int qi = 0; qi < 4; qi++) {
            float mt = sc[qi][0];
#pragma unroll
            for (int jj = 1; jj < 8; jj++) mt = fmaxf(mt, sc[qi][jj]);
#pragma unroll
            for (int off = 1; off < 8; off <<= 1)
                mt = fmaxf(mt, __shfl_xor_sync(0xffffffffu, mt, off));
            float mn = fmaxf(mr[qi], mt);
            float corr = __expf(mr[qi] - mn);
            float ps = 0.f;
#pragma unroll
            for (int jj = 0; jj < 8; jj++) {
                float pv = (sc[qi][jj] <= -1e29f) ? 0.f : __expf(sc[qi][jj] - mn);
                Ps[q[qi]][jj * 8 + tg] = pv;
                ps += pv;
            }
#pragma unroll
            for (int off = 1; off < 8; off <<= 1)
                ps += __shfl_xor_sync(0xffffffffu, ps, off);
            lr[qi] = lr[qi] * corr + ps;
            mr[qi] = mn;
#pragma unroll
            for (int dd = 0; dd < 8; dd++) acc[qi][dd] *= corr;
        }
        __syncwarp();

        // ---- AV (fp32) ----
#pragma unroll 2
        for (int j = 0; j < 64; j += 4) {
            float4 pq[4];
#pragma unroll
            for (int qi = 0; qi < 4; qi++) pq[qi] = *(float4*)&Ps[q[qi]][j];
            float pv[4][4] = {{pq[0].x, pq[0].y, pq[0].z, pq[0].w},
                              {pq[1].x, pq[1].y, pq[1].z, pq[1].w},
                              {pq[2].x, pq[2].y, pq[2].z, pq[2].w},
                              {pq[3].x, pq[3].y, pq[3].z, pq[3].w}};
#pragma unroll
            for (int u = 0; u < 4; u++) {
                float4 va = *(float4*)&Vs[j + u][tg * 8];
                float4 vb = *(float4*)&Vs[j + u][tg * 8 + 4];
#pragma unroll
                for (int qi = 0; qi < 4; qi++) {
                    acc[qi][0] = fmaf(pv[qi][u], va.x, acc[qi][0]);
                    acc[qi][1] = fmaf(pv[qi][u], va.y, acc[qi][1]);
                    acc[qi][2] = fmaf(pv[qi][u], va.z, acc[qi][2]);
                    acc[qi][3] = fmaf(pv[qi][u], va.w, acc[qi][3]);
                    acc[qi][4] = fmaf(pv[qi][u], vb.x, acc[qi][4]);
                    acc[qi][5] = fmaf(pv[qi][u], vb.y, acc[qi][5]);
                    acc[qi][6] = fmaf(pv[qi][u], vb.z, acc[qi][6]);
                    acc[qi][7] = fmaf(pv[qi][u], vb.w, acc[qi][7]);
                }
            }
        }
    }

#pragma unroll
    for (int qi = 0; qi < 4; qi++) {
        if (qok[qi] && lr[qi] > 0.f) {
            float inv = 1.f / lr[qi];
            unsigned hw[4], lw[4];
#pragma unroll
            for (int k = 0; k < 4; k++)
                split2(acc[qi][2 * k] * inv, acc[qi][2 * k + 1] * inv, hw[k], lw[k]);
            size_t off = ((p0 + qbase + q[qi]) * D + hh * HD + tg * 8) * 2;
            *(uint4*)((char*)ohi + off) = make_uint4(hw[0], hw[1], hw[2], hw[3]);
            *(uint4*)((char*)olo + off) = make_uint4(lw[0], lw[1], lw[2], lw[3]);
        }
    }
}

// ---------------- host orchestration ----------------
extern "C" void kernel_launch(void* const* d_in, const int* in_sizes, int n_in,
                              void* d_out, int out_size) {
    const float* x   = (const float*)d_in[0];
    const void* edge = d_in[1];
    const void* mask = d_in[2];
    const void* ptr  = d_in[3];
    const float* gw1   = (const float*)d_in[4];
    const float* gb1   = (const float*)d_in[5];
    const float* gw2   = (const float*)d_in[6];
    const float* gb2   = (const float*)d_in[7];
    const float* gamma = (const float*)d_in[8];
    const float* beta  = (const float*)d_in[9];
    const float* sw    = (const float*)d_in[10];
    const float* sb    = (const float*)d_in[11];
    const float* qkw   = (const float*)d_in[12];
    const float* qkb   = (const float*)d_in[13];
    const float* vw    = (const float*)d_in[14];
    const float* vb    = (const float*)d_in[15];
    const float* ow    = (const float*)d_in[16];
    const float* ob    = (const float*)d_in[17];
    float* out = (float*)d_out;

    int N  = in_sizes[0] / D;
    int E  = in_sizes[1] / 2;
    int Bg = in_sizes[3] - 1;
    int ngin = in_sizes[4] / (D * D);
    int L;
    {
        long long ll = (long long)in_sizes[2] / Bg;
        int l = 1;
        while ((long long)l * l < ll) l++;
        L = l;
    }
    long long masktotal = (long long)Bg * L * L;
    if (N > NMAX || masktotal > MASKMAX || ngin > 3 || E > EMAX) return;

    float *pv, *ph, *pbf, *pzero;
    double* pstats;
    __nv_bfloat16 *whi, *wlo, *shi0, *slo0, *shi1, *slo1, *wfhi, *wflo, *qkhi, *qklo;
    int* pdeg;
    cudaGetSymbolAddress((void**)&pv,    g_v);
    cudaGetSymbolAddress((void**)&ph,    g_h);
    cudaGetSymbolAddress((void**)&pstats, g_stats);
    cudaGetSymbolAddress((void**)&whi,   g_whi);
    cudaGetSymbolAddress((void**)&wlo,   g_wlo);
    cudaGetSymbolAddress((void**)&shi0,  g_shi0);
    cudaGetSymbolAddress((void**)&slo0,  g_slo0);
    cudaGetSymbolAddress((void**)&shi1,  g_shi1);
    cudaGetSymbolAddress((void**)&slo1,  g_slo1);
    cudaGetSymbolAddress((void**)&wfhi,  g_wfhi);
    cudaGetSymbolAddress((void**)&wflo,  g_wflo);
    cudaGetSymbolAddress((void**)&qkhi,  g_qkhi);
    cudaGetSymbolAddress((void**)&qklo,  g_qklo);
    cudaGetSymbolAddress((void**)&pbf,   g_bf);
    cudaGetSymbolAddress((void**)&pzero, g_zero);
    cudaGetSymbolAddress((void**)&pdeg,  g_deg);

    cudaFuncSetAttribute(pgemm_kernel<false, false, true, false>,
                         cudaFuncAttributeMaxDynamicSharedMemorySize, GEMM_SMEM);
    cudaFuncSetAttribute(pgemm_kernel<true, true, false, false>,
                         cudaFuncAttributeMaxDynamicSharedMemorySize, GEMM_SMEM);
    cudaFuncSetAttribute(pgemm_kernel<true, false, true, false>,
                         cudaFuncAttributeMaxDynamicSharedMemorySize, GEMM_SMEM);
    cudaFuncSetAttribute(pgemm_kernel<false, true, false, true>,
                         cudaFuncAttributeMaxDynamicSharedMemorySize, GEMM_SMEM);
    cudaFuncSetAttribute(pgemm_kernel<false, true, false, false>,
                         cudaFuncAttributeMaxDynamicSharedMemorySize, GEMM_SMEM);
    cudaFuncSetAttribute(attn_kernel,
                         cudaFuncAttributeMaxDynamicSharedMemorySize, ATTN_SMEM);

    const size_t SZ = (size_t)D * D;
    size_t off_v = 0, off_g1[3], off_g2[3];
    size_t cur = SZ;
    for (int i = 0; i < 3; i++) { off_g1[i] = cur; cur += SZ; off_g2[i] = cur; cur += SZ; }
    size_t off_qk = cur; cur += 2 * SZ;
    size_t off_o  = cur;

    WJobs J;
    int jn = 0, rows = 0;
    auto addjob = [&](const float* src, size_t off, int Nc) {
        J.src[jn] = src; J.hi[jn] = whi + off; J.lo[jn] = wlo + off;
        J.N[jn] = Nc; J.row0[jn] = rows;
        rows += Nc; jn++;
    };
    addjob(vw, off_v, D);
    for (int i = 0; i < ngin; i++) {
        addjob(gw1 + SZ * i, off_g1[i], D);
        addjob(gw2 + SZ * i, off_g2[i], D);
    }
    addjob(qkw, off_qk, 2 * D);
    addjob(ow, off_o, D);
    J.njobs = jn;

    int mt = (N + 63) / 64;
    dim3 g512(D / 128, mt);
    dim3 g1024(2 * D / 128, mt);
    dim3 gprep(2 * D / 128, 512 / 64);
    const int NOSC = 1 << 30;

    detect_kernel<<<1, 256>>>((const int*)edge, (const int*)ptr, (const unsigned int*)mask);
    asplit_kernel<<<N, 128>>>(x, shi0, slo0);
    wsplit_all_kernel<<<rows, 256>>>(J);
    pgemm_kernel<false, false, true, false><<<g512, 256, GEMM_SMEM>>>(      // v = x@vw
        shi0, slo0, whi + off_v, wlo + off_v, vb, pv, nullptr, nullptr, N, D, NOSC);

    // fused se->qk weight prep (q-half scaled by 0.125)
    asplit_kernel<<<512, 128>>>(sw, shi1, slo1);
    pgemm_kernel<false, true, false, true><<<gprep, 256, GEMM_SMEM>>>(
        shi1, slo1, whi + off_qk, wlo + off_qk, pzero, nullptr, wfhi, wflo, 512, 2 * D, 512);
    bfold_kernel<<<4, 256>>>(sb, qkw, qkb);

    mask_convert_kernel<<<(unsigned)((masktotal + 511) / 512), 512>>>(mask, masktotal);
    cudaMemsetAsync(pdeg, 0, (size_t)N * sizeof(int));
    csr_count_kernel<<<(E + 255) / 256, 256>>>(edge, E);
    csr_scan_kernel<<<1, 1024>>>(N);
    csr_fill_kernel<<<(E + 255) / 256, 256>>>(edge, E);

    const float* hin = x;
    for (int i = 0; i < ngin; i++) {
        gather_kernel<<<N, 128>>>(hin, shi1, slo1);
        pgemm_kernel<true, true, false, false><<<g512, 256, GEMM_SMEM>>>(
            shi1, slo1, whi + off_g1[i], wlo + off_g1[i], gb1 + (size_t)i * D,
            nullptr, shi0, slo0, N, D, NOSC);
        pgemm_kernel<true, false, true, false><<<g512, 256, GEMM_SMEM>>>(
            shi0, slo0, whi + off_g2[i], wlo + off_g2[i], gb2 + (size_t)i * D,
            ph, nullptr, nullptr, N, D, NOSC);
        hin = ph;
    }

    cudaMemsetAsync(pstats, 0, 2 * D * sizeof(double));
    bn_stats_kernel<<<256, D>>>(ph, N);
    bn_apply_kernel<<<(unsigned)(((long long)N * (D / 2) + 255) / 256), 256>>>(
        ph, gamma, beta, shi1, slo1, N);

    // qk = bn @ W' + b'  -> split output for tensor-core attention
    pgemm_kernel<false, true, false, false><<<g1024, 256, GEMM_SMEM>>>(
        shi1, slo1, wfhi, wflo, pbf, nullptr, qkhi, qklo, N, 2 * D, NOSC);

    dim3 gattn((L + QT - 1) / QT, NHEAD, Bg);
    attn_kernel<<<gattn, 128, ATTN_SMEM>>>(ptr, L, qkhi, qklo, shi1, slo1);

    pgemm_kernel<false, false, true, false><<<g512, 256, GEMM_SMEM>>>(
        shi1, slo1, whi + off_o, wlo + off_o, ob, out, nullptr, nullptr, N, D, NOSC);
}

// round 15
// speedup vs baseline: 1.1930x; 1.1177x over previous
#include <cuda_runtime.h>
#include <cuda_bf16.h>
#include <math.h>

#define D 512
#define NMAX 12288
#define HD 64
#define NHEAD 8
#define MASKMAX (32 * 512 * 512)
#define WELEMS 2883584
#define EMAX (16 * NMAX)
#define QT 64
#define ATTN_SMEM (65536 + 128)

// ---------------- scratch (static device globals; no allocation) ----------------
__device__ float  g_h  [NMAX * D];
__device__ double g_stats[2 * D];
__device__ unsigned char g_mask[MASKMAX];
__device__ __nv_bfloat16 g_whi[WELEMS];
__device__ __nv_bfloat16 g_wlo[WELEMS];
__device__ __nv_bfloat16 g_shi0[NMAX * D];
__device__ __nv_bfloat16 g_slo0[NMAX * D];
__device__ __nv_bfloat16 g_shi1[NMAX * D];
__device__ __nv_bfloat16 g_slo1[NMAX * D];
__device__ __nv_bfloat16 g_qkhi[NMAX * 2 * D];
__device__ __nv_bfloat16 g_qklo[NMAX * 2 * D];
__device__ __nv_bfloat16 g_vthi[(size_t)D * NMAX];   // V^T [dim][node], split
__device__ __nv_bfloat16 g_vtlo[(size_t)D * NMAX];
__device__ __nv_bfloat16 g_wfhi[1024 * 512];
__device__ __nv_bfloat16 g_wflo[1024 * 512];
__device__ float  g_bf[1024];
__device__ float  g_zero[1024];
__device__ int    g_flags[4];
__device__ int    g_deg [NMAX];
__device__ int    g_bse [NMAX];
__device__ int    g_cur [NMAX];
__device__ int    g_eidx[EMAX];

__device__ __forceinline__ long long ldidx(const void* p, int is64, long long i) {
    if (is64) return ((const long long*)p)[i];
    return (long long)((const int*)p)[i];
}

__device__ __forceinline__ unsigned smem_u32(const void* p) {
    unsigned a;
    asm("{ .reg .u64 t; cvta.to.shared.u64 t, %1; cvt.u32.u64 %0, t; }" : "=r"(a) : "l"(p));
    return a;
}

__device__ __forceinline__ unsigned pack_bf2(float x, float y) {
    __nv_bfloat162 p(__float2bfloat16(x), __float2bfloat16(y));
    return *(unsigned*)&p;
}
__device__ __forceinline__ void split2(float x, float y, unsigned& hiw, unsigned& low) {
    __nv_bfloat16 hx = __float2bfloat16(x), hy = __float2bfloat16(y);
    __nv_bfloat162 hp(hx, hy);
    hiw = *(unsigned*)&hp;
    low = pack_bf2(x - __bfloat162float(hx), y - __bfloat162float(hy));
}

// ---------------- detection ----------------
__global__ void detect_kernel(const int* __restrict__ ew, const int* __restrict__ pw,
                              const unsigned int* __restrict__ mw) {
    __shared__ int bad;
    if (threadIdx.x == 0) bad = 0;
    __syncthreads();
    int ok = 1;
    for (int i = threadIdx.x; i < 4096; i += 256) {
        unsigned int w = mw[i];
        if (w != 0u && w != 1u && w != 0x3f800000u) { ok = 0; break; }
    }
    if (!ok) atomicExch(&bad, 1);
    __syncthreads();
    if (threadIdx.x == 0) {
        g_flags[0] = (ew[17] == 0) ? 1 : 0;
        g_flags[1] = (pw[1]  == 0) ? 1 : 0;
        g_flags[2] = bad ? 0 : 1;
    }
}

__global__ void mask_convert_kernel(const void* __restrict__ mask, long long total) {
    long long i = (long long)blockIdx.x * blockDim.x + threadIdx.x;
    if (i >= total) return;
    unsigned char m;
    if (g_flags[2]) m = (((const unsigned int*)mask)[i] != 0u) ? 1 : 0;
    else            m = (((const unsigned char*)mask)[i] != 0) ? 1 : 0;
    g_mask[i] = m;
}

// ---------------- fused weight split ----------------
struct WJobs {
    const float* src[12];
    __nv_bfloat16* hi[12];
    __nv_bfloat16* lo[12];
    int N[12];
    int row0[12];
    int njobs;
};

__global__ void wsplit_all_kernel(WJobs J) {
    int row = blockIdx.x;
    int j = 0;
    while (j + 1 < J.njobs && row >= J.row0[j + 1]) j++;
    int n = row - J.row0[j];
    int Nc = J.N[j];
    const float* src = J.src[j];
    __nv_bfloat16* hi = J.hi[j];
    __nv_bfloat16* lo = J.lo[j];
    for (int k = threadIdx.x; k < 512; k += blockDim.x) {
        float v = src[(size_t)k * Nc + n];
        __nv_bfloat16 h = __float2bfloat16(v);
        hi[(size_t)n * 512 + k] = h;
        lo[(size_t)n * 512 + k] = __float2bfloat16(v - __bfloat162float(h));
    }
}

// ---------------- activation split ----------------
__global__ void __launch_bounds__(128)
asplit_kernel(const float* __restrict__ x, __nv_bfloat16* __restrict__ hi,
              __nv_bfloat16* __restrict__ lo) {
    int node = blockIdx.x, t = threadIdx.x;
    float4 v = *(const float4*)(x + (size_t)node * D + t * 4);
    unsigned h0, l0, h1, l1;
    split2(v.x, v.y, h0, l0);
    split2(v.z, v.w, h1, l1);
    *(uint2*)((char*)hi + ((size_t)node * D + t * 4) * 2) = make_uint2(h0, h1);
    *(uint2*)((char*)lo + ((size_t)node * D + t * 4) * 2) = make_uint2(l0, l1);
}

// ---------------- fused bias ----------------
__global__ void bfold_kernel(const float* __restrict__ seb, const float* __restrict__ qkw,
                             const float* __restrict__ qkb) {
    int j = blockIdx.x * blockDim.x + threadIdx.x;
    float s = qkb[j];
    for (int k = 0; k < 512; k++) s = fmaf(seb[k], qkw[(size_t)k * 1024 + j], s);
    g_bf[j] = (j >= 512) ? s * 0.125f : s;
}

// ---------------- in-edge CSR build ----------------
__global__ void csr_count_kernel(const void* __restrict__ edge, int E) {
    int e = blockIdx.x * blockDim.x + threadIdx.x;
    if (e >= E) return;
    int is64 = g_flags[0];
    long long t = ldidx(edge, is64, (long long)E + e);
    atomicAdd(&g_deg[t], 1);
}

__global__ void csr_scan_kernel(int N) {
    __shared__ int ss[1024];
    int t = threadIdx.x;
    int chunk = (N + 1023) >> 10;
    int s0 = t * chunk, s1 = min(s0 + chunk, N);
    int sum = 0;
    for (int i = s0; i < s1; i++) sum += g_deg[i];
    ss[t] = sum;
    __syncthreads();
    for (int off = 1; off < 1024; off <<= 1) {
        int v = (t >= off) ? ss[t - off] : 0;
        __syncthreads();
        ss[t] += v;
        __syncthreads();
    }
    int base = (t == 0) ? 0 : ss[t - 1];
    for (int i = s0; i < s1; i++) {
        g_bse[i] = base;
        g_cur[i] = base;
        base += g_deg[i];
    }
}

__global__ void csr_fill_kernel(const void* __restrict__ edge, int E) {
    int e = blockIdx.x * blockDim.x + threadIdx.x;
    if (e >= E) return;
    int is64 = g_flags[0];
    long long s = ldidx(edge, is64, e);
    long long t = ldidx(edge, is64, (long long)E + e);
    int pos = atomicAdd(&g_cur[t], 1);
    g_eidx[pos] = (int)s;
}

// ---------------- GIN aggregation ----------------
__global__ void __launch_bounds__(128)
gather_kernel(const float* __restrict__ h, __nv_bfloat16* __restrict__ ohi,
              __nv_bfloat16* __restrict__ olo) {
    int node = blockIdx.x;
    int d4 = threadIdx.x;
    int base = g_bse[node], deg = g_deg[node];
    float4 acc = *(const float4*)(h + (size_t)node * D + d4 * 4);
    int j = 0;
    for (; j + 4 <= deg; j += 4) {
        int s0 = g_eidx[base + j];
        int s1 = g_eidx[base + j + 1];
        int s2 = g_eidx[base + j + 2];
        int s3 = g_eidx[base + j + 3];
        float4 v0 = *(const float4*)(h + (size_t)s0 * D + d4 * 4);
        float4 v1 = *(const float4*)(h + (size_t)s1 * D + d4 * 4);
        float4 v2 = *(const float4*)(h + (size_t)s2 * D + d4 * 4);
        float4 v3 = *(const float4*)(h + (size_t)s3 * D + d4 * 4);
        acc.x += v0.x + v1.x + v2.x + v3.x;
        acc.y += v0.y + v1.y + v2.y + v3.y;
        acc.z += v0.z + v1.z + v2.z + v3.z;
        acc.w += v0.w + v1.w + v2.w + v3.w;
    }
    for (; j < deg; j++) {
        int src = g_eidx[base + j];
        float4 v = *(const float4*)(h + (size_t)src * D + d4 * 4);
        acc.x += v.x; acc.y += v.y; acc.z += v.z; acc.w += v.w;
    }
    unsigned h0, l0, h1, l1;
    split2(acc.x, acc.y, h0, l0);
    split2(acc.z, acc.w, h1, l1);
    *(uint2*)((char*)ohi + ((size_t)node * D + d4 * 4) * 2) = make_uint2(h0, h1);
    *(uint2*)((char*)olo + ((size_t)node * D + d4 * 4) * 2) = make_uint2(l0, l1);
}

// ---------------- pipelined tensor-core GEMM ----------------
#define OFF_ALO 4096u
#define OFF_BHI 8192u
#define OFF_BLO 16384u
#define STAGEB  24576u
#define GEMM_SMEM (3 * 24576 + 128)

#define LDM4(r0, r1, r2, r3, addr) \
    asm volatile("ldmatrix.sync.aligned.m8n8.x4.shared.b16 {%0,%1,%2,%3}, [%4];" \
                 : "=r"(r0), "=r"(r1), "=r"(r2), "=r"(r3) : "r"(addr))
#define CP16(dst, src) \
    asm volatile("cp.async.cg.shared.global [%0], [%1], 16;" :: "r"(dst), "l"(src))
#define CPCOMMIT() asm volatile("cp.async.commit_group;" ::: "memory")
#define CPWAIT1()  asm volatile("cp.async.wait_group 1;" ::: "memory")
#define CPWAIT0()  asm volatile("cp.async.wait_group 0;" ::: "memory")
#define STS32(addr, v) \
    asm volatile("st.shared.b32 [%0], %1;" :: "r"(addr), "r"(v) : "memory")

__device__ __forceinline__ void mma_bf16(float* c, unsigned a0, unsigned a1, unsigned a2,
                                         unsigned a3, unsigned b0, unsigned b1) {
    asm volatile(
        "mma.sync.aligned.m16n8k16.row.col.f32.bf16.bf16.f32 "
        "{%0,%1,%2,%3}, {%4,%5,%6,%7}, {%8,%9}, {%0,%1,%2,%3};"
        : "+f"(c[0]), "+f"(c[1]), "+f"(c[2]), "+f"(c[3])
        : "r"(a0), "r"(a1), "r"(a2), "r"(a3), "r"(b0), "r"(b1));
}

template <bool RELU, bool WSPLIT, bool WF32, bool WT>
__global__ void __launch_bounds__(256, 3)
pgemm_kernel(const __nv_bfloat16* __restrict__ Ahi, const __nv_bfloat16* __restrict__ Alo,
             const __nv_bfloat16* __restrict__ Bhi, const __nv_bfloat16* __restrict__ Blo,
             const float* __restrict__ bias, float* __restrict__ C,
             __nv_bfloat16* __restrict__ Ohi, __nv_bfloat16* __restrict__ Olo,
             int M, int Nc, int qscol, long long wts) {
    extern __shared__ char dynsmem[];
    unsigned sb = (smem_u32(dynsmem) + 127) & ~127u;

    int tid = threadIdx.x, wid = tid >> 5, lane = tid & 31;
    int m0 = blockIdx.y * 64, n0 = blockIdx.x * 128;
    int warp_m = (wid & 1) * 32, warp_n = (wid >> 1) * 32;
    int g = lane >> 2, kp = (lane & 3) * 2;

    int crow = tid >> 2, cch = tid & 3;
    unsigned dstA = (unsigned)(crow * 64 + ((cch ^ ((crow >> 1) & 3)) * 16));
    long long arow = m0 + crow; if (arow > M - 1) arow = M - 1;
    const __nv_bfloat16* pAhi = Ahi + arow * 512 + cch * 8;
    const __nv_bfloat16* pAlo = Alo + arow * 512 + cch * 8;
    int brow2 = crow + 64;
    unsigned dstB0 = dstA;
    unsigned dstB1 = (unsigned)(brow2 * 64 + ((cch ^ ((brow2 >> 1) & 3)) * 16));
    const __nv_bfloat16* pBhi0 = Bhi + (size_t)(n0 + crow) * 512 + cch * 8;
    const __nv_bfloat16* pBhi1 = Bhi + (size_t)(n0 + brow2) * 512 + cch * 8;
    const __nv_bfloat16* pBlo0 = Blo + (size_t)(n0 + crow) * 512 + cch * 8;
    const __nv_bfloat16* pBlo1 = Blo + (size_t)(n0 + brow2) * 512 + cch * 8;

    int rA = lane & 15, hA = lane >> 4;
    unsigned aoff = (unsigned)((warp_m + rA) * 64 + ((hA ^ ((rA >> 1) & 3)) * 16));
    int rB = (lane & 7) + ((lane >> 4) * 8);
    int cB = (lane >> 3) & 1;
    unsigned boff = (unsigned)((warp_n + rB) * 64 + ((cB ^ ((rB >> 1) & 3)) * 16));

    float acc[2][4][4];
#pragma unroll
    for (int i = 0; i < 2; i++)
#pragma unroll
        for (int j = 0; j < 4; j++)
#pragma unroll
            for (int r = 0; r < 4; r++) acc[i][j][r] = 0.f;

#pragma unroll
    for (int s = 0; s < 2; s++) {
        unsigned bb = sb + (unsigned)s * STAGEB;
        int kg = s * 32;
        CP16(bb + dstA,            pAhi + kg);
        CP16(bb + OFF_ALO + dstA,  pAlo + kg);
        CP16(bb + OFF_BHI + dstB0, pBhi0 + kg);
        CP16(bb + OFF_BHI + dstB1, pBhi1 + kg);
        CP16(bb + OFF_BLO + dstB0, pBlo0 + kg);
        CP16(bb + OFF_BLO + dstB1, pBlo1 + kg);
        CPCOMMIT();
    }

    unsigned bufoff[3] = {0u, STAGEB, 2u * STAGEB};
#pragma unroll 1
    for (int s = 0; s < 16; s++) {
        CPWAIT1();
        __syncthreads();
        if (s + 2 < 16) {
            unsigned bb = sb + bufoff[(s + 2) % 3];
            int kg = (s + 2) * 32;
            CP16(bb + dstA,            pAhi + kg);
            CP16(bb + OFF_ALO + dstA,  pAlo + kg);
            CP16(bb + OFF_BHI + dstB0, pBhi0 + kg);
            CP16(bb + OFF_BHI + dstB1, pBhi1 + kg);
            CP16(bb + OFF_BLO + dstB0, pBlo0 + kg);
            CP16(bb + OFF_BLO + dstB1, pBlo1 + kg);
        }
        CPCOMMIT();

        unsigned bcur = sb + bufoff[s % 3];
#pragma unroll
        for (int kx = 0; kx < 2; kx++) {
            unsigned kxor = kx ? 32u : 0u;
            unsigned ah[2][4], al[2][4], bh[4][2], bl[4][2];
#pragma unroll
            for (int mi = 0; mi < 2; mi++)
                LDM4(ah[mi][0], ah[mi][1], ah[mi][2], ah[mi][3],
                     bcur + (unsigned)(mi * 1024) + (aoff ^ kxor));
            {
                unsigned r0, r1, r2, r3;
#pragma unroll
                for (int p = 0; p < 2; p++) {
                    LDM4(r0, r1, r2, r3, bcur + OFF_BHI + (unsigned)(p * 1024) + (boff ^ kxor));
                    bh[2 * p][0] = r0; bh[2 * p][1] = r1;
                    bh[2 * p + 1][0] = r2; bh[2 * p + 1][1] = r3;
                    LDM4(r0, r1, r2, r3, bcur + OFF_BLO + (unsigned)(p * 1024) + (boff ^ kxor));
                    bl[2 * p][0] = r0; bl[2 * p][1] = r1;
                    bl[2 * p + 1][0] = r2; bl[2 * p + 1][1] = r3;
                }
            }
#pragma unroll
            for (int mi = 0; mi < 2; mi++)
                LDM4(al[mi][0], al[mi][1], al[mi][2], al[mi][3],
                     bcur + OFF_ALO + (unsigned)(mi * 1024) + (aoff ^ kxor));
#pragma unroll
            for (int mi = 0; mi < 2; mi++)
#pragma unroll
                for (int ni = 0; ni < 4; ni++)
                    mma_bf16(acc[mi][ni], ah[mi][0], ah[mi][1], ah[mi][2], ah[mi][3],
                             bh[ni][0], bh[ni][1]);
#pragma unroll
            for (int mi = 0; mi < 2; mi++)
#pragma unroll
                for (int ni = 0; ni < 4; ni++)
                    mma_bf16(acc[mi][ni], ah[mi][0], ah[mi][1], ah[mi][2], ah[mi][3],
                             bl[ni][0], bl[ni][1]);
#pragma unroll
            for (int mi = 0; mi < 2; mi++)
#pragma unroll
                for (int ni = 0; ni < 4; ni++)
                    mma_bf16(acc[mi][ni], al[mi][0], al[mi][1], al[mi][2], al[mi][3],
                             bh[ni][0], bh[ni][1]);
        }
    }

#pragma unroll
    for (int mi = 0; mi < 2; mi++) {
        int row0 = m0 + warp_m + mi * 16 + g;
        int row1 = row0 + 8;
#pragma unroll
        for (int ni = 0; ni < 4; ni++) {
            int col = n0 + warp_n + ni * 8 + kp;
            float b0 = bias[col], b1 = bias[col + 1];
            float o0 = acc[mi][ni][0] + b0, o1 = acc[mi][ni][1] + b1;
            float o2 = acc[mi][ni][2] + b0, o3 = acc[mi][ni][3] + b1;
            if (RELU) {
                o0 = fmaxf(o0, 0.f); o1 = fmaxf(o1, 0.f);
                o2 = fmaxf(o2, 0.f); o3 = fmaxf(o3, 0.f);
            }
            if (WT) {
                float f0 = (col >= qscol) ? 0.125f : 1.f;
                float f1 = (col + 1 >= qscol) ? 0.125f : 1.f;
                o0 *= f0; o1 *= f1; o2 *= f0; o3 *= f1;
            }
            if (row0 < M) {
                if (WF32)
                    *(float2*)(C + (size_t)row0 * Nc + col) = make_float2(o0, o1);
                if (WSPLIT && !WT) {
                    unsigned hw, lw;
                    split2(o0, o1, hw, lw);
                    *(unsigned*)((char*)Ohi + ((size_t)row0 * Nc + col) * 2) = hw;
                    *(unsigned*)((char*)Olo + ((size_t)row0 * Nc + col) * 2) = lw;
                }
                if (WT) {
                    __nv_bfloat16 h0 = __float2bfloat16(o0);
                    __nv_bfloat16 h1 = __float2bfloat16(o1);
                    Ohi[(size_t)col * wts + row0] = h0;
                    Olo[(size_t)col * wts + row0] = __float2bfloat16(o0 - __bfloat162float(h0));
                    Ohi[(size_t)(col + 1) * wts + row0] = h1;
                    Olo[(size_t)(col + 1) * wts + row0] = __float2bfloat16(o1 - __bfloat162float(h1));
                }
            }
            if (row1 < M) {
                if (WF32)
                    *(float2*)(C + (size_t)row1 * Nc + col) = make_float2(o2, o3);
                if (WSPLIT && !WT) {
                    unsigned hw, lw;
                    split2(o2, o3, hw, lw);
                    *(unsigned*)((char*)Ohi + ((size_t)row1 * Nc + col) * 2) = hw;
                    *(unsigned*)((char*)Olo + ((size_t)row1 * Nc + col) * 2) = lw;
                }
                if (WT) {
                    __nv_bfloat16 h2 = __float2bfloat16(o2);
                    __nv_bfloat16 h3 = __float2bfloat16(o3);
                    Ohi[(size_t)col * wts + row1] = h2;
                    Olo[(size_t)col * wts + row1] = __float2bfloat16(o2 - __bfloat162float(h2));
                    Ohi[(size_t)(col + 1) * wts + row1] = h3;
                    Olo[(size_t)(col + 1) * wts + row1] = __float2bfloat16(o3 - __bfloat162float(h3));
                }
            }
        }
    }
}

// ---------------- BatchNorm ----------------
__global__ void bn_stats_kernel(const float* __restrict__ h, int N) {
    int c = threadIdx.x;
    double s = 0.0, s2 = 0.0;
    for (int r = blockIdx.x; r < N; r += gridDim.x) {
        float v = h[(size_t)r * D + c];
        s += v;
        s2 += (double)v * v;
    }
    atomicAdd(&g_stats[c], s);
    atomicAdd(&g_stats[D + c], s2);
}

__global__ void bn_apply_kernel(const float* __restrict__ h, const float* __restrict__ gamma,
                                const float* __restrict__ beta,
                                __nv_bfloat16* __restrict__ ohi, __nv_bfloat16* __restrict__ olo,
                                int N) {
    long long i = (long long)blockIdx.x * blockDim.x + threadIdx.x;
    if (i >= (long long)N * (D / 2)) return;
    int p = (int)(i & (D / 2 - 1));
    long long row = i >> 8;
    int c0 = 2 * p, c1 = c0 + 1;
    double mean0 = g_stats[c0] / N, mean1 = g_stats[c1] / N;
    double var0  = g_stats[D + c0] / N - mean0 * mean0;
    double var1  = g_stats[D + c1] / N - mean1 * mean1;
    float is0 = rsqrtf((float)var0 + 1e-5f), is1 = rsqrtf((float)var1 + 1e-5f);
    float2 v = *(const float2*)(h + row * D + c0);
    float o0 = (v.x - (float)mean0) * is0 * gamma[c0] + beta[c0];
    float o1 = (v.y - (float)mean1) * is1 * gamma[c1] + beta[c1];
    unsigned hw, lw;
    split2(o0, o1, hw, lw);
    *(unsigned*)((char*)ohi + (row * D + c0) * 2) = hw;
    *(unsigned*)((char*)olo + (row * D + c0) * 2) = lw;
}

// ---------------- attention: full tensor-core (scores + AV), frag softmax ----------------
// Block = (64-query tile, head, graph); 128 thr = 4 warps; warp w owns q-rows [16w,16w+16).
// Thread owns frag rows g=lane>>2 and g+8: softmax/corr/l fully in-lane via quad shuffles.
// P packed split-bf16 into PA smem; AV = P @ V^T-tiles via mma (V^T pre-built by v-GEMM).
__global__ void __launch_bounds__(128)
attn_kernel(const void* __restrict__ ptr, int L, int Nn,
            const __nv_bfloat16* __restrict__ qkhi, const __nv_bfloat16* __restrict__ qklo,
            const __nv_bfloat16* __restrict__ vthi, const __nv_bfloat16* __restrict__ vtlo,
            __nv_bfloat16* __restrict__ ohi, __nv_bfloat16* __restrict__ olo) {
    extern __shared__ char smraw[];
    unsigned sb0 = smem_u32(smraw);
    unsigned sb = (sb0 + 127) & ~127u;
    const unsigned QHI = 0, QLO = 8192, KHI = 16384, KLO = 24576;
    const unsigned VHI = 32768, VLO = 40960, PHI = 49152, PLO = 57344;

    int qt = blockIdx.x, hh = blockIdx.y, b = blockIdx.z;
    int is64 = g_flags[1];
    long long p0 = ldidx(ptr, is64, b);
    long long p1 = ldidx(ptr, is64, b + 1);
    int s = (int)(p1 - p0);
    int qbase = qt * QT;
    if (qbase >= s) return;

    int tid = threadIdx.x, wid = tid >> 5, lane = tid & 31;
    int w16 = wid * 16;
    int g = lane >> 2, fc = (lane & 3) * 2;
    int rA = lane & 15, hA = lane >> 4;
    int rB = (lane & 7) + ((lane >> 4) * 8);
    int cB = (lane >> 3) & 1;
    unsigned aswz = (unsigned)((hA ^ (rA & 3)) * 16);
    unsigned bswz = (unsigned)((cB ^ (rB & 3)) * 16);

    // Q tile (once): q-half cols 512.., pre-scaled by 0.125 via W'/b'
    {
        int row = tid >> 1, kb = tid & 1;
        long long node = p0 + min(qbase + row, s - 1);
        const __nv_bfloat16* qh = qkhi + node * 1024 + 512 + hh * 64 + kb * 32;
        const __nv_bfloat16* ql = qklo + node * 1024 + 512 + hh * 64 + kb * 32;
        unsigned dst = (unsigned)((row * 2 + kb) * 64);
        unsigned sw = (unsigned)(row & 3);
#pragma unroll
        for (int c = 0; c < 4; c++) {
            CP16(sb + QHI + dst + ((c ^ sw) * 16), qh + c * 8);
            CP16(sb + QLO + dst + ((c ^ sw) * 16), ql + c * 8);
        }
        CPCOMMIT();
    }

    // this thread's two q rows
    int r0 = w16 + g, r1 = r0 + 8;
    bool r0ok = (qbase + r0) < s, r1ok = (qbase + r1) < s;
    const unsigned char* mk0 = g_mask + ((size_t)b * L + (r0ok ? qbase + r0 : 0)) * L;
    const unsigned char* mk1 = g_mask + ((size_t)b * L + (r1ok ? qbase + r1 : 0)) * L;
    unsigned swz0 = (unsigned)(r0 & 3), swz1 = (unsigned)(r1 & 3);

    float oacc[8][4];
#pragma unroll
    for (int nt = 0; nt < 8; nt++)
#pragma unroll
        for (int r = 0; r < 4; r++) oacc[nt][r] = 0.f;
    float mr0 = -1e30f, mr1 = -1e30f, lr0 = 0.f, lr1 = 0.f;

    int kmax = (s - 8) & ~7;   // 8-aligned clamp for 16B cp.async sources

    for (int j0 = 0; j0 < s; j0 += 64) {
        __syncthreads();
        // K tile
        {
            int row = tid >> 1, kb = tid & 1;
            long long node = p0 + min(j0 + row, s - 1);
            const __nv_bfloat16* kh = qkhi + node * 1024 + hh * 64 + kb * 32;
            const __nv_bfloat16* kl = qklo + node * 1024 + hh * 64 + kb * 32;
            unsigned dst = (unsigned)((row * 2 + kb) * 64);
            unsigned sw = (unsigned)(row & 3);
#pragma unroll
            for (int c = 0; c < 4; c++) {
                CP16(sb + KHI + dst + ((c ^ sw) * 16), kh + c * 8);
                CP16(sb + KLO + dst + ((c ^ sw) * 16), kl + c * 8);
            }
        }
        // V^T tile: rows = dims, cols = keys (contiguous in V^T); clamp key chunks
        {
            int drow = tid >> 1, kb = tid & 1;
            const __nv_bfloat16* vh = vthi + (size_t)(hh * 64 + drow) * Nn + p0;
            const __nv_bfloat16* vl = vtlo + (size_t)(hh * 64 + drow) * Nn + p0;
            unsigned dst = (unsigned)((drow * 2 + kb) * 64);
            unsigned sw = (unsigned)(drow & 3);
#pragma unroll
            for (int c = 0; c < 4; c++) {
                int kidx = min(j0 + kb * 32 + c * 8, kmax);
                CP16(sb + VHI + dst + ((c ^ sw) * 16), vh + kidx);
                CP16(sb + VLO + dst + ((c ^ sw) * 16), vl + kidx);
            }
        }
        CPCOMMIT();
        CPWAIT0();
        __syncthreads();

        // ---- scores (mma): warp rows [w16,w16+16) x 64 keys ----
        float sacc[8][4];
#pragma unroll
        for (int nt = 0; nt < 8; nt++)
#pragma unroll
            for (int r = 0; r < 4; r++) sacc[nt][r] = 0.f;
#pragma unroll
        for (int ks = 0; ks < 4; ks++) {
            int kb = ks >> 1;
            unsigned kxor = (unsigned)((ks & 1) * 32);
            unsigned asub = (unsigned)((2 * (w16 + rA) + kb) * 64) + (aswz ^ kxor);
            unsigned ah[4], al[4], bh[8][2], bl[8][2];
            LDM4(ah[0], ah[1], ah[2], ah[3], sb + QHI + asub);
            LDM4(al[0], al[1], al[2], al[3], sb + QLO + asub);
#pragma unroll
            for (int p = 0; p < 4; p++) {
                unsigned bsub = (unsigned)((2 * (p * 16 + rB) + kb) * 64) + (bswz ^ kxor);
                unsigned q0, q1, q2, q3;
                LDM4(q0, q1, q2, q3, sb + KHI + bsub);
                bh[2 * p][0] = q0; bh[2 * p][1] = q1;
                bh[2 * p + 1][0] = q2; bh[2 * p + 1][1] = q3;
                LDM4(q0, q1, q2, q3, sb + KLO + bsub);
                bl[2 * p][0] = q0; bl[2 * p][1] = q1;
                bl[2 * p + 1][0] = q2; bl[2 * p + 1][1] = q3;
            }
#pragma unroll
            for (int nt = 0; nt < 8; nt++)
                mma_bf16(sacc[nt], ah[0], ah[1], ah[2], ah[3], bh[nt][0], bh[nt][1]);
#pragma unroll
            for (int nt = 0; nt < 8; nt++)
                mma_bf16(sacc[nt], al[0], al[1], al[2], al[3], bh[nt][0], bh[nt][1]);
#pragma unroll
            for (int nt = 0; nt < 8; nt++)
                mma_bf16(sacc[nt], ah[0], ah[1], ah[2], ah[3], bl[nt][0], bl[nt][1]);
        }

        // ---- mask + frag-resident online softmax (quad shuffles) ----
#pragma unroll
        for (int nt = 0; nt < 8; nt++) {
            int c0 = nt * 8 + fc, c1 = c0 + 1;
            bool in0 = (j0 + c0 < s), in1 = (j0 + c1 < s);
            sacc[nt][0] = (in0 && mk0[j0 + c0] == 0) ? sacc[nt][0] : -1e30f;
            sacc[nt][1] = (in1 && mk0[j0 + c1] == 0) ? sacc[nt][1] : -1e30f;
            sacc[nt][2] = (in0 && mk1[j0 + c0] == 0) ? sacc[nt][2] : -1e30f;
            sacc[nt][3] = (in1 && mk1[j0 + c1] == 0) ? sacc[nt][3] : -1e30f;
        }
        float mt0 = -1e30f, mt1 = -1e30f;
#pragma unroll
        for (int nt = 0; nt < 8; nt++) {
            mt0 = fmaxf(mt0, fmaxf(sacc[nt][0], sacc[nt][1]));
            mt1 = fmaxf(mt1, fmaxf(sacc[nt][2], sacc[nt][3]));
        }
        mt0 = fmaxf(mt0, __shfl_xor_sync(0xffffffffu, mt0, 1));
        mt0 = fmaxf(mt0, __shfl_xor_sync(0xffffffffu, mt0, 2));
        mt1 = fmaxf(mt1, __shfl_xor_sync(0xffffffffu, mt1, 1));
        mt1 = fmaxf(mt1, __shfl_xor_sync(0xffffffffu, mt1, 2));
        float mn0 = fmaxf(mr0, mt0), mn1 = fmaxf(mr1, mt1);
        float co0 = __expf(mr0 - mn0), co1 = __expf(mr1 - mn1);
        float ps0 = 0.f, ps1 = 0.f;
#pragma unroll
        for (int nt = 0; nt < 8; nt++) {
            float p00 = (sacc[nt][0] <= -1e29f) ? 0.f : __expf(sacc[nt][0] - mn0);
            float p01 = (sacc[nt][1] <= -1e29f) ? 0.f : __expf(sacc[nt][1] - mn0);
            float p10 = (sacc[nt][2] <= -1e29f) ? 0.f : __expf(sacc[nt][2] - mn1);
            float p11 = (sacc[nt][3] <= -1e29f) ? 0.f : __expf(sacc[nt][3] - mn1);
            ps0 += p00 + p01;
            ps1 += p10 + p11;
            int col = nt * 8 + fc;
            int kb = col >> 5;
            unsigned bofs = (unsigned)((col & 31) * 2);
            unsigned chunk = bofs >> 4, rem = bofs & 15;
            unsigned hw, lw;
            split2(p00, p01, hw, lw);
            unsigned a0 = (unsigned)((2 * r0 + kb) * 64) + ((chunk ^ swz0) * 16) + rem;
            STS32(sb + PHI + a0, hw);
            STS32(sb + PLO + a0, lw);
            split2(p10, p11, hw, lw);
            unsigned a1 = (unsigned)((2 * r1 + kb) * 64) + ((chunk ^ swz1) * 16) + rem;
            STS32(sb + PHI + a1, hw);
            STS32(sb + PLO + a1, lw);
        }
        ps0 += __shfl_xor_sync(0xffffffffu, ps0, 1);
        ps0 += __shfl_xor_sync(0xffffffffu, ps0, 2);
        ps1 += __shfl_xor_sync(0xffffffffu, ps1, 1);
        ps1 += __shfl_xor_sync(0xffffffffu, ps1, 2);
        lr0 = lr0 * co0 + ps0; mr0 = mn0;
        lr1 = lr1 * co1 + ps1; mr1 = mn1;
#pragma unroll
        for (int nt = 0; nt < 8; nt++) {
            oacc[nt][0] *= co0; oacc[nt][1] *= co0;
            oacc[nt][2] *= co1; oacc[nt][3] *= co1;
        }
        __syncwarp();

        // ---- AV (mma): O += P @ V^T-tiles ----
#pragma unroll
        for (int ks = 0; ks < 4; ks++) {
            int kb = ks >> 1;
            unsigned kxor = (unsigned)((ks & 1) * 32);
            unsigned asub = (unsigned)((2 * (w16 + rA) + kb) * 64) + (aswz ^ kxor);
            unsigned ah[4], al[4], bh[8][2], bl[8][2];
            LDM4(ah[0], ah[1], ah[2], ah[3], sb + PHI + asub);
            LDM4(al[0], al[1], al[2], al[3], sb + PLO + asub);
#pragma unroll
            for (int p = 0; p < 4; p++) {
                unsigned bsub = (unsigned)((2 * (p * 16 + rB) + kb) * 64) + (bswz ^ kxor);
                unsigned q0, q1, q2, q3;
                LDM4(q0, q1, q2, q3, sb + VHI + bsub);
                bh[2 * p][0] = q0; bh[2 * p][1] = q1;
                bh[2 * p + 1][0] = q2; bh[2 * p + 1][1] = q3;
                LDM4(q0, q1, q2, q3, sb + VLO + bsub);
                bl[2 * p][0] = q0; bl[2 * p][1] = q1;
                bl[2 * p + 1][0] = q2; bl[2 * p + 1][1] = q3;
            }
#pragma unroll
            for (int nt = 0; nt < 8; nt++)
                mma_bf16(oacc[nt], ah[0], ah[1], ah[2], ah[3], bh[nt][0], bh[nt][1]);
#pragma unroll
            for (int nt = 0; nt < 8; nt++)
                mma_bf16(oacc[nt], al[0], al[1], al[2], al[3], bh[nt][0], bh[nt][1]);
#pragma unroll
            for (int nt = 0; nt < 8; nt++)
                mma_bf16(oacc[nt], ah[0], ah[1], ah[2], ah[3], bl[nt][0], bl[nt][1]);
        }
        __syncwarp();
    }

    // ---- output: rows r0/r1, cols nt*8+fc..+1; divide by l, split-write ----
    if (r0ok && lr0 > 0.f) {
        float inv = 1.f / lr0;
        size_t base = ((p0 + qbase + r0) * D + hh * HD) * 2;
#pragma unroll
        for (int nt = 0; nt < 8; nt++) {
            unsigned hw, lw;
            split2(oacc[nt][0] * inv, oacc[nt][1] * inv, hw, lw);
            *(unsigned*)((char*)ohi + base + (nt * 8 + fc) * 2) = hw;
            *(unsigned*)((char*)olo + base + (nt * 8 + fc) * 2) = lw;
        }
    }
    if (r1ok && lr1 > 0.f) {
        float inv = 1.f / lr1;
        size_t base = ((p0 + qbase + r1) * D + hh * HD) * 2;
#pragma unroll
        for (int nt = 0; nt < 8; nt++) {
            unsigned hw, lw;
            split2(oacc[nt][2] * inv, oacc[nt][3] * inv, hw, lw);
            *(unsigned*)((char*)ohi + base + (nt * 8 + fc) * 2) = hw;
            *(unsigned*)((char*)olo + base + (nt * 8 + fc) * 2) = lw;
        }
    }
}

// ---------------- host orchestration ----------------
extern "C" void kernel_launch(void* const* d_in, const int* in_sizes, int n_in,
                              void* d_out, int out_size) {
    const float* x   = (const float*)d_in[0];
    const void* edge = d_in[1];
    const void* mask = d_in[2];
    const void* ptr  = d_in[3];
    const float* gw1   = (const float*)d_in[4];
    const float* gb1   = (const float*)d_in[5];
    const float* gw2   = (const float*)d_in[6];
    const float* gb2   = (const float*)d_in[7];
    const float* gamma = (const float*)d_in[8];
    const float* beta  = (const float*)d_in[9];
    const float* sw    = (const float*)d_in[10];
    const float* sb    = (const float*)d_in[11];
    const float* qkw   = (const float*)d_in[12];
    const float* qkb   = (const float*)d_in[13];
    const float* vw    = (const float*)d_in[14];
    const float* vb    = (const float*)d_in[15];
    const float* ow    = (const float*)d_in[16];
    const float* ob    = (const float*)d_in[17];
    float* out = (float*)d_out;

    int N  = in_sizes[0] / D;
    int E  = in_sizes[1] / 2;
    int Bg = in_sizes[3] - 1;
    int ngin = in_sizes[4] / (D * D);
    int L;
    {
        long long ll = (long long)in_sizes[2] / Bg;
        int l = 1;
        while ((long long)l * l < ll) l++;
        L = l;
    }
    long long masktotal = (long long)Bg * L * L;
    if (N > NMAX || masktotal > MASKMAX || ngin > 3 || E > EMAX) return;

    float *ph, *pbf, *pzero;
    double* pstats;
    __nv_bfloat16 *whi, *wlo, *shi0, *slo0, *shi1, *slo1, *wfhi, *wflo, *qkhi, *qklo, *vthi, *vtlo;
    int* pdeg;
    cudaGetSymbolAddress((void**)&ph,    g_h);
    cudaGetSymbolAddress((void**)&pstats, g_stats);
    cudaGetSymbolAddress((void**)&whi,   g_whi);
    cudaGetSymbolAddress((void**)&wlo,   g_wlo);
    cudaGetSymbolAddress((void**)&shi0,  g_shi0);
    cudaGetSymbolAddress((void**)&slo0,  g_slo0);
    cudaGetSymbolAddress((void**)&shi1,  g_shi1);
    cudaGetSymbolAddress((void**)&slo1,  g_slo1);
    cudaGetSymbolAddress((void**)&wfhi,  g_wfhi);
    cudaGetSymbolAddress((void**)&wflo,  g_wflo);
    cudaGetSymbolAddress((void**)&qkhi,  g_qkhi);
    cudaGetSymbolAddress((void**)&qklo,  g_qklo);
    cudaGetSymbolAddress((void**)&vthi,  g_vthi);
    cudaGetSymbolAddress((void**)&vtlo,  g_vtlo);
    cudaGetSymbolAddress((void**)&pbf,   g_bf);
    cudaGetSymbolAddress((void**)&pzero, g_zero);
    cudaGetSymbolAddress((void**)&pdeg,  g_deg);

    cudaFuncSetAttribute(pgemm_kernel<false, false, true, false>,
                         cudaFuncAttributeMaxDynamicSharedMemorySize, GEMM_SMEM);
    cudaFuncSetAttribute(pgemm_kernel<true, true, false, false>,
                         cudaFuncAttributeMaxDynamicSharedMemorySize, GEMM_SMEM);
    cudaFuncSetAttribute(pgemm_kernel<true, false, true, false>,
                         cudaFuncAttributeMaxDynamicSharedMemorySize, GEMM_SMEM);
    cudaFuncSetAttribute(pgemm_kernel<false, true, false, true>,
                         cudaFuncAttributeMaxDynamicSharedMemorySize, GEMM_SMEM);
    cudaFuncSetAttribute(pgemm_kernel<false, true, false, false>,
                         cudaFuncAttributeMaxDynamicSharedMemorySize, GEMM_SMEM);
    cudaFuncSetAttribute(attn_kernel,
                         cudaFuncAttributeMaxDynamicSharedMemorySize, ATTN_SMEM);

    const size_t SZ = (size_t)D * D;
    size_t off_v = 0, off_g1[3], off_g2[3];
    size_t cur = SZ;
    for (int i = 0; i < 3; i++) { off_g1[i] = cur; cur += SZ; off_g2[i] = cur; cur += SZ; }
    size_t off_qk = cur; cur += 2 * SZ;
    size_t off_o  = cur;

    WJobs J;
    int jn = 0, rows = 0;
    auto addjob = [&](const float* src, size_t off, int Nc) {
        J.src[jn] = src; J.hi[jn] = whi + off; J.lo[jn] = wlo + off;
        J.N[jn] = Nc; J.row0[jn] = rows;
        rows += Nc; jn++;
    };
    addjob(vw, off_v, D);
    for (int i = 0; i < ngin; i++) {
        addjob(gw1 + SZ * i, off_g1[i], D);
        addjob(gw2 + SZ * i, off_g2[i], D);
    }
    addjob(qkw, off_qk, 2 * D);
    addjob(ow, off_o, D);
    J.njobs = jn;

    int mt = (N + 63) / 64;
    dim3 g512(D / 128, mt);
    dim3 g1024(2 * D / 128, mt);
    dim3 gprep(2 * D / 128, 512 / 64);
    const int NOSC = 1 << 30;

    detect_kernel<<<1, 256>>>((const int*)edge, (const int*)ptr, (const unsigned int*)mask);
    asplit_kernel<<<N, 128>>>(x, shi0, slo0);
    wsplit_all_kernel<<<rows, 256>>>(J);
    // v = x@vw, emitted directly as split V^T [dim][node]
    pgemm_kernel<false, true, false, true><<<g512, 256, GEMM_SMEM>>>(
        shi0, slo0, whi + off_v, wlo + off_v, vb, nullptr, vthi, vtlo, N, D, NOSC, (long long)N);

    // fused se->qk weight prep (q-half scaled by 0.125)
    asplit_kernel<<<512, 128>>>(sw, shi1, slo1);
    pgemm_kernel<false, true, false, true><<<gprep, 256, GEMM_SMEM>>>(
        shi1, slo1, whi + off_qk, wlo + off_qk, pzero, nullptr, wfhi, wflo, 512, 2 * D, 512, 512);
    bfold_kernel<<<4, 256>>>(sb, qkw, qkb);

    mask_convert_kernel<<<(unsigned)((masktotal + 511) / 512), 512>>>(mask, masktotal);
    cudaMemsetAsync(pdeg, 0, (size_t)N * sizeof(int));
    csr_count_kernel<<<(E + 255) / 256, 256>>>(edge, E);
    csr_scan_kernel<<<1, 1024>>>(N);
    csr_fill_kernel<<<(E + 255) / 256, 256>>>(edge, E);

    const float* hin = x;
    for (int i = 0; i < ngin; i++) {
        gather_kernel<<<N, 128>>>(hin, shi1, slo1);
        pgemm_kernel<true, true, false, false><<<g512, 256, GEMM_SMEM>>>(
            shi1, slo1, whi + off_g1[i], wlo + off_g1[i], gb1 + (size_t)i * D,
            nullptr, shi0, slo0, N, D, NOSC, 0);
        pgemm_kernel<true, false, true, false><<<g512, 256, GEMM_SMEM>>>(
            shi0, slo0, whi + off_g2[i], wlo + off_g2[i], gb2 + (size_t)i * D,
            ph, nullptr, nullptr, N, D, NOSC, 0);
        hin = ph;
    }

    cudaMemsetAsync(pstats, 0, 2 * D * sizeof(double));
    bn_stats_kernel<<<256, D>>>(ph, N);
    bn_apply_kernel<<<(unsigned)(((long long)N * (D / 2) + 255) / 256), 256>>>(
        ph, gamma, beta, shi1, slo1, N);

    // qk = bn @ W' + b' -> split output
    pgemm_kernel<false, true, false, false><<<g1024, 256, GEMM_SMEM>>>(
        shi1, slo1, wfhi, wflo, pbf, nullptr, qkhi, qklo, N, 2 * D, NOSC, 0);

    dim3 gattn((L + QT - 1) / QT, NHEAD, Bg);
    attn_kernel<<<gattn, 128, ATTN_SMEM>>>(ptr, L, N, qkhi, qklo, vthi, vtlo, shi1, slo1);

    pgemm_kernel<false, false, true, false><<<g512, 256, GEMM_SMEM>>>(
        shi1, slo1, whi + off_o, wlo + off_o, ob, out, nullptr, nullptr, N, D, NOSC, 0);
}

// round 16
// speedup vs baseline: 1.2713x; 1.0657x over previous
#include <cuda_runtime.h>
#include <cuda_bf16.h>
#include <math.h>

#define D 512
#define NMAX 12288
#define HD 64
#define NHEAD 8
#define MASKMAX (32 * 512 * 512)
#define WELEMS 2883584
#define EMAX (16 * NMAX)
#define QT 64
#define ATTN_SMEM (65536 + 128)

// ---------------- scratch (static device globals; no allocation) ----------------
__device__ float  g_h  [NMAX * D];
__device__ double g_stats[2 * D];
__device__ unsigned char g_mask[MASKMAX];
__device__ __nv_bfloat16 g_whi[WELEMS];
__device__ __nv_bfloat16 g_wlo[WELEMS];
__device__ __nv_bfloat16 g_shi0[NMAX * D];
__device__ __nv_bfloat16 g_slo0[NMAX * D];
__device__ __nv_bfloat16 g_shi1[NMAX * D];
__device__ __nv_bfloat16 g_slo1[NMAX * D];
__device__ __nv_bfloat16 g_shi2[NMAX * D];
__device__ __nv_bfloat16 g_slo2[NMAX * D];
__device__ __nv_bfloat16 g_swhi[512 * 512];
__device__ __nv_bfloat16 g_swlo[512 * 512];
__device__ __nv_bfloat16 g_qkhi[NMAX * 2 * D];
__device__ __nv_bfloat16 g_qklo[NMAX * 2 * D];
__device__ __nv_bfloat16 g_vthi[(size_t)D * NMAX];   // V^T [dim][node], split
__device__ __nv_bfloat16 g_vtlo[(size_t)D * NMAX];
__device__ __nv_bfloat16 g_wfhi[1024 * 512];
__device__ __nv_bfloat16 g_wflo[1024 * 512];
__device__ float  g_bf[1024];
__device__ float  g_zero[1024];
__device__ int    g_flags[4];
__device__ int    g_deg [NMAX];
__device__ int    g_bse [NMAX];
__device__ int    g_cur [NMAX];
__device__ int    g_eidx[EMAX];

__device__ __forceinline__ long long ldidx(const void* p, int is64, long long i) {
    if (is64) return ((const long long*)p)[i];
    return (long long)((const int*)p)[i];
}

__device__ __forceinline__ unsigned smem_u32(const void* p) {
    unsigned a;
    asm("{ .reg .u64 t; cvta.to.shared.u64 t, %1; cvt.u32.u64 %0, t; }" : "=r"(a) : "l"(p));
    return a;
}

__device__ __forceinline__ unsigned pack_bf2(float x, float y) {
    __nv_bfloat162 p(__float2bfloat16(x), __float2bfloat16(y));
    return *(unsigned*)&p;
}
__device__ __forceinline__ void split2(float x, float y, unsigned& hiw, unsigned& low) {
    __nv_bfloat16 hx = __float2bfloat16(x), hy = __float2bfloat16(y);
    __nv_bfloat162 hp(hx, hy);
    hiw = *(unsigned*)&hp;
    low = pack_bf2(x - __bfloat162float(hx), y - __bfloat162float(hy));
}

// ---------------- detection ----------------
__global__ void detect_kernel(const int* __restrict__ ew, const int* __restrict__ pw,
                              const unsigned int* __restrict__ mw) {
    __shared__ int bad;
    if (threadIdx.x == 0) bad = 0;
    __syncthreads();
    int ok = 1;
    for (int i = threadIdx.x; i < 4096; i += 256) {
        unsigned int w = mw[i];
        if (w != 0u && w != 1u && w != 0x3f800000u) { ok = 0; break; }
    }
    if (!ok) atomicExch(&bad, 1);
    __syncthreads();
    if (threadIdx.x == 0) {
        g_flags[0] = (ew[17] == 0) ? 1 : 0;
        g_flags[1] = (pw[1]  == 0) ? 1 : 0;
        g_flags[2] = bad ? 0 : 1;
    }
}

__global__ void mask_convert_kernel(const void* __restrict__ mask, long long total) {
    long long i = (long long)blockIdx.x * blockDim.x + threadIdx.x;
    if (i >= total) return;
    unsigned char m;
    if (g_flags[2]) m = (((const unsigned int*)mask)[i] != 0u) ? 1 : 0;
    else            m = (((const unsigned char*)mask)[i] != 0) ? 1 : 0;
    g_mask[i] = m;
}

// ---------------- fused weight split ----------------
struct WJobs {
    const float* src[12];
    __nv_bfloat16* hi[12];
    __nv_bfloat16* lo[12];
    int N[12];
    int row0[12];
    int njobs;
};

__global__ void wsplit_all_kernel(WJobs J) {
    int row = blockIdx.x;
    int j = 0;
    while (j + 1 < J.njobs && row >= J.row0[j + 1]) j++;
    int n = row - J.row0[j];
    int Nc = J.N[j];
    const float* src = J.src[j];
    __nv_bfloat16* hi = J.hi[j];
    __nv_bfloat16* lo = J.lo[j];
    for (int k = threadIdx.x; k < 512; k += blockDim.x) {
        float v = src[(size_t)k * Nc + n];
        __nv_bfloat16 h = __float2bfloat16(v);
        hi[(size_t)n * 512 + k] = h;
        lo[(size_t)n * 512 + k] = __float2bfloat16(v - __bfloat162float(h));
    }
}

// ---------------- activation split ----------------
__global__ void __launch_bounds__(128)
asplit_kernel(const float* __restrict__ x, __nv_bfloat16* __restrict__ hi,
              __nv_bfloat16* __restrict__ lo) {
    int node = blockIdx.x, t = threadIdx.x;
    float4 v = *(const float4*)(x + (size_t)node * D + t * 4);
    unsigned h0, l0, h1, l1;
    split2(v.x, v.y, h0, l0);
    split2(v.z, v.w, h1, l1);
    *(uint2*)((char*)hi + ((size_t)node * D + t * 4) * 2) = make_uint2(h0, h1);
    *(uint2*)((char*)lo + ((size_t)node * D + t * 4) * 2) = make_uint2(l0, l1);
}

// ---------------- fused bias ----------------
__global__ void bfold_kernel(const float* __restrict__ seb, const float* __restrict__ qkw,
                             const float* __restrict__ qkb) {
    int j = blockIdx.x * blockDim.x + threadIdx.x;
    float s = qkb[j];
    for (int k = 0; k < 512; k++) s = fmaf(seb[k], qkw[(size_t)k * 1024 + j], s);
    g_bf[j] = (j >= 512) ? s * 0.125f : s;
}

// ---------------- in-edge CSR build ----------------
__global__ void csr_count_kernel(const void* __restrict__ edge, int E) {
    int e = blockIdx.x * blockDim.x + threadIdx.x;
    if (e >= E) return;
    int is64 = g_flags[0];
    long long t = ldidx(edge, is64, (long long)E + e);
    atomicAdd(&g_deg[t], 1);
}

__global__ void csr_scan_kernel(int N) {
    __shared__ int ss[1024];
    int t = threadIdx.x;
    int chunk = (N + 1023) >> 10;
    int s0 = t * chunk, s1 = min(s0 + chunk, N);
    int sum = 0;
    for (int i = s0; i < s1; i++) sum += g_deg[i];
    ss[t] = sum;
    __syncthreads();
    for (int off = 1; off < 1024; off <<= 1) {
        int v = (t >= off) ? ss[t - off] : 0;
        __syncthreads();
        ss[t] += v;
        __syncthreads();
    }
    int base = (t == 0) ? 0 : ss[t - 1];
    for (int i = s0; i < s1; i++) {
        g_bse[i] = base;
        g_cur[i] = base;
        base += g_deg[i];
    }
}

__global__ void csr_fill_kernel(const void* __restrict__ edge, int E) {
    int e = blockIdx.x * blockDim.x + threadIdx.x;
    if (e >= E) return;
    int is64 = g_flags[0];
    long long s = ldidx(edge, is64, e);
    long long t = ldidx(edge, is64, (long long)E + e);
    int pos = atomicAdd(&g_cur[t], 1);
    g_eidx[pos] = (int)s;
}

// ---------------- GIN aggregation ----------------
__global__ void __launch_bounds__(128)
gather_kernel(const float* __restrict__ h, __nv_bfloat16* __restrict__ ohi,
              __nv_bfloat16* __restrict__ olo) {
    int node = blockIdx.x;
    int d4 = threadIdx.x;
    int base = g_bse[node], deg = g_deg[node];
    float4 acc = *(const float4*)(h + (size_t)node * D + d4 * 4);
    int j = 0;
    for (; j + 4 <= deg; j += 4) {
        int s0 = g_eidx[base + j];
        int s1 = g_eidx[base + j + 1];
        int s2 = g_eidx[base + j + 2];
        int s3 = g_eidx[base + j + 3];
        float4 v0 = *(const float4*)(h + (size_t)s0 * D + d4 * 4);
        float4 v1 = *(const float4*)(h + (size_t)s1 * D + d4 * 4);
        float4 v2 = *(const float4*)(h + (size_t)s2 * D + d4 * 4);
        float4 v3 = *(const float4*)(h + (size_t)s3 * D + d4 * 4);
        acc.x += v0.x + v1.x + v2.x + v3.x;
        acc.y += v0.y + v1.y + v2.y + v3.y;
        acc.z += v0.z + v1.z + v2.z + v3.z;
        acc.w += v0.w + v1.w + v2.w + v3.w;
    }
    for (; j < deg; j++) {
        int src = g_eidx[base + j];
        float4 v = *(const float4*)(h + (size_t)src * D + d4 * 4);
        acc.x += v.x; acc.y += v.y; acc.z += v.z; acc.w += v.w;
    }
    unsigned h0, l0, h1, l1;
    split2(acc.x, acc.y, h0, l0);
    split2(acc.z, acc.w, h1, l1);
    *(uint2*)((char*)ohi + ((size_t)node * D + d4 * 4) * 2) = make_uint2(h0, h1);
    *(uint2*)((char*)olo + ((size_t)node * D + d4 * 4) * 2) = make_uint2(l0, l1);
}

// ---------------- pipelined tensor-core GEMM ----------------
#define OFF_ALO 4096u
#define OFF_BHI 8192u
#define OFF_BLO 16384u
#define STAGEB  24576u
#define GEMM_SMEM (3 * 24576 + 128)

#define LDM4(r0, r1, r2, r3, addr) \
    asm volatile("ldmatrix.sync.aligned.m8n8.x4.shared.b16 {%0,%1,%2,%3}, [%4];" \
                 : "=r"(r0), "=r"(r1), "=r"(r2), "=r"(r3) : "r"(addr))
#define CP16(dst, src) \
    asm volatile("cp.async.cg.shared.global [%0], [%1], 16;" :: "r"(dst), "l"(src))
#define CPCOMMIT() asm volatile("cp.async.commit_group;" ::: "memory")
#define CPWAIT1()  asm volatile("cp.async.wait_group 1;" ::: "memory")
#define CPWAIT0()  asm volatile("cp.async.wait_group 0;" ::: "memory")
#define STS32(addr, v) \
    asm volatile("st.shared.b32 [%0], %1;" :: "r"(addr), "r"(v) : "memory")

__device__ __forceinline__ void mma_bf16(float* c, unsigned a0, unsigned a1, unsigned a2,
                                         unsigned a3, unsigned b0, unsigned b1) {
    asm volatile(
        "mma.sync.aligned.m16n8k16.row.col.f32.bf16.bf16.f32 "
        "{%0,%1,%2,%3}, {%4,%5,%6,%7}, {%8,%9}, {%0,%1,%2,%3};"
        : "+f"(c[0]), "+f"(c[1]), "+f"(c[2]), "+f"(c[3])
        : "r"(a0), "r"(a1), "r"(a2), "r"(a3), "r"(b0), "r"(b1));
}

template <bool RELU, bool WSPLIT, bool WF32, bool WT>
__global__ void __launch_bounds__(256, 3)
pgemm_kernel(const __nv_bfloat16* __restrict__ Ahi, const __nv_bfloat16* __restrict__ Alo,
             const __nv_bfloat16* __restrict__ Bhi, const __nv_bfloat16* __restrict__ Blo,
             const float* __restrict__ bias, float* __restrict__ C,
             __nv_bfloat16* __restrict__ Ohi, __nv_bfloat16* __restrict__ Olo,
             int M, int Nc, int qscol, long long wts) {
    extern __shared__ char dynsmem[];
    unsigned sb = (smem_u32(dynsmem) + 127) & ~127u;

    int tid = threadIdx.x, wid = tid >> 5, lane = tid & 31;
    int m0 = blockIdx.y * 64, n0 = blockIdx.x * 128;
    int warp_m = (wid & 1) * 32, warp_n = (wid >> 1) * 32;
    int g = lane >> 2, kp = (lane & 3) * 2;

    int crow = tid >> 2, cch = tid & 3;
    unsigned dstA = (unsigned)(crow * 64 + ((cch ^ ((crow >> 1) & 3)) * 16));
    long long arow = m0 + crow; if (arow > M - 1) arow = M - 1;
    const __nv_bfloat16* pAhi = Ahi + arow * 512 + cch * 8;
    const __nv_bfloat16* pAlo = Alo + arow * 512 + cch * 8;
    int brow2 = crow + 64;
    unsigned dstB0 = dstA;
    unsigned dstB1 = (unsigned)(brow2 * 64 + ((cch ^ ((brow2 >> 1) & 3)) * 16));
    const __nv_bfloat16* pBhi0 = Bhi + (size_t)(n0 + crow) * 512 + cch * 8;
    const __nv_bfloat16* pBhi1 = Bhi + (size_t)(n0 + brow2) * 512 + cch * 8;
    const __nv_bfloat16* pBlo0 = Blo + (size_t)(n0 + crow) * 512 + cch * 8;
    const __nv_bfloat16* pBlo1 = Blo + (size_t)(n0 + brow2) * 512 + cch * 8;

    int rA = lane & 15, hA = lane >> 4;
    unsigned aoff = (unsigned)((warp_m + rA) * 64 + ((hA ^ ((rA >> 1) & 3)) * 16));
    int rB = (lane & 7) + ((lane >> 4) * 8);
    int cB = (lane >> 3) & 1;
    unsigned boff = (unsigned)((warp_n + rB) * 64 + ((cB ^ ((rB >> 1) & 3)) * 16));

    float acc[2][4][4];
#pragma unroll
    for (int i = 0; i < 2; i++)
#pragma unroll
        for (int j = 0; j < 4; j++)
#pragma unroll
            for (int r = 0; r < 4; r++) acc[i][j][r] = 0.f;

#pragma unroll
    for (int s = 0; s < 2; s++) {
        unsigned bb = sb + (unsigned)s * STAGEB;
        int kg = s * 32;
        CP16(bb + dstA,            pAhi + kg);
        CP16(bb + OFF_ALO + dstA,  pAlo + kg);
        CP16(bb + OFF_BHI + dstB0, pBhi0 + kg);
        CP16(bb + OFF_BHI + dstB1, pBhi1 + kg);
        CP16(bb + OFF_BLO + dstB0, pBlo0 + kg);
        CP16(bb + OFF_BLO + dstB1, pBlo1 + kg);
        CPCOMMIT();
    }

    unsigned bufoff[3] = {0u, STAGEB, 2u * STAGEB};
#pragma unroll 1
    for (int s = 0; s < 16; s++) {
        CPWAIT1();
        __syncthreads();
        if (s + 2 < 16) {
            unsigned bb = sb + bufoff[(s + 2) % 3];
            int kg = (s + 2) * 32;
            CP16(bb + dstA,            pAhi + kg);
            CP16(bb + OFF_ALO + dstA,  pAlo + kg);
            CP16(bb + OFF_BHI + dstB0, pBhi0 + kg);
            CP16(bb + OFF_BHI + dstB1, pBhi1 + kg);
            CP16(bb + OFF_BLO + dstB0, pBlo0 + kg);
            CP16(bb + OFF_BLO + dstB1, pBlo1 + kg);
        }
        CPCOMMIT();

        unsigned bcur = sb + bufoff[s % 3];
#pragma unroll
        for (int kx = 0; kx < 2; kx++) {
            unsigned kxor = kx ? 32u : 0u;
            unsigned ah[2][4], al[2][4], bh[4][2], bl[4][2];
#pragma unroll
            for (int mi = 0; mi < 2; mi++)
                LDM4(ah[mi][0], ah[mi][1], ah[mi][2], ah[mi][3],
                     bcur + (unsigned)(mi * 1024) + (aoff ^ kxor));
            {
                unsigned r0, r1, r2, r3;
#pragma unroll
                for (int p = 0; p < 2; p++) {
                    LDM4(r0, r1, r2, r3, bcur + OFF_BHI + (unsigned)(p * 1024) + (boff ^ kxor));
                    bh[2 * p][0] = r0; bh[2 * p][1] = r1;
                    bh[2 * p + 1][0] = r2; bh[2 * p + 1][1] = r3;
                    LDM4(r0, r1, r2, r3, bcur + OFF_BLO + (unsigned)(p * 1024) + (boff ^ kxor));
                    bl[2 * p][0] = r0; bl[2 * p][1] = r1;
                    bl[2 * p + 1][0] = r2; bl[2 * p + 1][1] = r3;
                }
            }
#pragma unroll
            for (int mi = 0; mi < 2; mi++)
                LDM4(al[mi][0], al[mi][1], al[mi][2], al[mi][3],
                     bcur + OFF_ALO + (unsigned)(mi * 1024) + (aoff ^ kxor));
#pragma unroll
            for (int mi = 0; mi < 2; mi++)
#pragma unroll
                for (int ni = 0; ni < 4; ni++)
                    mma_bf16(acc[mi][ni], ah[mi][0], ah[mi][1], ah[mi][2], ah[mi][3],
                             bh[ni][0], bh[ni][1]);
#pragma unroll
            for (int mi = 0; mi < 2; mi++)
#pragma unroll
                for (int ni = 0; ni < 4; ni++)
                    mma_bf16(acc[mi][ni], ah[mi][0], ah[mi][1], ah[mi][2], ah[mi][3],
                             bl[ni][0], bl[ni][1]);
#pragma unroll
            for (int mi = 0; mi < 2; mi++)
#pragma unroll
                for (int ni = 0; ni < 4; ni++)
                    mma_bf16(acc[mi][ni], al[mi][0], al[mi][1], al[mi][2], al[mi][3],
                             bh[ni][0], bh[ni][1]);
        }
    }

#pragma unroll
    for (int mi = 0; mi < 2; mi++) {
        int row0 = m0 + warp_m + mi * 16 + g;
        int row1 = row0 + 8;
#pragma unroll
        for (int ni = 0; ni < 4; ni++) {
            int col = n0 + warp_n + ni * 8 + kp;
            float b0 = bias[col], b1 = bias[col + 1];
            float o0 = acc[mi][ni][0] + b0, o1 = acc[mi][ni][1] + b1;
            float o2 = acc[mi][ni][2] + b0, o3 = acc[mi][ni][3] + b1;
            if (RELU) {
                o0 = fmaxf(o0, 0.f); o1 = fmaxf(o1, 0.f);
                o2 = fmaxf(o2, 0.f); o3 = fmaxf(o3, 0.f);
            }
            if (WT) {
                float f0 = (col >= qscol) ? 0.125f : 1.f;
                float f1 = (col + 1 >= qscol) ? 0.125f : 1.f;
                o0 *= f0; o1 *= f1; o2 *= f0; o3 *= f1;
            }
            if (row0 < M) {
                if (WF32)
                    *(float2*)(C + (size_t)row0 * Nc + col) = make_float2(o0, o1);
                if (WSPLIT && !WT) {
                    unsigned hw, lw;
                    split2(o0, o1, hw, lw);
                    *(unsigned*)((char*)Ohi + ((size_t)row0 * Nc + col) * 2) = hw;
                    *(unsigned*)((char*)Olo + ((size_t)row0 * Nc + col) * 2) = lw;
                }
                if (WT) {
                    __nv_bfloat16 h0 = __float2bfloat16(o0);
                    __nv_bfloat16 h1 = __float2bfloat16(o1);
                    Ohi[(size_t)col * wts + row0] = h0;
                    Olo[(size_t)col * wts + row0] = __float2bfloat16(o0 - __bfloat162float(h0));
                    Ohi[(size_t)(col + 1) * wts + row0] = h1;
                    Olo[(size_t)(col + 1) * wts + row0] = __float2bfloat16(o1 - __bfloat162float(h1));
                }
            }
            if (row1 < M) {
                if (WF32)
                    *(float2*)(C + (size_t)row1 * Nc + col) = make_float2(o2, o3);
                if (WSPLIT && !WT) {
                    unsigned hw, lw;
                    split2(o2, o3, hw, lw);
                    *(unsigned*)((char*)Ohi + ((size_t)row1 * Nc + col) * 2) = hw;
                    *(unsigned*)((char*)Olo + ((size_t)row1 * Nc + col) * 2) = lw;
                }
                if (WT) {
                    __nv_bfloat16 h2 = __float2bfloat16(o2);
                    __nv_bfloat16 h3 = __float2bfloat16(o3);
                    Ohi[(size_t)col * wts + row1] = h2;
                    Olo[(size_t)col * wts + row1] = __float2bfloat16(o2 - __bfloat162float(h2));
                    Ohi[(size_t)(col + 1) * wts + row1] = h3;
                    Olo[(size_t)(col + 1) * wts + row1] = __float2bfloat16(o3 - __bfloat162float(h3));
                }
            }
        }
    }
}

// ---------------- BatchNorm ----------------
__global__ void bn_stats_kernel(const float* __restrict__ h, int N) {
    int c = threadIdx.x;
    double s = 0.0, s2 = 0.0;
    for (int r = blockIdx.x; r < N; r += gridDim.x) {
        float v = h[(size_t)r * D + c];
        s += v;
        s2 += (double)v * v;
    }
    atomicAdd(&g_stats[c], s);
    atomicAdd(&g_stats[D + c], s2);
}

__global__ void bn_apply_kernel(const float* __restrict__ h, const float* __restrict__ gamma,
                                const float* __restrict__ beta,
                                __nv_bfloat16* __restrict__ ohi, __nv_bfloat16* __restrict__ olo,
                                int N) {
    long long i = (long long)blockIdx.x * blockDim.x + threadIdx.x;
    if (i >= (long long)N * (D / 2)) return;
    int p = (int)(i & (D / 2 - 1));
    long long row = i >> 8;
    int c0 = 2 * p, c1 = c0 + 1;
    double mean0 = g_stats[c0] / N, mean1 = g_stats[c1] / N;
    double var0  = g_stats[D + c0] / N - mean0 * mean0;
    double var1  = g_stats[D + c1] / N - mean1 * mean1;
    float is0 = rsqrtf((float)var0 + 1e-5f), is1 = rsqrtf((float)var1 + 1e-5f);
    float2 v = *(const float2*)(h + row * D + c0);
    float o0 = (v.x - (float)mean0) * is0 * gamma[c0] + beta[c0];
    float o1 = (v.y - (float)mean1) * is1 * gamma[c1] + beta[c1];
    unsigned hw, lw;
    split2(o0, o1, hw, lw);
    *(unsigned*)((char*)ohi + (row * D + c0) * 2) = hw;
    *(unsigned*)((char*)olo + (row * D + c0) * 2) = lw;
}

// ---------------- attention: full tensor-core (scores + AV), frag softmax ----------------
__global__ void __launch_bounds__(128)
attn_kernel(const void* __restrict__ ptr, int L, int Nn,
            const __nv_bfloat16* __restrict__ qkhi, const __nv_bfloat16* __restrict__ qklo,
            const __nv_bfloat16* __restrict__ vthi, const __nv_bfloat16* __restrict__ vtlo,
            __nv_bfloat16* __restrict__ ohi, __nv_bfloat16* __restrict__ olo) {
    extern __shared__ char smraw[];
    unsigned sb0 = smem_u32(smraw);
    unsigned sb = (sb0 + 127) & ~127u;
    const unsigned QHI = 0, QLO = 8192, KHI = 16384, KLO = 24576;
    const unsigned VHI = 32768, VLO = 40960, PHI = 49152, PLO = 57344;

    int qt = blockIdx.x, hh = blockIdx.y, b = blockIdx.z;
    int is64 = g_flags[1];
    long long p0 = ldidx(ptr, is64, b);
    long long p1 = ldidx(ptr, is64, b + 1);
    int s = (int)(p1 - p0);
    int qbase = qt * QT;
    if (qbase >= s) return;

    int tid = threadIdx.x, wid = tid >> 5, lane = tid & 31;
    int w16 = wid * 16;
    int g = lane >> 2, fc = (lane & 3) * 2;
    int rA = lane & 15, hA = lane >> 4;
    int rB = (lane & 7) + ((lane >> 4) * 8);
    int cB = (lane >> 3) & 1;
    unsigned aswz = (unsigned)((hA ^ (rA & 3)) * 16);
    unsigned bswz = (unsigned)((cB ^ (rB & 3)) * 16);

    {
        int row = tid >> 1, kb = tid & 1;
        long long node = p0 + min(qbase + row, s - 1);
        const __nv_bfloat16* qh = qkhi + node * 1024 + 512 + hh * 64 + kb * 32;
        const __nv_bfloat16* ql = qklo + node * 1024 + 512 + hh * 64 + kb * 32;
        unsigned dst = (unsigned)((row * 2 + kb) * 64);
        unsigned sw = (unsigned)(row & 3);
#pragma unroll
        for (int c = 0; c < 4; c++) {
            CP16(sb + QHI + dst + ((c ^ sw) * 16), qh + c * 8);
            CP16(sb + QLO + dst + ((c ^ sw) * 16), ql + c * 8);
        }
        CPCOMMIT();
    }

    int r0 = w16 + g, r1 = r0 + 8;
    bool r0ok = (qbase + r0) < s, r1ok = (qbase + r1) < s;
    const unsigned char* mk0 = g_mask + ((size_t)b * L + (r0ok ? qbase + r0 : 0)) * L;
    const unsigned char* mk1 = g_mask + ((size_t)b * L + (r1ok ? qbase + r1 : 0)) * L;
    unsigned swz0 = (unsigned)(r0 & 3), swz1 = (unsigned)(r1 & 3);

    float oacc[8][4];
#pragma unroll
    for (int nt = 0; nt < 8; nt++)
#pragma unroll
        for (int r = 0; r < 4; r++) oacc[nt][r] = 0.f;
    float mr0 = -1e30f, mr1 = -1e30f, lr0 = 0.f, lr1 = 0.f;

    int kmax = (s - 8) & ~7;

    for (int j0 = 0; j0 < s; j0 += 64) {
        __syncthreads();
        {
            int row = tid >> 1, kb = tid & 1;
            long long node = p0 + min(j0 + row, s - 1);
            const __nv_bfloat16* kh = qkhi + node * 1024 + hh * 64 + kb * 32;
            const __nv_bfloat16* kl = qklo + node * 1024 + hh * 64 + kb * 32;
            unsigned dst = (unsigned)((row * 2 + kb) * 64);
            unsigned sw = (unsigned)(row & 3);
#pragma unroll
            for (int c = 0; c < 4; c++) {
                CP16(sb + KHI + dst + ((c ^ sw) * 16), kh + c * 8);
                CP16(sb + KLO + dst + ((c ^ sw) * 16), kl + c * 8);
            }
        }
        {
            int drow = tid >> 1, kb = tid & 1;
            const __nv_bfloat16* vh = vthi + (size_t)(hh * 64 + drow) * Nn + p0;
            const __nv_bfloat16* vl = vtlo + (size_t)(hh * 64 + drow) * Nn + p0;
            unsigned dst = (unsigned)((drow * 2 + kb) * 64);
            unsigned sw = (unsigned)(drow & 3);
#pragma unroll
            for (int c = 0; c < 4; c++) {
                int kidx = min(j0 + kb * 32 + c * 8, kmax);
                CP16(sb + VHI + dst + ((c ^ sw) * 16), vh + kidx);
                CP16(sb + VLO + dst + ((c ^ sw) * 16), vl + kidx);
            }
        }
        CPCOMMIT();
        CPWAIT0();
        __syncthreads();

        float sacc[8][4];
#pragma unroll
        for (int nt = 0; nt < 8; nt++)
#pragma unroll
            for (int r = 0; r < 4; r++) sacc[nt][r] = 0.f;
#pragma unroll
        for (int ks = 0; ks < 4; ks++) {
            int kb = ks >> 1;
            unsigned kxor = (unsigned)((ks & 1) * 32);
            unsigned asub = (unsigned)((2 * (w16 + rA) + kb) * 64) + (aswz ^ kxor);
            unsigned ah[4], al[4], bh[8][2], bl[8][2];
            LDM4(ah[0], ah[1], ah[2], ah[3], sb + QHI + asub);
            LDM4(al[0], al[1], al[2], al[3], sb + QLO + asub);
#pragma unroll
            for (int p = 0; p < 4; p++) {
                unsigned bsub = (unsigned)((2 * (p * 16 + rB) + kb) * 64) + (bswz ^ kxor);
                unsigned q0, q1, q2, q3;
                LDM4(q0, q1, q2, q3, sb + KHI + bsub);
                bh[2 * p][0] = q0; bh[2 * p][1] = q1;
                bh[2 * p + 1][0] = q2; bh[2 * p + 1][1] = q3;
                LDM4(q0, q1, q2, q3, sb + KLO + bsub);
                bl[2 * p][0] = q0; bl[2 * p][1] = q1;
                bl[2 * p + 1][0] = q2; bl[2 * p + 1][1] = q3;
            }
#pragma unroll
            for (int nt = 0; nt < 8; nt++)
                mma_bf16(sacc[nt], ah[0], ah[1], ah[2], ah[3], bh[nt][0], bh[nt][1]);
#pragma unroll
            for (int nt = 0; nt < 8; nt++)
                mma_bf16(sacc[nt], al[0], al[1], al[2], al[3], bh[nt][0], bh[nt][1]);
#pragma unroll
            for (int nt = 0; nt < 8; nt++)
                mma_bf16(sacc[nt], ah[0], ah[1], ah[2], ah[3], bl[nt][0], bl[nt][1]);
        }

#pragma unroll
        for (int nt = 0; nt < 8; nt++) {
            int c0 = nt * 8 + fc, c1 = c0 + 1;
            bool in0 = (j0 + c0 < s), in1 = (j0 + c1 < s);
            sacc[nt][0] = (in0 && mk0[j0 + c0] == 0) ? sacc[nt][0] : -1e30f;
            sacc[nt][1] = (in1 && mk0[j0 + c1] == 0) ? sacc[nt][1] : -1e30f;
            sacc[nt][2] = (in0 && mk1[j0 + c0] == 0) ? sacc[nt][2] : -1e30f;
            sacc[nt][3] = (in1 && mk1[j0 + c1] == 0) ? sacc[nt][3] : -1e30f;
        }
        float mt0 = -1e30f, mt1 = -1e30f;
#pragma unroll
        for (int nt = 0; nt < 8; nt++) {
            mt0 = fmaxf(mt0, fmaxf(sacc[nt][0], sacc[nt][1]));
            mt1 = fmaxf(mt1, fmaxf(sacc[nt][2], sacc[nt][3]));
        }
        mt0 = fmaxf(mt0, __shfl_xor_sync(0xffffffffu, mt0, 1));
        mt0 = fmaxf(mt0, __shfl_xor_sync(0xffffffffu, mt0, 2));
        mt1 = fmaxf(mt1, __shfl_xor_sync(0xffffffffu, mt1, 1));
        mt1 = fmaxf(mt1, __shfl_xor_sync(0xffffffffu, mt1, 2));
        float mn0 = fmaxf(mr0, mt0), mn1 = fmaxf(mr1, mt1);
        float co0 = __expf(mr0 - mn0), co1 = __expf(mr1 - mn1);
        float ps0 = 0.f, ps1 = 0.f;
#pragma unroll
        for (int nt = 0; nt < 8; nt++) {
            float p00 = (sacc[nt][0] <= -1e29f) ? 0.f : __expf(sacc[nt][0] - mn0);
            float p01 = (sacc[nt][1] <= -1e29f) ? 0.f : __expf(sacc[nt][1] - mn0);
            float p10 = (sacc[nt][2] <= -1e29f) ? 0.f : __expf(sacc[nt][2] - mn1);
            float p11 = (sacc[nt][3] <= -1e29f) ? 0.f : __expf(sacc[nt][3] - mn1);
            ps0 += p00 + p01;
            ps1 += p10 + p11;
            int col = nt * 8 + fc;
            int kb = col >> 5;
            unsigned bofs = (unsigned)((col & 31) * 2);
            unsigned chunk = bofs >> 4, rem = bofs & 15;
            unsigned hw, lw;
            split2(p00, p01, hw, lw);
            unsigned a0 = (unsigned)((2 * r0 + kb) * 64) + ((chunk ^ swz0) * 16) + rem;
            STS32(sb + PHI + a0, hw);
            STS32(sb + PLO + a0, lw);
            split2(p10, p11, hw, lw);
            unsigned a1 = (unsigned)((2 * r1 + kb) * 64) + ((chunk ^ swz1) * 16) + rem;
            STS32(sb + PHI + a1, hw);
            STS32(sb + PLO + a1, lw);
        }
        ps0 += __shfl_xor_sync(0xffffffffu, ps0, 1);
        ps0 += __shfl_xor_sync(0xffffffffu, ps0, 2);
        ps1 += __shfl_xor_sync(0xffffffffu, ps1, 1);
        ps1 += __shfl_xor_sync(0xffffffffu, ps1, 2);
        lr0 = lr0 * co0 + ps0; mr0 = mn0;
        lr1 = lr1 * co1 + ps1; mr1 = mn1;
#pragma unroll
        for (int nt = 0; nt < 8; nt++) {
            oacc[nt][0] *= co0; oacc[nt][1] *= co0;
            oacc[nt][2] *= co1; oacc[nt][3] *= co1;
        }
        __syncwarp();

#pragma unroll
        for (int ks = 0; ks < 4; ks++) {
            int kb = ks >> 1;
            unsigned kxor = (unsigned)((ks & 1) * 32);
            unsigned asub = (unsigned)((2 * (w16 + rA) + kb) * 64) + (aswz ^ kxor);
            unsigned ah[4], al[4], bh[8][2], bl[8][2];
            LDM4(ah[0], ah[1], ah[2], ah[3], sb + PHI + asub);
            LDM4(al[0], al[1], al[2], al[3], sb + PLO + asub);
#pragma unroll
            for (int p = 0; p < 4; p++) {
                unsigned bsub = (unsigned)((2 * (p * 16 + rB) + kb) * 64) + (bswz ^ kxor);
                unsigned q0, q1, q2, q3;
                LDM4(q0, q1, q2, q3, sb + VHI + bsub);
                bh[2 * p][0] = q0; bh[2 * p][1] = q1;
                bh[2 * p + 1][0] = q2; bh[2 * p + 1][1] = q3;
                LDM4(q0, q1, q2, q3, sb + VLO + bsub);
                bl[2 * p][0] = q0; bl[2 * p][1] = q1;
                bl[2 * p + 1][0] = q2; bl[2 * p + 1][1] = q3;
            }
#pragma unroll
            for (int nt = 0; nt < 8; nt++)
                mma_bf16(oacc[nt], ah[0], ah[1], ah[2], ah[3], bh[nt][0], bh[nt][1]);
#pragma unroll
            for (int nt = 0; nt < 8; nt++)
                mma_bf16(oacc[nt], al[0], al[1], al[2], al[3], bh[nt][0], bh[nt][1]);
#pragma unroll
            for (int nt = 0; nt < 8; nt++)
                mma_bf16(oacc[nt], ah[0], ah[1], ah[2], ah[3], bl[nt][0], bl[nt][1]);
        }
        __syncwarp();
    }

    if (r0ok && lr0 > 0.f) {
        float inv = 1.f / lr0;
        size_t base = ((p0 + qbase + r0) * D + hh * HD) * 2;
#pragma unroll
        for (int nt = 0; nt < 8; nt++) {
            unsigned hw, lw;
            split2(oacc[nt][0] * inv, oacc[nt][1] * inv, hw, lw);
            *(unsigned*)((char*)ohi + base + (nt * 8 + fc) * 2) = hw;
            *(unsigned*)((char*)olo + base + (nt * 8 + fc) * 2) = lw;
        }
    }
    if (r1ok && lr1 > 0.f) {
        float inv = 1.f / lr1;
        size_t base = ((p0 + qbase + r1) * D + hh * HD) * 2;
#pragma unroll
        for (int nt = 0; nt < 8; nt++) {
            unsigned hw, lw;
            split2(oacc[nt][2] * inv, oacc[nt][3] * inv, hw, lw);
            *(unsigned*)((char*)ohi + base + (nt * 8 + fc) * 2) = hw;
            *(unsigned*)((char*)olo + base + (nt * 8 + fc) * 2) = lw;
        }
    }
}

// ---------------- host orchestration ----------------
extern "C" void kernel_launch(void* const* d_in, const int* in_sizes, int n_in,
                              void* d_out, int out_size) {
    const float* x   = (const float*)d_in[0];
    const void* edge = d_in[1];
    const void* mask = d_in[2];
    const void* ptr  = d_in[3];
    const float* gw1   = (const float*)d_in[4];
    const float* gb1   = (const float*)d_in[5];
    const float* gw2   = (const float*)d_in[6];
    const float* gb2   = (const float*)d_in[7];
    const float* gamma = (const float*)d_in[8];
    const float* beta  = (const float*)d_in[9];
    const float* sw    = (const float*)d_in[10];
    const float* sb    = (const float*)d_in[11];
    const float* qkw   = (const float*)d_in[12];
    const float* qkb   = (const float*)d_in[13];
    const float* vw    = (const float*)d_in[14];
    const float* vb    = (const float*)d_in[15];
    const float* ow    = (const float*)d_in[16];
    const float* ob    = (const float*)d_in[17];
    float* out = (float*)d_out;

    int N  = in_sizes[0] / D;
    int E  = in_sizes[1] / 2;
    int Bg = in_sizes[3] - 1;
    int ngin = in_sizes[4] / (D * D);
    int L;
    {
        long long ll = (long long)in_sizes[2] / Bg;
        int l = 1;
        while ((long long)l * l < ll) l++;
        L = l;
    }
    long long masktotal = (long long)Bg * L * L;
    if (N > NMAX || masktotal > MASKMAX || ngin > 3 || E > EMAX) return;

    float *ph, *pbf, *pzero;
    double* pstats;
    __nv_bfloat16 *whi, *wlo, *shi0, *slo0, *shi1, *slo1, *shi2, *slo2;
    __nv_bfloat16 *swhi, *swlo, *wfhi, *wflo, *qkhi, *qklo, *vthi, *vtlo;
    int* pdeg;
    cudaGetSymbolAddress((void**)&ph,    g_h);
    cudaGetSymbolAddress((void**)&pstats, g_stats);
    cudaGetSymbolAddress((void**)&whi,   g_whi);
    cudaGetSymbolAddress((void**)&wlo,   g_wlo);
    cudaGetSymbolAddress((void**)&shi0,  g_shi0);
    cudaGetSymbolAddress((void**)&slo0,  g_slo0);
    cudaGetSymbolAddress((void**)&shi1,  g_shi1);
    cudaGetSymbolAddress((void**)&slo1,  g_slo1);
    cudaGetSymbolAddress((void**)&shi2,  g_shi2);
    cudaGetSymbolAddress((void**)&slo2,  g_slo2);
    cudaGetSymbolAddress((void**)&swhi,  g_swhi);
    cudaGetSymbolAddress((void**)&swlo,  g_swlo);
    cudaGetSymbolAddress((void**)&wfhi,  g_wfhi);
    cudaGetSymbolAddress((void**)&wflo,  g_wflo);
    cudaGetSymbolAddress((void**)&qkhi,  g_qkhi);
    cudaGetSymbolAddress((void**)&qklo,  g_qklo);
    cudaGetSymbolAddress((void**)&vthi,  g_vthi);
    cudaGetSymbolAddress((void**)&vtlo,  g_vtlo);
    cudaGetSymbolAddress((void**)&pbf,   g_bf);
    cudaGetSymbolAddress((void**)&pzero, g_zero);
    cudaGetSymbolAddress((void**)&pdeg,  g_deg);

    cudaFuncSetAttribute(pgemm_kernel<false, false, true, false>,
                         cudaFuncAttributeMaxDynamicSharedMemorySize, GEMM_SMEM);
    cudaFuncSetAttribute(pgemm_kernel<true, true, false, false>,
                         cudaFuncAttributeMaxDynamicSharedMemorySize, GEMM_SMEM);
    cudaFuncSetAttribute(pgemm_kernel<true, false, true, false>,
                         cudaFuncAttributeMaxDynamicSharedMemorySize, GEMM_SMEM);
    cudaFuncSetAttribute(pgemm_kernel<false, true, false, true>,
                         cudaFuncAttributeMaxDynamicSharedMemorySize, GEMM_SMEM);
    cudaFuncSetAttribute(pgemm_kernel<false, true, false, false>,
                         cudaFuncAttributeMaxDynamicSharedMemorySize, GEMM_SMEM);
    cudaFuncSetAttribute(attn_kernel,
                         cudaFuncAttributeMaxDynamicSharedMemorySize, ATTN_SMEM);

    const size_t SZ = (size_t)D * D;
    size_t off_v = 0, off_g1[3], off_g2[3];
    size_t cur = SZ;
    for (int i = 0; i < 3; i++) { off_g1[i] = cur; cur += SZ; off_g2[i] = cur; cur += SZ; }
    size_t off_qk = cur; cur += 2 * SZ;
    size_t off_o  = cur;

    WJobs J;
    int jn = 0, rows = 0;
    auto addjob = [&](const float* src, size_t off, int Nc) {
        J.src[jn] = src; J.hi[jn] = whi + off; J.lo[jn] = wlo + off;
        J.N[jn] = Nc; J.row0[jn] = rows;
        rows += Nc; jn++;
    };
    addjob(vw, off_v, D);
    for (int i = 0; i < ngin; i++) {
        addjob(gw1 + SZ * i, off_g1[i], D);
        addjob(gw2 + SZ * i, off_g2[i], D);
    }
    addjob(qkw, off_qk, 2 * D);
    addjob(ow, off_o, D);
    J.njobs = jn;

    int mt = (N + 63) / 64;
    dim3 g512(D / 128, mt);
    dim3 g1024(2 * D / 128, mt);
    dim3 gprep(2 * D / 128, 512 / 64);
    const int NOSC = 1 << 30;

    // side stream for the independent chain (created per call, leaked —
    // kernel_launch runs only a handful of times; destroying a capturing
    // stream mid-capture is unsafe)
    cudaStream_t sB;
    cudaStreamCreateWithFlags(&sB, cudaStreamNonBlocking);
    cudaEvent_t evFork, evB;
    cudaEventCreateWithFlags(&evFork, cudaEventDisableTiming);
    cudaEventCreateWithFlags(&evB, cudaEventDisableTiming);

    // ---- stream 0: shared prologue ----
    detect_kernel<<<1, 256>>>((const int*)edge, (const int*)ptr, (const unsigned int*)mask);
    asplit_kernel<<<N, 128>>>(x, shi0, slo0);
    wsplit_all_kernel<<<rows, 256>>>(J);
    cudaEventRecord(evFork, 0);

    // ---- stream B: independent chain (v-GEMM, weight-prep, mask) ----
    cudaStreamWaitEvent(sB, evFork, 0);
    pgemm_kernel<false, true, false, true><<<g512, 256, GEMM_SMEM, sB>>>(   // V^T split
        shi0, slo0, whi + off_v, wlo + off_v, vb, nullptr, vthi, vtlo, N, D, NOSC, (long long)N);
    asplit_kernel<<<512, 128, 0, sB>>>(sw, swhi, swlo);
    pgemm_kernel<false, true, false, true><<<gprep, 256, GEMM_SMEM, sB>>>(  // W' = se_w@qk_w
        swhi, swlo, whi + off_qk, wlo + off_qk, pzero, nullptr, wfhi, wflo, 512, 2 * D, 512, 512);
    bfold_kernel<<<4, 256, 0, sB>>>(sb, qkw, qkb);
    mask_convert_kernel<<<(unsigned)((masktotal + 511) / 512), 512, 0, sB>>>(mask, masktotal);
    cudaEventRecord(evB, sB);

    // ---- stream 0: CSR + GIN chain (uses S1/S2; S0 is read-only now) ----
    cudaMemsetAsync(pdeg, 0, (size_t)N * sizeof(int));
    csr_count_kernel<<<(E + 255) / 256, 256>>>(edge, E);
    csr_scan_kernel<<<1, 1024>>>(N);
    csr_fill_kernel<<<(E + 255) / 256, 256>>>(edge, E);

    const float* hin = x;
    for (int i = 0; i < ngin; i++) {
        gather_kernel<<<N, 128>>>(hin, shi1, slo1);
        pgemm_kernel<true, true, false, false><<<g512, 256, GEMM_SMEM>>>(
            shi1, slo1, whi + off_g1[i], wlo + off_g1[i], gb1 + (size_t)i * D,
            nullptr, shi2, slo2, N, D, NOSC, 0);
        pgemm_kernel<true, false, true, false><<<g512, 256, GEMM_SMEM>>>(
            shi2, slo2, whi + off_g2[i], wlo + off_g2[i], gb2 + (size_t)i * D,
            ph, nullptr, nullptr, N, D, NOSC, 0);
        hin = ph;
    }

    cudaMemsetAsync(pstats, 0, 2 * D * sizeof(double));
    bn_stats_kernel<<<256, D>>>(ph, N);
    bn_apply_kernel<<<(unsigned)(((long long)N * (D / 2) + 255) / 256), 256>>>(
        ph, gamma, beta, shi1, slo1, N);

    // ---- join: qk GEMM needs W'; attention needs VT + mask ----
    cudaStreamWaitEvent(0, evB, 0);

    pgemm_kernel<false, true, false, false><<<g1024, 256, GEMM_SMEM>>>(
        shi1, slo1, wfhi, wflo, pbf, nullptr, qkhi, qklo, N, 2 * D, NOSC, 0);

    dim3 gattn((L + QT - 1) / QT, NHEAD, Bg);
    attn_kernel<<<gattn, 128, ATTN_SMEM>>>(ptr, L, N, qkhi, qklo, vthi, vtlo, shi1, slo1);

    pgemm_kernel<false, false, true, false><<<g512, 256, GEMM_SMEM>>>(
        shi1, slo1, whi + off_o, wlo + off_o, ob, out, nullptr, nullptr, N, D, NOSC, 0);
}